// round 2
// baseline (speedup 1.0000x reference)
#include <cuda_runtime.h>
#include <math.h>

#define B_    8
#define C_    512
#define H_    64
#define W_    64
#define N_    4096          // H*W
#define AREA_ 4
#define NHEAD 8
#define HD_   64
#define NA_   1024          // N/AREA
#define EPS_  1e-5f

// ---------------- scratch (device globals; no allocation allowed) ----------
__device__ float g_qk [B_ * 2 * C_ * N_];   // [B][1024][4096]  qk act (post BN+SiLU)
__device__ float g_v  [B_ * C_ * N_];       // [B][512][4096]   v act
__device__ float g_pp [B_ * C_ * N_];       // position embed branch
__device__ float g_att[B_ * C_ * N_];       // attention output, channel-major

__device__ __forceinline__ float silu_f(float y) {
    return y / (1.0f + __expf(-y));
}

// ============================================================================
// Kernel 1/2: Y[b][m][n] = silu( (sum_k W[m][k] * X[b][k][n]) * sc[m] + sh[m] )
// grid: (N_/64, M/64, B_), 256 threads, 64x64 tile, 4x4 per thread
// ============================================================================
__global__ void gemm_bn_silu(const float* __restrict__ Wt,   // [M][K]
                             const float* __restrict__ X,    // [B][K][N]
                             const float* __restrict__ gg,
                             const float* __restrict__ bb,
                             const float* __restrict__ rm,
                             const float* __restrict__ rv,
                             float* __restrict__ Y, int M)
{
    const int K = C_;
    __shared__ float Ws[16 * 65];   // [k][m], padded
    __shared__ float Xs[16 * 64];   // [k][n]

    const int n0 = blockIdx.x * 64;
    const int m0 = blockIdx.y * 64;
    const int b  = blockIdx.z;
    const float* Xb = X + (size_t)b * K * N_;

    const int tid = threadIdx.x;
    const int tx = tid & 15, ty = tid >> 4;

    float acc[4][4] = {};

    for (int k0 = 0; k0 < K; k0 += 16) {
        // W tile: coalesced along k (16-wide segments)
        #pragma unroll
        for (int i = 0; i < 4; i++) {
            int e = tid + 256 * i;
            int m = e >> 4, k = e & 15;
            Ws[k * 65 + m] = Wt[(size_t)(m0 + m) * K + k0 + k];
        }
        // X tile: coalesced along n
        #pragma unroll
        for (int i = 0; i < 4; i++) {
            int e = tid + 256 * i;
            int k = e >> 6, n = e & 63;
            Xs[k * 64 + n] = Xb[(size_t)(k0 + k) * N_ + n0 + n];
        }
        __syncthreads();
        #pragma unroll
        for (int kk = 0; kk < 16; kk++) {
            float a[4], bv[4];
            #pragma unroll
            for (int i = 0; i < 4; i++) a[i]  = Ws[kk * 65 + ty * 4 + i];
            #pragma unroll
            for (int j = 0; j < 4; j++) bv[j] = Xs[kk * 64 + tx * 4 + j];
            #pragma unroll
            for (int i = 0; i < 4; i++)
                #pragma unroll
                for (int j = 0; j < 4; j++) acc[i][j] += a[i] * bv[j];
        }
        __syncthreads();
    }

    #pragma unroll
    for (int i = 0; i < 4; i++) {
        int m = m0 + ty * 4 + i;
        float sc = gg[m] * rsqrtf(rv[m] + EPS_);
        float sh = bb[m] - rm[m] * sc;
        #pragma unroll
        for (int j = 0; j < 4; j++) {
            float yv = acc[i][j] * sc + sh;
            Y[((size_t)b * M + m) * N_ + n0 + tx * 4 + j] = silu_f(yv);
        }
    }
}

// ============================================================================
// Kernel 3: 3x3 SAME conv over v -> pp, with BN+SiLU.
// One block = one output row (64 px) x 64 output channels.
// grid: (H_=64, C_/64=8, B_), 256 threads.
// ============================================================================
__global__ void conv3_bn_silu(const float* __restrict__ Wt,  // [O][I][3][3]
                              const float* __restrict__ Xin, // g_v
                              const float* __restrict__ gg,
                              const float* __restrict__ bb,
                              const float* __restrict__ rm,
                              const float* __restrict__ rv,
                              float* __restrict__ Yout)      // g_pp
{
    __shared__ float Xs[3 * 16 * 66];   // [row][c][x+halo]
    __shared__ float Ws[16 * 65];       // [c][o], padded

    const int y  = blockIdx.x;
    const int m0 = blockIdx.y * 64;
    const int b  = blockIdx.z;
    const float* Xb = Xin + (size_t)b * C_ * N_;

    const int tid = threadIdx.x;
    const int tx = tid & 15, ty = tid >> 4;

    float acc[4][4] = {};

    for (int c0 = 0; c0 < C_; c0 += 16) {
        __syncthreads();   // previous iteration fully consumed Xs/Ws
        // load 3 input rows (with zero halo) for 16 channels
        for (int e = tid; e < 3 * 16 * 66; e += 256) {
            int r   = e / (16 * 66);
            int rem = e - r * (16 * 66);
            int cc  = rem / 66;
            int xx  = rem - cc * 66;
            int yy  = y + r - 1;
            int gx  = xx - 1;
            float v = 0.0f;
            if (yy >= 0 && yy < H_ && gx >= 0 && gx < W_)
                v = Xb[(size_t)(c0 + cc) * N_ + yy * W_ + gx];
            Xs[(r * 16 + cc) * 66 + xx] = v;
        }
        for (int t = 0; t < 9; t++) {
            const int dy = t / 3, dx = t - dy * 3;
            __syncthreads();   // Xs visible (t==0) / Ws consumers done (t>0)
            #pragma unroll
            for (int i = 0; i < 4; i++) {
                int e = tid + 256 * i;
                int m = e >> 4, k = e & 15;
                Ws[k * 65 + m] = Wt[((size_t)(m0 + m) * C_ + c0 + k) * 9 + t];
            }
            __syncthreads();
            #pragma unroll
            for (int kk = 0; kk < 16; kk++) {
                float a[4], bv[4];
                #pragma unroll
                for (int i = 0; i < 4; i++) a[i]  = Ws[kk * 65 + ty * 4 + i];
                #pragma unroll
                for (int j = 0; j < 4; j++) bv[j] = Xs[(dy * 16 + kk) * 66 + tx * 4 + j + dx];
                #pragma unroll
                for (int i = 0; i < 4; i++)
                    #pragma unroll
                    for (int j = 0; j < 4; j++) acc[i][j] += a[i] * bv[j];
            }
        }
    }

    #pragma unroll
    for (int i = 0; i < 4; i++) {
        int m = m0 + ty * 4 + i;
        float sc = gg[m] * rsqrtf(rv[m] + EPS_);
        float sh = bb[m] - rm[m] * sc;
        #pragma unroll
        for (int j = 0; j < 4; j++) {
            float yv = acc[i][j] * sc + sh;
            Yout[((size_t)b * C_ + m) * N_ + y * W_ + tx * 4 + j] = silu_f(yv);
        }
    }
}

// ============================================================================
// Kernel 4: area attention, fp32 flash style.
// grid: (NA_/64 = 16 q-tiles, NHEAD, B_*AREA_ = 32), 256 threads.
// dyn smem: Qs[64*64] + KV[64*65] + Ss[64*65] + m/l/alpha (3*64)
// ============================================================================
__global__ void attn_kernel(const float* __restrict__ qk,   // g_qk
                            const float* __restrict__ vv_g, // g_v
                            float* __restrict__ att)        // g_att
{
    extern __shared__ float sm[];
    float* Qs   = sm;            // [d][i]  (4096)
    float* KV   = sm + 4096;     // K: [d*65+j], V: [j*65+d]  (4160)
    float* Ss   = sm + 4096 + 4160;   // [i*65+j]  (4160)
    float* mrow = Ss + 4160;
    float* lrow = mrow + 64;
    float* arow = lrow + 64;

    const int q0   = blockIdx.x * 64;
    const int head = blockIdx.y;
    const int ba   = blockIdx.z;
    const int b    = ba >> 2;
    const int area = ba & 3;

    const float* Qb = qk   + ((size_t)b * 2 * C_ +       head * HD_) * N_ + area * NA_;
    const float* Kb = qk   + ((size_t)b * 2 * C_ + C_ +  head * HD_) * N_ + area * NA_;
    const float* Vb = vv_g + ((size_t)b * C_      +      head * HD_) * N_ + area * NA_;
    float*       Ob = att  + ((size_t)b * C_      +      head * HD_) * N_ + area * NA_;

    const int tid = threadIdx.x;
    const int tx = tid & 15, ty = tid >> 4;

    for (int e = tid; e < 4096; e += 256) {
        int d = e >> 6, i = e & 63;
        Qs[d * 64 + i] = Qb[(size_t)d * N_ + q0 + i];
    }
    if (tid < 64) { mrow[tid] = -1e30f; lrow[tid] = 0.0f; }

    float O[4][4] = {};
    const float scale = 0.125f;   // hd^-0.5

    for (int j0 = 0; j0 < NA_; j0 += 64) {
        __syncthreads();                       // Q visible / prev-iter consumers done
        for (int e = tid; e < 4096; e += 256) {        // K tile [d][j]
            int d = e >> 6, j = e & 63;
            KV[d * 65 + j] = Kb[(size_t)d * N_ + j0 + j];
        }
        __syncthreads();
        float s[4][4] = {};
        #pragma unroll
        for (int d = 0; d < 64; d++) {
            float a[4], bv[4];
            #pragma unroll
            for (int i = 0; i < 4; i++) a[i]  = Qs[d * 64 + ty * 4 + i];
            #pragma unroll
            for (int j = 0; j < 4; j++) bv[j] = KV[d * 65 + tx * 4 + j];
            #pragma unroll
            for (int i = 0; i < 4; i++)
                #pragma unroll
                for (int j = 0; j < 4; j++) s[i][j] += a[i] * bv[j];
        }
        #pragma unroll
        for (int i = 0; i < 4; i++)
            #pragma unroll
            for (int j = 0; j < 4; j++)
                Ss[(ty * 4 + i) * 65 + tx * 4 + j] = s[i][j] * scale;
        __syncthreads();
        if (tid < 64) {                        // online softmax row update
            float* row = Ss + tid * 65;
            float tm = row[0];
            for (int j = 1; j < 64; j++) tm = fmaxf(tm, row[j]);
            float mold = mrow[tid];
            float mnew = fmaxf(mold, tm);
            float alpha = __expf(mold - mnew);
            float sum = 0.0f;
            for (int j = 0; j < 64; j++) { float p = __expf(row[j] - mnew); row[j] = p; sum += p; }
            lrow[tid] = lrow[tid] * alpha + sum;
            mrow[tid] = mnew;
            arow[tid] = alpha;
        }
        __syncthreads();
        for (int e = tid; e < 4096; e += 256) {        // V tile [j][d]
            int d = e & 63, j = e >> 6;
            KV[j * 65 + d] = Vb[(size_t)d * N_ + j0 + j];
        }
        float al[4];
        #pragma unroll
        for (int i = 0; i < 4; i++) al[i] = arow[ty * 4 + i];
        #pragma unroll
        for (int i = 0; i < 4; i++)
            #pragma unroll
            for (int dd = 0; dd < 4; dd++) O[i][dd] *= al[i];
        __syncthreads();
        #pragma unroll
        for (int jj = 0; jj < 64; jj++) {
            float p[4], vv[4];
            #pragma unroll
            for (int i = 0; i < 4; i++)  p[i]  = Ss[(ty * 4 + i) * 65 + jj];
            #pragma unroll
            for (int dd = 0; dd < 4; dd++) vv[dd] = KV[jj * 65 + tx * 4 + dd];
            #pragma unroll
            for (int i = 0; i < 4; i++)
                #pragma unroll
                for (int dd = 0; dd < 4; dd++) O[i][dd] += p[i] * vv[dd];
        }
    }
    __syncthreads();
    // normalize + transpose through Ss for coalesced channel-major stores
    #pragma unroll
    for (int i = 0; i < 4; i++) {
        float linv = 1.0f / lrow[ty * 4 + i];
        #pragma unroll
        for (int dd = 0; dd < 4; dd++)
            Ss[(tx * 4 + dd) * 65 + ty * 4 + i] = O[i][dd] * linv;
    }
    __syncthreads();
    for (int e = tid; e < 4096; e += 256) {
        int d = e >> 6, i = e & 63;
        Ob[(size_t)d * N_ + q0 + i] = Ss[d * 65 + i];
    }
}

// ============================================================================
// Kernel 5: final 1x1 conv over (att + pp), BN+SiLU -> d_out
// ============================================================================
__global__ void gemm_add_bn_silu(const float* __restrict__ Wt,   // [512][512]
                                 const float* __restrict__ Xa,   // g_att
                                 const float* __restrict__ Xp,   // g_pp
                                 const float* __restrict__ gg,
                                 const float* __restrict__ bb,
                                 const float* __restrict__ rm,
                                 const float* __restrict__ rv,
                                 float* __restrict__ Y)
{
    const int K = C_, M = C_;
    __shared__ float Ws[16 * 65];
    __shared__ float Xs[16 * 64];

    const int n0 = blockIdx.x * 64;
    const int m0 = blockIdx.y * 64;
    const int b  = blockIdx.z;
    const float* X1 = Xa + (size_t)b * K * N_;
    const float* X2 = Xp + (size_t)b * K * N_;

    const int tid = threadIdx.x;
    const int tx = tid & 15, ty = tid >> 4;

    float acc[4][4] = {};

    for (int k0 = 0; k0 < K; k0 += 16) {
        #pragma unroll
        for (int i = 0; i < 4; i++) {
            int e = tid + 256 * i;
            int m = e >> 4, k = e & 15;
            Ws[k * 65 + m] = Wt[(size_t)(m0 + m) * K + k0 + k];
        }
        #pragma unroll
        for (int i = 0; i < 4; i++) {
            int e = tid + 256 * i;
            int k = e >> 6, n = e & 63;
            size_t idx = (size_t)(k0 + k) * N_ + n0 + n;
            Xs[k * 64 + n] = X1[idx] + X2[idx];
        }
        __syncthreads();
        #pragma unroll
        for (int kk = 0; kk < 16; kk++) {
            float a[4], bv[4];
            #pragma unroll
            for (int i = 0; i < 4; i++) a[i]  = Ws[kk * 65 + ty * 4 + i];
            #pragma unroll
            for (int j = 0; j < 4; j++) bv[j] = Xs[kk * 64 + tx * 4 + j];
            #pragma unroll
            for (int i = 0; i < 4; i++)
                #pragma unroll
                for (int j = 0; j < 4; j++) acc[i][j] += a[i] * bv[j];
        }
        __syncthreads();
    }

    #pragma unroll
    for (int i = 0; i < 4; i++) {
        int m = m0 + ty * 4 + i;
        float sc = gg[m] * rsqrtf(rv[m] + EPS_);
        float sh = bb[m] - rm[m] * sc;
        #pragma unroll
        for (int j = 0; j < 4; j++) {
            float yv = acc[i][j] * sc + sh;
            Y[((size_t)b * M + m) * N_ + n0 + tx * 4 + j] = silu_f(yv);
        }
    }
}

// ============================================================================
extern "C" void kernel_launch(void* const* d_in, const int* in_sizes, int n_in,
                              void* d_out, int out_size)
{
    const float* x     = (const float*)d_in[0];
    const float* qk_w  = (const float*)d_in[1];
    const float* qk_g  = (const float*)d_in[2];
    const float* qk_b  = (const float*)d_in[3];
    const float* qk_rm = (const float*)d_in[4];
    const float* qk_rv = (const float*)d_in[5];
    const float* v_w   = (const float*)d_in[6];
    const float* v_g   = (const float*)d_in[7];
    const float* v_b   = (const float*)d_in[8];
    const float* v_rm  = (const float*)d_in[9];
    const float* v_rv  = (const float*)d_in[10];
    const float* pe_w  = (const float*)d_in[11];
    const float* pe_g  = (const float*)d_in[12];
    const float* pe_b  = (const float*)d_in[13];
    const float* pe_rm = (const float*)d_in[14];
    const float* pe_rv = (const float*)d_in[15];
    const float* pr_w  = (const float*)d_in[16];
    const float* pr_g  = (const float*)d_in[17];
    const float* pr_b  = (const float*)d_in[18];
    const float* pr_rm = (const float*)d_in[19];
    const float* pr_rv = (const float*)d_in[20];
    float* out = (float*)d_out;

    // Resolve device-global scratch to real device pointers (capture-safe).
    float *p_qk, *p_v, *p_pp, *p_att;
    cudaGetSymbolAddress((void**)&p_qk,  g_qk);
    cudaGetSymbolAddress((void**)&p_v,   g_v);
    cudaGetSymbolAddress((void**)&p_pp,  g_pp);
    cudaGetSymbolAddress((void**)&p_att, g_att);

    static const size_t attn_smem = (4096 + 4160 + 4160 + 192) * sizeof(float);
    cudaFuncSetAttribute(attn_kernel, cudaFuncAttributeMaxDynamicSharedMemorySize,
                         (int)attn_smem);

    dim3 thr(256);

    // 1) qk = bn_silu(conv1x1(x, qk_w))   M=1024
    gemm_bn_silu<<<dim3(N_ / 64, 1024 / 64, B_), thr>>>(
        qk_w, x, qk_g, qk_b, qk_rm, qk_rv, p_qk, 1024);

    // 2) vmap = bn_silu(conv1x1(x, v_w))  M=512
    gemm_bn_silu<<<dim3(N_ / 64, C_ / 64, B_), thr>>>(
        v_w, x, v_g, v_b, v_rm, v_rv, p_v, C_);

    // 3) pp = bn_silu(conv3x3(vmap, pe_w))
    conv3_bn_silu<<<dim3(H_, C_ / 64, B_), thr>>>(
        pe_w, p_v, pe_g, pe_b, pe_rm, pe_rv, p_pp);

    // 4) area attention
    attn_kernel<<<dim3(NA_ / 64, NHEAD, B_ * AREA_), thr, attn_smem>>>(
        p_qk, p_v, p_att);

    // 5) y = bn_silu(conv1x1(att + pp, pr_w))
    gemm_add_bn_silu<<<dim3(N_ / 64, C_ / 64, B_), thr>>>(
        pr_w, p_att, p_pp, pr_g, pr_b, pr_rm, pr_rv, out);
}

// round 3
// speedup vs baseline: 4.2174x; 4.2174x over previous
#include <cuda_runtime.h>
#include <math.h>

#define B_    8
#define C_    512
#define H_    64
#define W_    64
#define N_    4096          // H*W
#define AREA_ 4
#define NHEAD 8
#define HD_   64
#define NA_   1024          // N/AREA
#define EPS_  1e-5f

// ---------------- scratch (device globals; no allocation allowed) ----------
__device__ float g_qk [B_ * 2 * C_ * N_];   // [B][1024][4096]  qk act (post BN+SiLU)
__device__ float g_v  [B_ * C_ * N_];       // [B][512][4096]   v act
__device__ float g_pp [B_ * C_ * N_];       // position embed branch
__device__ float g_att[B_ * C_ * N_];       // attention output, channel-major

__device__ __forceinline__ float silu_f(float y) {
    return y / (1.0f + __expf(-y));
}
__device__ __forceinline__ unsigned f2tf(float x) {
    unsigned u; asm("cvt.rna.tf32.f32 %0, %1;" : "=r"(u) : "f"(x)); return u;
}
// D += A*B, m16n8k8 tf32, row.col
__device__ __forceinline__ void mma8(float* c, const unsigned* a, const unsigned* b) {
    asm volatile(
      "mma.sync.aligned.m16n8k8.row.col.f32.tf32.tf32.f32 "
      "{%0,%1,%2,%3},{%4,%5,%6,%7},{%8,%9},{%0,%1,%2,%3};"
      : "+f"(c[0]), "+f"(c[1]), "+f"(c[2]), "+f"(c[3])
      : "r"(a[0]), "r"(a[1]), "r"(a[2]), "r"(a[3]), "r"(b[0]), "r"(b[1]));
}

// ============================================================================
// Kernel 1/2: Y[b][m][n] = silu(BN(sum_k W[m][k] X[b][k][n]))  via tf32 mma
// block tile 128m x 64n, 8 warps (4m x 2n), k-chunk 16.
// grid: (N/64, M/128, B)
// ============================================================================
__global__ void gemm_bn_silu_tc(const float* __restrict__ Wt,   // [M][512]
                                const float* __restrict__ X,    // [B][512][N]
                                const float* __restrict__ gg,
                                const float* __restrict__ bb,
                                const float* __restrict__ rm,
                                const float* __restrict__ rv,
                                float* __restrict__ Y, int M)
{
    __shared__ unsigned Ws[128 * 20];   // [m][k], pad 20 -> conflict-free A frags
    __shared__ unsigned Xs[16 * 72];    // [k][n], pad 72 -> conflict-free B frags

    const int n0 = blockIdx.x * 64;
    const int m0 = blockIdx.y * 128;
    const int b  = blockIdx.z;
    const float* Xb = X + (size_t)b * C_ * N_;

    const int tid = threadIdx.x, lane = tid & 31, warp = tid >> 5;
    const int g = lane >> 2, t = lane & 3;
    const int wm = warp >> 1, wn = warp & 1;

    float acc[2][4][4] = {};

    for (int k0 = 0; k0 < C_; k0 += 16) {
        #pragma unroll
        for (int i = 0; i < 2; i++) {
            int e4 = i * 256 + tid;
            int m = e4 >> 2, kq = (e4 & 3) << 2;
            float4 w4 = *(const float4*)(Wt + (size_t)(m0 + m) * C_ + k0 + kq);
            unsigned* p = &Ws[m * 20 + kq];
            p[0] = f2tf(w4.x); p[1] = f2tf(w4.y); p[2] = f2tf(w4.z); p[3] = f2tf(w4.w);
        }
        {
            int k = tid >> 4, nq = (tid & 15) << 2;
            float4 x4 = *(const float4*)(Xb + (size_t)(k0 + k) * N_ + n0 + nq);
            unsigned* p = &Xs[k * 72 + nq];
            p[0] = f2tf(x4.x); p[1] = f2tf(x4.y); p[2] = f2tf(x4.z); p[3] = f2tf(x4.w);
        }
        __syncthreads();
        #pragma unroll
        for (int ks = 0; ks < 2; ks++) {
            unsigned a[2][4], bf[4][2];
            const int c = ks * 8 + t;
            #pragma unroll
            for (int mt = 0; mt < 2; mt++) {
                int r = wm * 32 + mt * 16 + g;
                a[mt][0] = Ws[r * 20 + c];       a[mt][1] = Ws[(r + 8) * 20 + c];
                a[mt][2] = Ws[r * 20 + c + 4];   a[mt][3] = Ws[(r + 8) * 20 + c + 4];
            }
            #pragma unroll
            for (int nt = 0; nt < 4; nt++) {
                int n = wn * 32 + nt * 8 + g;
                bf[nt][0] = Xs[c * 72 + n]; bf[nt][1] = Xs[(c + 4) * 72 + n];
            }
            #pragma unroll
            for (int mt = 0; mt < 2; mt++)
                #pragma unroll
                for (int nt = 0; nt < 4; nt++) mma8(acc[mt][nt], a[mt], bf[nt]);
        }
        __syncthreads();
    }

    #pragma unroll
    for (int mt = 0; mt < 2; mt++) {
        int m  = m0 + wm * 32 + mt * 16 + g;
        int m1 = m + 8;
        float sc0 = gg[m]  * rsqrtf(rv[m]  + EPS_), sh0 = bb[m]  - rm[m]  * sc0;
        float sc1 = gg[m1] * rsqrtf(rv[m1] + EPS_), sh1 = bb[m1] - rm[m1] * sc1;
        #pragma unroll
        for (int nt = 0; nt < 4; nt++) {
            int n = n0 + wn * 32 + nt * 8 + 2 * t;
            float* c = acc[mt][nt];
            *(float2*)&Y[((size_t)b * M + m)  * N_ + n] =
                make_float2(silu_f(c[0] * sc0 + sh0), silu_f(c[1] * sc0 + sh0));
            *(float2*)&Y[((size_t)b * M + m1) * N_ + n] =
                make_float2(silu_f(c[2] * sc1 + sh1), silu_f(c[3] * sc1 + sh1));
        }
    }
}

// ============================================================================
// Kernel 3: 3x3 SAME conv (tf32 mma) + BN + SiLU.
// block: 64 out-ch x 256 px (4 image rows). 8 warps (2m x 4n); each warp
// owns one image row (64 px). k-chunk = 16 in-ch x 9 taps.
// grid: (16, 8, B). dyn smem: W taps 46KB + X rows 27.6KB.
// ============================================================================
__global__ void conv3_bn_silu_tc(const float* __restrict__ Wt,  // [O][I][3][3]
                                 const float* __restrict__ Xin, // g_v
                                 const float* __restrict__ gg,
                                 const float* __restrict__ bb,
                                 const float* __restrict__ rm,
                                 const float* __restrict__ rv,
                                 float* __restrict__ Yout)      // g_pp
{
    extern __shared__ unsigned cs[];
    unsigned* Ws = cs;               // [9][64 o][20 pad] (k=16 c)
    unsigned* Xs = cs + 9 * 1280;    // [6 rows][16 c][72 pad] (66 used)

    const int y0 = blockIdx.x * 4;
    const int m0 = blockIdx.y * 64;
    const int b  = blockIdx.z;
    const float* Xb = Xin + (size_t)b * C_ * N_;

    const int tid = threadIdx.x, lane = tid & 31, warp = tid >> 5;
    const int g = lane >> 2, t = lane & 3;
    const int wm = warp >> 2, wn = warp & 3;   // 2m x 4n

    float acc[2][8][4] = {};

    for (int c0 = 0; c0 < C_; c0 += 16) {
        __syncthreads();
        // X: 6 rows (y0-1..y0+4) x 16 ch x 66 (x = -1..64), zero pad
        for (int e = tid; e < 6 * 16 * 66; e += 256) {
            int r = e / 1056; int rem = e - r * 1056;
            int c = rem / 66; int xx = rem - c * 66;
            int gy = y0 - 1 + r, gx = xx - 1;
            float v = 0.0f;
            if (gy >= 0 && gy < H_ && gx >= 0 && gx < W_)
                v = Xb[(size_t)(c0 + c) * N_ + gy * W_ + gx];
            Xs[(r * 16 + c) * 72 + xx] = f2tf(v);
        }
        // W: 64 o x 16 c x 9 taps
        #pragma unroll
        for (int i = 0; i < 4; i++) {
            int p = i * 256 + tid;
            int o = p >> 4, c = p & 15;
            const float* src = Wt + ((size_t)(m0 + o) * C_ + (c0 + c)) * 9;
            #pragma unroll
            for (int tp = 0; tp < 9; tp++)
                Ws[tp * 1280 + o * 20 + c] = f2tf(src[tp]);
        }
        __syncthreads();

        for (int tap = 0; tap < 9; tap++) {
            const int dy = tap / 3, dx = tap - dy * 3;
            const unsigned* Wt_s = Ws + tap * 1280;
            #pragma unroll
            for (int ks = 0; ks < 2; ks++) {
                const int c = ks * 8 + t;
                unsigned a[2][4];
                #pragma unroll
                for (int mt = 0; mt < 2; mt++) {
                    int r = wm * 32 + mt * 16 + g;
                    a[mt][0] = Wt_s[r * 20 + c];     a[mt][1] = Wt_s[(r + 8) * 20 + c];
                    a[mt][2] = Wt_s[r * 20 + c + 4]; a[mt][3] = Wt_s[(r + 8) * 20 + c + 4];
                }
                const int row0 = (wn + dy) * 16 + c;   // smem row for b0; b1 = +4
                #pragma unroll
                for (int nt = 0; nt < 8; nt++) {
                    int xb = nt * 8 + g;               // output x
                    unsigned bf[2];
                    bf[0] = Xs[row0 * 72 + xb + dx];
                    bf[1] = Xs[(row0 + 4) * 72 + xb + dx];
                    mma8(acc[0][nt], a[0], bf);
                    mma8(acc[1][nt], a[1], bf);
                }
            }
        }
    }

    #pragma unroll
    for (int mt = 0; mt < 2; mt++) {
        int m  = m0 + wm * 32 + mt * 16 + g;
        int m1 = m + 8;
        float sc0 = gg[m]  * rsqrtf(rv[m]  + EPS_), sh0 = bb[m]  - rm[m]  * sc0;
        float sc1 = gg[m1] * rsqrtf(rv[m1] + EPS_), sh1 = bb[m1] - rm[m1] * sc1;
        #pragma unroll
        for (int nt = 0; nt < 8; nt++) {
            int n = wn * 64 + nt * 8 + 2 * t;          // px within the 256 tile
            float* c = acc[mt][nt];
            *(float2*)&Yout[((size_t)b * C_ + m)  * N_ + y0 * W_ + n] =
                make_float2(silu_f(c[0] * sc0 + sh0), silu_f(c[1] * sc0 + sh0));
            *(float2*)&Yout[((size_t)b * C_ + m1) * N_ + y0 * W_ + n] =
                make_float2(silu_f(c[2] * sc1 + sh1), silu_f(c[3] * sc1 + sh1));
        }
    }
}

// ============================================================================
// Kernel 4: area attention, tf32 mma flash style.
// block: 64 q rows, loop over 16 key tiles of 64. 8 warps (4m x 2n).
// grid: (16, 8, 32). dyn smem: Qs/Ks/Vs/Ss 64x72 each + softmax rows.
// ============================================================================
__global__ void attn_kernel_tc(const float* __restrict__ qk,
                               const float* __restrict__ vv_g,
                               float* __restrict__ att)
{
    extern __shared__ unsigned as_[];
    unsigned* Qs = as_;                  // [q][d] pad 72 (tf32)
    unsigned* Ks = Qs + 64 * 72;         // [d][key] pad 72
    unsigned* Vs = Ks + 64 * 72;         // [d][key] pad 72
    float*    Ss = (float*)(Vs + 64 * 72);  // [q][key] pad 72 (float, then tf32 p)
    float* mrow = Ss + 64 * 72;
    float* lrow = mrow + 64;
    float* arow = lrow + 64;

    const int q0   = blockIdx.x * 64;
    const int head = blockIdx.y;
    const int ba   = blockIdx.z;
    const int b    = ba >> 2;
    const int area = ba & 3;

    const float* Qb = qk   + ((size_t)b * 2 * C_ +      head * HD_) * N_ + area * NA_;
    const float* Kb = qk   + ((size_t)b * 2 * C_ + C_ + head * HD_) * N_ + area * NA_;
    const float* Vb = vv_g + ((size_t)b * C_     +      head * HD_) * N_ + area * NA_;
    float*       Ob = att  + ((size_t)b * C_     +      head * HD_) * N_ + area * NA_;

    const int tid = threadIdx.x, lane = tid & 31, warp = tid >> 5;
    const int g = lane >> 2, t = lane & 3;
    const int wm = warp >> 1, wn = warp & 1;

    // Q tile (transpose load, once)
    #pragma unroll
    for (int i = 0; i < 4; i++) {
        int e4 = i * 256 + tid;
        int d = e4 >> 4, qq = (e4 & 15) << 2;
        float4 q4 = *(const float4*)(Qb + (size_t)d * N_ + q0 + qq);
        Qs[(qq + 0) * 72 + d] = f2tf(q4.x);
        Qs[(qq + 1) * 72 + d] = f2tf(q4.y);
        Qs[(qq + 2) * 72 + d] = f2tf(q4.z);
        Qs[(qq + 3) * 72 + d] = f2tf(q4.w);
    }
    if (tid < 64) { mrow[tid] = -1e30f; lrow[tid] = 0.0f; }

    float Oacc[4][4] = {};

    for (int j0 = 0; j0 < NA_; j0 += 64) {
        __syncthreads();   // prev iter fully consumed Ks/Vs/Ss; Q visible
        #pragma unroll
        for (int i = 0; i < 4; i++) {
            int e4 = i * 256 + tid;
            int d = e4 >> 4, kq = (e4 & 15) << 2;
            float4 k4 = *(const float4*)(Kb + (size_t)d * N_ + j0 + kq);
            unsigned* pk = &Ks[d * 72 + kq];
            pk[0] = f2tf(k4.x); pk[1] = f2tf(k4.y); pk[2] = f2tf(k4.z); pk[3] = f2tf(k4.w);
            float4 v4 = *(const float4*)(Vb + (size_t)d * N_ + j0 + kq);
            unsigned* pv = &Vs[d * 72 + kq];
            pv[0] = f2tf(v4.x); pv[1] = f2tf(v4.y); pv[2] = f2tf(v4.z); pv[3] = f2tf(v4.w);
        }
        __syncthreads();

        // S = Q K^T
        float Sacc[4][4] = {};
        #pragma unroll
        for (int ks = 0; ks < 8; ks++) {
            const int c = ks * 8 + t;
            const int q = wm * 16 + g;
            unsigned a[4];
            a[0] = Qs[q * 72 + c];       a[1] = Qs[(q + 8) * 72 + c];
            a[2] = Qs[q * 72 + c + 4];   a[3] = Qs[(q + 8) * 72 + c + 4];
            #pragma unroll
            for (int nt = 0; nt < 4; nt++) {
                int key = wn * 32 + nt * 8 + g;
                unsigned bf[2] = { Ks[c * 72 + key], Ks[(c + 4) * 72 + key] };
                mma8(Sacc[nt], a, bf);
            }
        }
        #pragma unroll
        for (int nt = 0; nt < 4; nt++) {
            int q = wm * 16 + g, key = wn * 32 + nt * 8 + 2 * t;
            Ss[q * 72 + key]           = Sacc[nt][0] * 0.125f;
            Ss[q * 72 + key + 1]       = Sacc[nt][1] * 0.125f;
            Ss[(q + 8) * 72 + key]     = Sacc[nt][2] * 0.125f;
            Ss[(q + 8) * 72 + key + 1] = Sacc[nt][3] * 0.125f;
        }
        __syncthreads();

        // online softmax: 4 threads per row
        {
            int row = tid >> 2, sub = tid & 3;
            float* rp = Ss + row * 72 + sub * 16;
            float tm = rp[0];
            #pragma unroll
            for (int j = 1; j < 16; j++) tm = fmaxf(tm, rp[j]);
            tm = fmaxf(tm, __shfl_xor_sync(0xffffffffu, tm, 1));
            tm = fmaxf(tm, __shfl_xor_sync(0xffffffffu, tm, 2));
            float mold = mrow[row];
            float mnew = fmaxf(mold, tm);
            float sum = 0.0f;
            unsigned* rpu = (unsigned*)rp;
            #pragma unroll
            for (int j = 0; j < 16; j++) {
                float p = __expf(rp[j] - mnew);
                sum += p;
                rpu[j] = f2tf(p);
            }
            sum += __shfl_xor_sync(0xffffffffu, sum, 1);
            sum += __shfl_xor_sync(0xffffffffu, sum, 2);
            if (sub == 0) {
                float alpha = __expf(mold - mnew);
                lrow[row] = lrow[row] * alpha + sum;
                mrow[row] = mnew;
                arow[row] = alpha;
            }
        }
        __syncthreads();

        // rescale O, then O += P V
        {
            float al0 = arow[wm * 16 + g], al1 = arow[wm * 16 + g + 8];
            #pragma unroll
            for (int nt = 0; nt < 4; nt++) {
                Oacc[nt][0] *= al0; Oacc[nt][1] *= al0;
                Oacc[nt][2] *= al1; Oacc[nt][3] *= al1;
            }
        }
        const unsigned* Pu = (const unsigned*)Ss;
        #pragma unroll
        for (int ks = 0; ks < 8; ks++) {
            const int c = ks * 8 + t;
            const int q = wm * 16 + g;
            unsigned a[4];
            a[0] = Pu[q * 72 + c];       a[1] = Pu[(q + 8) * 72 + c];
            a[2] = Pu[q * 72 + c + 4];   a[3] = Pu[(q + 8) * 72 + c + 4];
            #pragma unroll
            for (int nt = 0; nt < 4; nt++) {
                int d = wn * 32 + nt * 8 + g;
                unsigned bf[2] = { Vs[d * 72 + c], Vs[d * 72 + c + 4] };
                mma8(Oacc[nt], a, bf);
            }
        }
    }
    __syncthreads();

    float li0 = 1.0f / lrow[wm * 16 + g], li1 = 1.0f / lrow[wm * 16 + g + 8];
    int qp = q0 + wm * 16 + g;
    #pragma unroll
    for (int nt = 0; nt < 4; nt++) {
        int d = wn * 32 + nt * 8 + 2 * t;
        Ob[(size_t)d * N_ + qp]           = Oacc[nt][0] * li0;
        Ob[(size_t)(d + 1) * N_ + qp]     = Oacc[nt][1] * li0;
        Ob[(size_t)d * N_ + qp + 8]       = Oacc[nt][2] * li1;
        Ob[(size_t)(d + 1) * N_ + qp + 8] = Oacc[nt][3] * li1;
    }
}

// ============================================================================
// Kernel 5: final 1x1 conv over (att + pp), BN+SiLU -> d_out (tf32 mma)
// ============================================================================
__global__ void gemm_add_bn_silu_tc(const float* __restrict__ Wt,   // [512][512]
                                    const float* __restrict__ Xa,
                                    const float* __restrict__ Xp,
                                    const float* __restrict__ gg,
                                    const float* __restrict__ bb,
                                    const float* __restrict__ rm,
                                    const float* __restrict__ rv,
                                    float* __restrict__ Y)
{
    __shared__ unsigned Ws[128 * 20];
    __shared__ unsigned Xs[16 * 72];

    const int n0 = blockIdx.x * 64;
    const int m0 = blockIdx.y * 128;
    const int b  = blockIdx.z;
    const float* X1 = Xa + (size_t)b * C_ * N_;
    const float* X2 = Xp + (size_t)b * C_ * N_;

    const int tid = threadIdx.x, lane = tid & 31, warp = tid >> 5;
    const int g = lane >> 2, t = lane & 3;
    const int wm = warp >> 1, wn = warp & 1;

    float acc[2][4][4] = {};

    for (int k0 = 0; k0 < C_; k0 += 16) {
        #pragma unroll
        for (int i = 0; i < 2; i++) {
            int e4 = i * 256 + tid;
            int m = e4 >> 2, kq = (e4 & 3) << 2;
            float4 w4 = *(const float4*)(Wt + (size_t)(m0 + m) * C_ + k0 + kq);
            unsigned* p = &Ws[m * 20 + kq];
            p[0] = f2tf(w4.x); p[1] = f2tf(w4.y); p[2] = f2tf(w4.z); p[3] = f2tf(w4.w);
        }
        {
            int k = tid >> 4, nq = (tid & 15) << 2;
            size_t idx = (size_t)(k0 + k) * N_ + n0 + nq;
            float4 a4 = *(const float4*)(X1 + idx);
            float4 p4 = *(const float4*)(X2 + idx);
            unsigned* p = &Xs[k * 72 + nq];
            p[0] = f2tf(a4.x + p4.x); p[1] = f2tf(a4.y + p4.y);
            p[2] = f2tf(a4.z + p4.z); p[3] = f2tf(a4.w + p4.w);
        }
        __syncthreads();
        #pragma unroll
        for (int ks = 0; ks < 2; ks++) {
            unsigned a[2][4], bf[4][2];
            const int c = ks * 8 + t;
            #pragma unroll
            for (int mt = 0; mt < 2; mt++) {
                int r = wm * 32 + mt * 16 + g;
                a[mt][0] = Ws[r * 20 + c];       a[mt][1] = Ws[(r + 8) * 20 + c];
                a[mt][2] = Ws[r * 20 + c + 4];   a[mt][3] = Ws[(r + 8) * 20 + c + 4];
            }
            #pragma unroll
            for (int nt = 0; nt < 4; nt++) {
                int n = wn * 32 + nt * 8 + g;
                bf[nt][0] = Xs[c * 72 + n]; bf[nt][1] = Xs[(c + 4) * 72 + n];
            }
            #pragma unroll
            for (int mt = 0; mt < 2; mt++)
                #pragma unroll
                for (int nt = 0; nt < 4; nt++) mma8(acc[mt][nt], a[mt], bf[nt]);
        }
        __syncthreads();
    }

    #pragma unroll
    for (int mt = 0; mt < 2; mt++) {
        int m  = m0 + wm * 32 + mt * 16 + g;
        int m1 = m + 8;
        float sc0 = gg[m]  * rsqrtf(rv[m]  + EPS_), sh0 = bb[m]  - rm[m]  * sc0;
        float sc1 = gg[m1] * rsqrtf(rv[m1] + EPS_), sh1 = bb[m1] - rm[m1] * sc1;
        #pragma unroll
        for (int nt = 0; nt < 4; nt++) {
            int n = n0 + wn * 32 + nt * 8 + 2 * t;
            float* c = acc[mt][nt];
            *(float2*)&Y[((size_t)b * C_ + m)  * N_ + n] =
                make_float2(silu_f(c[0] * sc0 + sh0), silu_f(c[1] * sc0 + sh0));
            *(float2*)&Y[((size_t)b * C_ + m1) * N_ + n] =
                make_float2(silu_f(c[2] * sc1 + sh1), silu_f(c[3] * sc1 + sh1));
        }
    }
}

// ============================================================================
extern "C" void kernel_launch(void* const* d_in, const int* in_sizes, int n_in,
                              void* d_out, int out_size)
{
    const float* x     = (const float*)d_in[0];
    const float* qk_w  = (const float*)d_in[1];
    const float* qk_g  = (const float*)d_in[2];
    const float* qk_b  = (const float*)d_in[3];
    const float* qk_rm = (const float*)d_in[4];
    const float* qk_rv = (const float*)d_in[5];
    const float* v_w   = (const float*)d_in[6];
    const float* v_g   = (const float*)d_in[7];
    const float* v_b   = (const float*)d_in[8];
    const float* v_rm  = (const float*)d_in[9];
    const float* v_rv  = (const float*)d_in[10];
    const float* pe_w  = (const float*)d_in[11];
    const float* pe_g  = (const float*)d_in[12];
    const float* pe_b  = (const float*)d_in[13];
    const float* pe_rm = (const float*)d_in[14];
    const float* pe_rv = (const float*)d_in[15];
    const float* pr_w  = (const float*)d_in[16];
    const float* pr_g  = (const float*)d_in[17];
    const float* pr_b  = (const float*)d_in[18];
    const float* pr_rm = (const float*)d_in[19];
    const float* pr_rv = (const float*)d_in[20];
    float* out = (float*)d_out;

    float *p_qk, *p_v, *p_pp, *p_att;
    cudaGetSymbolAddress((void**)&p_qk,  g_qk);
    cudaGetSymbolAddress((void**)&p_v,   g_v);
    cudaGetSymbolAddress((void**)&p_pp,  g_pp);
    cudaGetSymbolAddress((void**)&p_att, g_att);

    const int conv_smem = (9 * 1280 + 6 * 16 * 72) * 4;            // 73728
    const int attn_smem = (4 * 64 * 72 + 3 * 64) * 4;              // 74496
    cudaFuncSetAttribute(conv3_bn_silu_tc,
                         cudaFuncAttributeMaxDynamicSharedMemorySize, conv_smem);
    cudaFuncSetAttribute(attn_kernel_tc,
                         cudaFuncAttributeMaxDynamicSharedMemorySize, attn_smem);

    dim3 thr(256);

    // 1) qk = bn_silu(conv1x1(x, qk_w))   M=1024
    gemm_bn_silu_tc<<<dim3(N_ / 64, 1024 / 128, B_), thr>>>(
        qk_w, x, qk_g, qk_b, qk_rm, qk_rv, p_qk, 1024);

    // 2) vmap = bn_silu(conv1x1(x, v_w))  M=512
    gemm_bn_silu_tc<<<dim3(N_ / 64, C_ / 128, B_), thr>>>(
        v_w, x, v_g, v_b, v_rm, v_rv, p_v, C_);

    // 3) pp = bn_silu(conv3x3(vmap, pe_w))
    conv3_bn_silu_tc<<<dim3(H_ / 4, C_ / 64, B_), thr, conv_smem>>>(
        pe_w, p_v, pe_g, pe_b, pe_rm, pe_rv, p_pp);

    // 4) area attention
    attn_kernel_tc<<<dim3(NA_ / 64, NHEAD, B_ * AREA_), thr, attn_smem>>>(
        p_qk, p_v, p_att);

    // 5) y = bn_silu(conv1x1(att + pp, pr_w))
    gemm_add_bn_silu_tc<<<dim3(N_ / 64, C_ / 128, B_), thr>>>(
        pr_w, p_att, p_pp, pr_g, pr_b, pr_rm, pr_rv, out);
}

// round 4
// speedup vs baseline: 4.8990x; 1.1616x over previous
#include <cuda_runtime.h>
#include <math.h>

#define B_    8
#define C_    512
#define H_    64
#define W_    64
#define N_    4096          // H*W
#define AREA_ 4
#define NHEAD 8
#define HD_   64
#define NA_   1024          // N/AREA
#define EPS_  1e-5f

// ---------------- scratch (device globals; no allocation allowed) ----------
__device__ float g_qk [B_ * 2 * C_ * N_];   // [B][1024][4096]  qk act (post BN+SiLU)
__device__ float g_v  [B_ * C_ * N_];       // [B][512][4096]   v act
__device__ float g_pp [B_ * C_ * N_];       // position embed branch
__device__ float g_att[B_ * C_ * N_];       // attention output, channel-major

__device__ __forceinline__ float silu_f(float y) {
    return y / (1.0f + __expf(-y));
}
__device__ __forceinline__ unsigned f2tf(float x) {
    unsigned u; asm("cvt.rna.tf32.f32 %0, %1;" : "=r"(u) : "f"(x)); return u;
}
// D += A*B, m16n8k8 tf32, row.col
__device__ __forceinline__ void mma8(float* c, const unsigned* a, const unsigned* b) {
    asm volatile(
      "mma.sync.aligned.m16n8k8.row.col.f32.tf32.tf32.f32 "
      "{%0,%1,%2,%3},{%4,%5,%6,%7},{%8,%9},{%0,%1,%2,%3};"
      : "+f"(c[0]), "+f"(c[1]), "+f"(c[2]), "+f"(c[3])
      : "r"(a[0]), "r"(a[1]), "r"(a[2]), "r"(a[3]), "r"(b[0]), "r"(b[1]));
}

// ============================================================================
// 1x1 conv GEMM + BN + SiLU.  Block tile 128m x 128n, 8 warps (4m x 2n),
// warp tile 32m x 64n, k-chunk 16.  grid: (N/128, M/128, B)
// ============================================================================
__global__ __launch_bounds__(256)
void gemm_bn_silu_tc(const float* __restrict__ Wt,   // [M][512]
                     const float* __restrict__ X,    // [B][512][N]
                     const float* __restrict__ gg,
                     const float* __restrict__ bb,
                     const float* __restrict__ rm,
                     const float* __restrict__ rv,
                     float* __restrict__ Y, int M)
{
    __shared__ unsigned Ws[128 * 20];   // [m][k]
    __shared__ unsigned Xs[16 * 136];   // [k][n]

    const int n0 = blockIdx.x * 128;
    const int m0 = blockIdx.y * 128;
    const int b  = blockIdx.z;
    const float* Xb = X + (size_t)b * C_ * N_;

    const int tid = threadIdx.x, lane = tid & 31, warp = tid >> 5;
    const int g = lane >> 2, t = lane & 3;
    const int wm = warp >> 1, wn = warp & 1;

    float acc[2][8][4] = {};

    for (int k0 = 0; k0 < C_; k0 += 16) {
        #pragma unroll
        for (int i = 0; i < 2; i++) {
            int e4 = i * 256 + tid;
            int m = e4 >> 2, kq = (e4 & 3) << 2;
            float4 w4 = *(const float4*)(Wt + (size_t)(m0 + m) * C_ + k0 + kq);
            unsigned* p = &Ws[m * 20 + kq];
            p[0] = f2tf(w4.x); p[1] = f2tf(w4.y); p[2] = f2tf(w4.z); p[3] = f2tf(w4.w);
        }
        #pragma unroll
        for (int i = 0; i < 2; i++) {
            int e4 = i * 256 + tid;
            int k = e4 >> 5, nq = (e4 & 31) << 2;
            float4 x4 = *(const float4*)(Xb + (size_t)(k0 + k) * N_ + n0 + nq);
            unsigned* p = &Xs[k * 136 + nq];
            p[0] = f2tf(x4.x); p[1] = f2tf(x4.y); p[2] = f2tf(x4.z); p[3] = f2tf(x4.w);
        }
        __syncthreads();
        #pragma unroll
        for (int ks = 0; ks < 2; ks++) {
            const int c = ks * 8 + t;
            unsigned a[2][4];
            #pragma unroll
            for (int mt = 0; mt < 2; mt++) {
                int r = wm * 32 + mt * 16 + g;
                a[mt][0] = Ws[r * 20 + c];       a[mt][1] = Ws[(r + 8) * 20 + c];
                a[mt][2] = Ws[r * 20 + c + 4];   a[mt][3] = Ws[(r + 8) * 20 + c + 4];
            }
            #pragma unroll
            for (int nt = 0; nt < 8; nt++) {
                int n = wn * 64 + nt * 8 + g;
                unsigned bf[2] = { Xs[c * 136 + n], Xs[(c + 4) * 136 + n] };
                mma8(acc[0][nt], a[0], bf);
                mma8(acc[1][nt], a[1], bf);
            }
        }
        __syncthreads();
    }

    #pragma unroll
    for (int mt = 0; mt < 2; mt++) {
        int m  = m0 + wm * 32 + mt * 16 + g;
        int m1 = m + 8;
        float sc0 = gg[m]  * rsqrtf(rv[m]  + EPS_), sh0 = bb[m]  - rm[m]  * sc0;
        float sc1 = gg[m1] * rsqrtf(rv[m1] + EPS_), sh1 = bb[m1] - rm[m1] * sc1;
        #pragma unroll
        for (int nt = 0; nt < 8; nt++) {
            int n = n0 + wn * 64 + nt * 8 + 2 * t;
            float* c = acc[mt][nt];
            *(float2*)&Y[((size_t)b * M + m)  * N_ + n] =
                make_float2(silu_f(c[0] * sc0 + sh0), silu_f(c[1] * sc0 + sh0));
            *(float2*)&Y[((size_t)b * M + m1) * N_ + n] =
                make_float2(silu_f(c[2] * sc1 + sh1), silu_f(c[3] * sc1 + sh1));
        }
    }
}

// ============================================================================
// 3x3 SAME conv (tf32 mma) + BN + SiLU.  (unchanged from round 3)
// ============================================================================
__global__ void conv3_bn_silu_tc(const float* __restrict__ Wt,  // [O][I][3][3]
                                 const float* __restrict__ Xin, // g_v
                                 const float* __restrict__ gg,
                                 const float* __restrict__ bb,
                                 const float* __restrict__ rm,
                                 const float* __restrict__ rv,
                                 float* __restrict__ Yout)      // g_pp
{
    extern __shared__ unsigned cs[];
    unsigned* Ws = cs;               // [9][64 o][20 pad]
    unsigned* Xs = cs + 9 * 1280;    // [6 rows][16 c][72 pad]

    const int y0 = blockIdx.x * 4;
    const int m0 = blockIdx.y * 64;
    const int b  = blockIdx.z;
    const float* Xb = Xin + (size_t)b * C_ * N_;

    const int tid = threadIdx.x, lane = tid & 31, warp = tid >> 5;
    const int g = lane >> 2, t = lane & 3;
    const int wm = warp >> 2, wn = warp & 3;   // 2m x 4n

    float acc[2][8][4] = {};

    for (int c0 = 0; c0 < C_; c0 += 16) {
        __syncthreads();
        for (int e = tid; e < 6 * 16 * 66; e += 256) {
            int r = e / 1056; int rem = e - r * 1056;
            int c = rem / 66; int xx = rem - c * 66;
            int gy = y0 - 1 + r, gx = xx - 1;
            float v = 0.0f;
            if (gy >= 0 && gy < H_ && gx >= 0 && gx < W_)
                v = Xb[(size_t)(c0 + c) * N_ + gy * W_ + gx];
            Xs[(r * 16 + c) * 72 + xx] = f2tf(v);
        }
        #pragma unroll
        for (int i = 0; i < 4; i++) {
            int p = i * 256 + tid;
            int o = p >> 4, c = p & 15;
            const float* src = Wt + ((size_t)(m0 + o) * C_ + (c0 + c)) * 9;
            #pragma unroll
            for (int tp = 0; tp < 9; tp++)
                Ws[tp * 1280 + o * 20 + c] = f2tf(src[tp]);
        }
        __syncthreads();

        for (int tap = 0; tap < 9; tap++) {
            const int dy = tap / 3, dx = tap - dy * 3;
            const unsigned* Wt_s = Ws + tap * 1280;
            #pragma unroll
            for (int ks = 0; ks < 2; ks++) {
                const int c = ks * 8 + t;
                unsigned a[2][4];
                #pragma unroll
                for (int mt = 0; mt < 2; mt++) {
                    int r = wm * 32 + mt * 16 + g;
                    a[mt][0] = Wt_s[r * 20 + c];     a[mt][1] = Wt_s[(r + 8) * 20 + c];
                    a[mt][2] = Wt_s[r * 20 + c + 4]; a[mt][3] = Wt_s[(r + 8) * 20 + c + 4];
                }
                const int row0 = (wn + dy) * 16 + c;
                #pragma unroll
                for (int nt = 0; nt < 8; nt++) {
                    int xb = nt * 8 + g;
                    unsigned bf[2];
                    bf[0] = Xs[row0 * 72 + xb + dx];
                    bf[1] = Xs[(row0 + 4) * 72 + xb + dx];
                    mma8(acc[0][nt], a[0], bf);
                    mma8(acc[1][nt], a[1], bf);
                }
            }
        }
    }

    #pragma unroll
    for (int mt = 0; mt < 2; mt++) {
        int m  = m0 + wm * 32 + mt * 16 + g;
        int m1 = m + 8;
        float sc0 = gg[m]  * rsqrtf(rv[m]  + EPS_), sh0 = bb[m]  - rm[m]  * sc0;
        float sc1 = gg[m1] * rsqrtf(rv[m1] + EPS_), sh1 = bb[m1] - rm[m1] * sc1;
        #pragma unroll
        for (int nt = 0; nt < 8; nt++) {
            int n = wn * 64 + nt * 8 + 2 * t;
            float* c = acc[mt][nt];
            *(float2*)&Yout[((size_t)b * C_ + m)  * N_ + y0 * W_ + n] =
                make_float2(silu_f(c[0] * sc0 + sh0), silu_f(c[1] * sc0 + sh0));
            *(float2*)&Yout[((size_t)b * C_ + m1) * N_ + y0 * W_ + n] =
                make_float2(silu_f(c[2] * sc1 + sh1), silu_f(c[3] * sc1 + sh1));
        }
    }
}

// ============================================================================
// Area attention, register-resident FA2 style.
// Block = 128 q rows; 8 warps, each 16 q x all 64 keys x d=64.
// Q frags + S/P/O + softmax state in registers; only K/V in smem.
// grid: (NA/128=8, NHEAD, 32)
// ============================================================================
__global__ __launch_bounds__(256)
void attn_tc2(const float* __restrict__ qk,
              const float* __restrict__ vv_g,
              float* __restrict__ att)
{
    extern __shared__ unsigned as_[];
    unsigned* Ks  = as_;             // [64][72]  (4608 w)
    unsigned* Vs  = as_ + 64 * 72;   // [64][68]  (4352 w)
    unsigned* Qst = as_;             // [128][70] staging (aliased, 8960 w)
    float*    Os  = (float*)as_;     // [128][68] out staging (aliased)

    const int q0   = blockIdx.x * 128;
    const int head = blockIdx.y;
    const int ba   = blockIdx.z;
    const int b    = ba >> 2;
    const int area = ba & 3;

    const float* Qb = qk   + ((size_t)b * 2 * C_ +      head * HD_) * N_ + area * NA_;
    const float* Kb = qk   + ((size_t)b * 2 * C_ + C_ + head * HD_) * N_ + area * NA_;
    const float* Vb = vv_g + ((size_t)b * C_     +      head * HD_) * N_ + area * NA_;
    float*       Ob = att  + ((size_t)b * C_     +      head * HD_) * N_ + area * NA_;

    const int tid = threadIdx.x, lane = tid & 31, warp = tid >> 5;
    const int g = lane >> 2, t = lane & 3;
    const int wq = warp * 16;

    // ---- stage Q [q][d] (transpose), extract per-warp fragments, once ----
    #pragma unroll
    for (int i = 0; i < 8; i++) {
        int e4 = i * 256 + tid;
        int d = e4 >> 5, qq = (e4 & 31) << 2;
        float4 q4 = *(const float4*)(Qb + (size_t)d * N_ + q0 + qq);
        Qst[(qq + 0) * 70 + d] = f2tf(q4.x);
        Qst[(qq + 1) * 70 + d] = f2tf(q4.y);
        Qst[(qq + 2) * 70 + d] = f2tf(q4.z);
        Qst[(qq + 3) * 70 + d] = f2tf(q4.w);
    }
    __syncthreads();
    unsigned qf[8][4];
    #pragma unroll
    for (int kc = 0; kc < 8; kc++) {
        int c = kc * 8 + t;
        qf[kc][0] = Qst[(wq + g)     * 70 + c];
        qf[kc][1] = Qst[(wq + 8 + g) * 70 + c];
        qf[kc][2] = Qst[(wq + g)     * 70 + c + 4];
        qf[kc][3] = Qst[(wq + 8 + g) * 70 + c + 4];
    }

    float mr0 = -1e30f, mr1 = -1e30f, lr0 = 0.0f, lr1 = 0.0f;
    float Oa[8][4] = {};
    const int sb = lane & ~3;
    const int s1l = sb + (t >> 1), s2l = s1l + 2;

    for (int j0 = 0; j0 < NA_; j0 += 64) {
        __syncthreads();   // prior consumers of Ks/Vs (or Qst) done
        #pragma unroll
        for (int i = 0; i < 4; i++) {
            int e4 = i * 256 + tid;
            int d = e4 >> 4, kq = (e4 & 15) << 2;
            float4 k4 = *(const float4*)(Kb + (size_t)d * N_ + j0 + kq);
            *(uint4*)&Ks[d * 72 + kq] =
                make_uint4(f2tf(k4.x), f2tf(k4.y), f2tf(k4.z), f2tf(k4.w));
            float4 v4 = *(const float4*)(Vb + (size_t)d * N_ + j0 + kq);
            *(uint4*)&Vs[d * 68 + kq] =
                make_uint4(f2tf(v4.x), f2tf(v4.y), f2tf(v4.z), f2tf(v4.w));
        }
        __syncthreads();

        // ---- S = Q K^T (16 x 64 per warp, registers) ----
        float S[8][4] = {};
        #pragma unroll
        for (int kc = 0; kc < 8; kc++) {
            const int c = kc * 8 + t;
            #pragma unroll
            for (int nt = 0; nt < 8; nt++) {
                unsigned bf[2] = { Ks[c * 72 + nt * 8 + g], Ks[(c + 4) * 72 + nt * 8 + g] };
                mma8(S[nt], qf[kc], bf);
            }
        }

        // ---- online softmax, fully in registers (rows g and g+8) ----
        float mx0 = -1e30f, mx1 = -1e30f;
        #pragma unroll
        for (int nt = 0; nt < 8; nt++) {
            S[nt][0] *= 0.125f; S[nt][1] *= 0.125f;
            S[nt][2] *= 0.125f; S[nt][3] *= 0.125f;
            mx0 = fmaxf(mx0, fmaxf(S[nt][0], S[nt][1]));
            mx1 = fmaxf(mx1, fmaxf(S[nt][2], S[nt][3]));
        }
        mx0 = fmaxf(mx0, __shfl_xor_sync(0xffffffffu, mx0, 1));
        mx0 = fmaxf(mx0, __shfl_xor_sync(0xffffffffu, mx0, 2));
        mx1 = fmaxf(mx1, __shfl_xor_sync(0xffffffffu, mx1, 1));
        mx1 = fmaxf(mx1, __shfl_xor_sync(0xffffffffu, mx1, 2));
        float mn0 = fmaxf(mr0, mx0), mn1 = fmaxf(mr1, mx1);
        float al0 = __expf(mr0 - mn0), al1 = __expf(mr1 - mn1);
        mr0 = mn0; mr1 = mn1;
        float s0 = 0.0f, s1 = 0.0f;
        unsigned P[8][4];
        #pragma unroll
        for (int nt = 0; nt < 8; nt++) {
            float p0 = __expf(S[nt][0] - mn0), p1 = __expf(S[nt][1] - mn0);
            float p2 = __expf(S[nt][2] - mn1), p3 = __expf(S[nt][3] - mn1);
            s0 += p0 + p1; s1 += p2 + p3;
            P[nt][0] = f2tf(p0); P[nt][1] = f2tf(p1);
            P[nt][2] = f2tf(p2); P[nt][3] = f2tf(p3);
        }
        s0 += __shfl_xor_sync(0xffffffffu, s0, 1);
        s0 += __shfl_xor_sync(0xffffffffu, s0, 2);
        s1 += __shfl_xor_sync(0xffffffffu, s1, 1);
        s1 += __shfl_xor_sync(0xffffffffu, s1, 2);
        lr0 = lr0 * al0 + s0; lr1 = lr1 * al1 + s1;

        #pragma unroll
        for (int dt = 0; dt < 8; dt++) {
            Oa[dt][0] *= al0; Oa[dt][1] *= al0;
            Oa[dt][2] *= al1; Oa[dt][3] *= al1;
        }

        // ---- O += P V ; P C-frag -> A-frag via lane shuffles ----
        #pragma unroll
        for (int kc = 0; kc < 8; kc++) {
            unsigned x0 = __shfl_sync(0xffffffffu, P[kc][0], s1l);
            unsigned x1 = __shfl_sync(0xffffffffu, P[kc][1], s1l);
            unsigned x2 = __shfl_sync(0xffffffffu, P[kc][2], s1l);
            unsigned x3 = __shfl_sync(0xffffffffu, P[kc][3], s1l);
            unsigned y0 = __shfl_sync(0xffffffffu, P[kc][0], s2l);
            unsigned y1 = __shfl_sync(0xffffffffu, P[kc][1], s2l);
            unsigned y2 = __shfl_sync(0xffffffffu, P[kc][2], s2l);
            unsigned y3 = __shfl_sync(0xffffffffu, P[kc][3], s2l);
            unsigned av[4];
            if (t & 1) { av[0] = x1; av[1] = x3; av[2] = y1; av[3] = y3; }
            else       { av[0] = x0; av[1] = x2; av[2] = y0; av[3] = y2; }
            #pragma unroll
            for (int dt = 0; dt < 8; dt++) {
                unsigned bf[2] = { Vs[(dt * 8 + g) * 68 + kc * 8 + t],
                                   Vs[(dt * 8 + g) * 68 + kc * 8 + t + 4] };
                mma8(Oa[dt], av, bf);
            }
        }
    }

    // ---- epilogue: normalize, stage through smem, coalesced [d][q] store ----
    __syncthreads();
    float li0 = 1.0f / lr0, li1 = 1.0f / lr1;
    #pragma unroll
    for (int dt = 0; dt < 8; dt++) {
        Os[(wq + g)     * 68 + dt * 8 + 2 * t]     = Oa[dt][0] * li0;
        Os[(wq + g)     * 68 + dt * 8 + 2 * t + 1] = Oa[dt][1] * li0;
        Os[(wq + 8 + g) * 68 + dt * 8 + 2 * t]     = Oa[dt][2] * li1;
        Os[(wq + 8 + g) * 68 + dt * 8 + 2 * t + 1] = Oa[dt][3] * li1;
    }
    __syncthreads();
    #pragma unroll
    for (int i = 0; i < 8; i++) {
        int e4 = i * 256 + tid;
        int d = e4 >> 5, qq = (e4 & 31) << 2;
        float4 o4 = make_float4(Os[(qq + 0) * 68 + d], Os[(qq + 1) * 68 + d],
                                Os[(qq + 2) * 68 + d], Os[(qq + 3) * 68 + d]);
        *(float4*)(Ob + (size_t)d * N_ + q0 + qq) = o4;
    }
}

// ============================================================================
// Final 1x1 conv over (att + pp), BN+SiLU -> d_out.  128x128 tiles.
// ============================================================================
__global__ __launch_bounds__(256)
void gemm_add_bn_silu_tc(const float* __restrict__ Wt,   // [512][512]
                         const float* __restrict__ Xa,
                         const float* __restrict__ Xp,
                         const float* __restrict__ gg,
                         const float* __restrict__ bb,
                         const float* __restrict__ rm,
                         const float* __restrict__ rv,
                         float* __restrict__ Y)
{
    __shared__ unsigned Ws[128 * 20];
    __shared__ unsigned Xs[16 * 136];

    const int n0 = blockIdx.x * 128;
    const int m0 = blockIdx.y * 128;
    const int b  = blockIdx.z;
    const float* X1 = Xa + (size_t)b * C_ * N_;
    const float* X2 = Xp + (size_t)b * C_ * N_;

    const int tid = threadIdx.x, lane = tid & 31, warp = tid >> 5;
    const int g = lane >> 2, t = lane & 3;
    const int wm = warp >> 1, wn = warp & 1;

    float acc[2][8][4] = {};

    for (int k0 = 0; k0 < C_; k0 += 16) {
        #pragma unroll
        for (int i = 0; i < 2; i++) {
            int e4 = i * 256 + tid;
            int m = e4 >> 2, kq = (e4 & 3) << 2;
            float4 w4 = *(const float4*)(Wt + (size_t)(m0 + m) * C_ + k0 + kq);
            unsigned* p = &Ws[m * 20 + kq];
            p[0] = f2tf(w4.x); p[1] = f2tf(w4.y); p[2] = f2tf(w4.z); p[3] = f2tf(w4.w);
        }
        #pragma unroll
        for (int i = 0; i < 2; i++) {
            int e4 = i * 256 + tid;
            int k = e4 >> 5, nq = (e4 & 31) << 2;
            size_t idx = (size_t)(k0 + k) * N_ + n0 + nq;
            float4 a4 = *(const float4*)(X1 + idx);
            float4 p4 = *(const float4*)(X2 + idx);
            unsigned* p = &Xs[k * 136 + nq];
            p[0] = f2tf(a4.x + p4.x); p[1] = f2tf(a4.y + p4.y);
            p[2] = f2tf(a4.z + p4.z); p[3] = f2tf(a4.w + p4.w);
        }
        __syncthreads();
        #pragma unroll
        for (int ks = 0; ks < 2; ks++) {
            const int c = ks * 8 + t;
            unsigned a[2][4];
            #pragma unroll
            for (int mt = 0; mt < 2; mt++) {
                int r = wm * 32 + mt * 16 + g;
                a[mt][0] = Ws[r * 20 + c];       a[mt][1] = Ws[(r + 8) * 20 + c];
                a[mt][2] = Ws[r * 20 + c + 4];   a[mt][3] = Ws[(r + 8) * 20 + c + 4];
            }
            #pragma unroll
            for (int nt = 0; nt < 8; nt++) {
                int n = wn * 64 + nt * 8 + g;
                unsigned bf[2] = { Xs[c * 136 + n], Xs[(c + 4) * 136 + n] };
                mma8(acc[0][nt], a[0], bf);
                mma8(acc[1][nt], a[1], bf);
            }
        }
        __syncthreads();
    }

    #pragma unroll
    for (int mt = 0; mt < 2; mt++) {
        int m  = m0 + wm * 32 + mt * 16 + g;
        int m1 = m + 8;
        float sc0 = gg[m]  * rsqrtf(rv[m]  + EPS_), sh0 = bb[m]  - rm[m]  * sc0;
        float sc1 = gg[m1] * rsqrtf(rv[m1] + EPS_), sh1 = bb[m1] - rm[m1] * sc1;
        #pragma unroll
        for (int nt = 0; nt < 8; nt++) {
            int n = n0 + wn * 64 + nt * 8 + 2 * t;
            float* c = acc[mt][nt];
            *(float2*)&Y[((size_t)b * C_ + m)  * N_ + n] =
                make_float2(silu_f(c[0] * sc0 + sh0), silu_f(c[1] * sc0 + sh0));
            *(float2*)&Y[((size_t)b * C_ + m1) * N_ + n] =
                make_float2(silu_f(c[2] * sc1 + sh1), silu_f(c[3] * sc1 + sh1));
        }
    }
}

// ============================================================================
extern "C" void kernel_launch(void* const* d_in, const int* in_sizes, int n_in,
                              void* d_out, int out_size)
{
    const float* x     = (const float*)d_in[0];
    const float* qk_w  = (const float*)d_in[1];
    const float* qk_g  = (const float*)d_in[2];
    const float* qk_b  = (const float*)d_in[3];
    const float* qk_rm = (const float*)d_in[4];
    const float* qk_rv = (const float*)d_in[5];
    const float* v_w   = (const float*)d_in[6];
    const float* v_g   = (const float*)d_in[7];
    const float* v_b   = (const float*)d_in[8];
    const float* v_rm  = (const float*)d_in[9];
    const float* v_rv  = (const float*)d_in[10];
    const float* pe_w  = (const float*)d_in[11];
    const float* pe_g  = (const float*)d_in[12];
    const float* pe_b  = (const float*)d_in[13];
    const float* pe_rm = (const float*)d_in[14];
    const float* pe_rv = (const float*)d_in[15];
    const float* pr_w  = (const float*)d_in[16];
    const float* pr_g  = (const float*)d_in[17];
    const float* pr_b  = (const float*)d_in[18];
    const float* pr_rm = (const float*)d_in[19];
    const float* pr_rv = (const float*)d_in[20];
    float* out = (float*)d_out;

    float *p_qk, *p_v, *p_pp, *p_att;
    cudaGetSymbolAddress((void**)&p_qk,  g_qk);
    cudaGetSymbolAddress((void**)&p_v,   g_v);
    cudaGetSymbolAddress((void**)&p_pp,  g_pp);
    cudaGetSymbolAddress((void**)&p_att, g_att);

    const int conv_smem = (9 * 1280 + 6 * 16 * 72) * 4;            // 73728
    const int attn_smem = (64 * 72 + 64 * 68) * 4;                 // 35840
    cudaFuncSetAttribute(conv3_bn_silu_tc,
                         cudaFuncAttributeMaxDynamicSharedMemorySize, conv_smem);

    dim3 thr(256);

    // 1) qk = bn_silu(conv1x1(x, qk_w))   M=1024
    gemm_bn_silu_tc<<<dim3(N_ / 128, 1024 / 128, B_), thr>>>(
        qk_w, x, qk_g, qk_b, qk_rm, qk_rv, p_qk, 1024);

    // 2) vmap = bn_silu(conv1x1(x, v_w))  M=512
    gemm_bn_silu_tc<<<dim3(N_ / 128, C_ / 128, B_), thr>>>(
        v_w, x, v_g, v_b, v_rm, v_rv, p_v, C_);

    // 3) pp = bn_silu(conv3x3(vmap, pe_w))
    conv3_bn_silu_tc<<<dim3(H_ / 4, C_ / 64, B_), thr, conv_smem>>>(
        pe_w, p_v, pe_g, pe_b, pe_rm, pe_rv, p_pp);

    // 4) area attention (register-resident)
    attn_tc2<<<dim3(NA_ / 128, NHEAD, B_ * AREA_), thr, attn_smem>>>(
        p_qk, p_v, p_att);

    // 5) y = bn_silu(conv1x1(att + pp, pr_w))
    gemm_add_bn_silu_tc<<<dim3(N_ / 128, C_ / 128, B_), thr>>>(
        pr_w, p_att, p_pp, pr_g, pr_b, pr_rm, pr_rv, out);
}

// round 5
// speedup vs baseline: 5.2331x; 1.0682x over previous
#include <cuda_runtime.h>
#include <math.h>

#define B_    8
#define C_    512
#define H_    64
#define W_    64
#define N_    4096          // H*W
#define AREA_ 4
#define NHEAD 8
#define HD_   64
#define NA_   1024          // N/AREA
#define EPS_  1e-5f

// ---------------- scratch (device globals; no allocation allowed) ----------
__device__ float g_qk [B_ * 2 * C_ * N_];   // [B][1024][4096]  qk act (post BN+SiLU)
__device__ float g_v  [B_ * C_ * N_];       // [B][512][4096]   v act
__device__ float g_pp [B_ * C_ * N_];       // position embed branch
__device__ float g_att[B_ * C_ * N_];       // attention output, channel-major

__device__ __forceinline__ float silu_f(float y) {
    return y / (1.0f + __expf(-y));
}
__device__ __forceinline__ unsigned f2tf(float x) {
    unsigned u; asm("cvt.rna.tf32.f32 %0, %1;" : "=r"(u) : "f"(x)); return u;
}
// D += A*B, m16n8k8 tf32, row.col
__device__ __forceinline__ void mma8(float* c, const unsigned* a, const unsigned* b) {
    asm volatile(
      "mma.sync.aligned.m16n8k8.row.col.f32.tf32.tf32.f32 "
      "{%0,%1,%2,%3},{%4,%5,%6,%7},{%8,%9},{%0,%1,%2,%3};"
      : "+f"(c[0]), "+f"(c[1]), "+f"(c[2]), "+f"(c[3])
      : "r"(a[0]), "r"(a[1]), "r"(a[2]), "r"(a[3]), "r"(b[0]), "r"(b[1]));
}

// ============================================================================
// 1x1 conv GEMM + BN + SiLU.  Block tile 128m x 128n, 8 warps (4m x 2n),
// warp tile 32m x 64n, k-chunk 16, register double-buffered gmem loads.
// grid: (N/128, M/128, B)
// ============================================================================
__global__ __launch_bounds__(256, 2)
void gemm_bn_silu_tc(const float* __restrict__ Wt,   // [M][512]
                     const float* __restrict__ X,    // [B][512][N]
                     const float* __restrict__ gg,
                     const float* __restrict__ bb,
                     const float* __restrict__ rm,
                     const float* __restrict__ rv,
                     float* __restrict__ Y, int M)
{
    __shared__ unsigned Ws[128 * 20];   // [m][k]
    __shared__ unsigned Xs[16 * 136];   // [k][n]

    const int n0 = blockIdx.x * 128;
    const int m0 = blockIdx.y * 128;
    const int b  = blockIdx.z;
    const float* Xb = X + (size_t)b * C_ * N_;

    const int tid = threadIdx.x, lane = tid & 31, warp = tid >> 5;
    const int g = lane >> 2, t = lane & 3;
    const int wm = warp >> 1, wn = warp & 1;

    // per-thread load coordinates
    const int wm0 = tid >> 2,            wk0 = (tid & 3) << 2;        // W half 0
    const int wm1 = (256 + tid) >> 2,    wk1 = ((256 + tid) & 3) << 2;
    const int xk0 = tid >> 5,            xn0 = (tid & 31) << 2;
    const int xk1 = (256 + tid) >> 5,    xn1 = ((256 + tid) & 31) << 2;

    float acc[2][8][4] = {};
    float4 w4a, w4b, x4a, x4b;

    // preload k0 = 0
    w4a = *(const float4*)(Wt + (size_t)(m0 + wm0) * C_ + wk0);
    w4b = *(const float4*)(Wt + (size_t)(m0 + wm1) * C_ + wk1);
    x4a = *(const float4*)(Xb + (size_t)xk0 * N_ + n0 + xn0);
    x4b = *(const float4*)(Xb + (size_t)xk1 * N_ + n0 + xn1);

    for (int k0 = 0; k0 < C_; k0 += 16) {
        {   // STS (convert) current chunk
            unsigned* p;
            p = &Ws[wm0 * 20 + wk0];
            p[0]=f2tf(w4a.x); p[1]=f2tf(w4a.y); p[2]=f2tf(w4a.z); p[3]=f2tf(w4a.w);
            p = &Ws[wm1 * 20 + wk1];
            p[0]=f2tf(w4b.x); p[1]=f2tf(w4b.y); p[2]=f2tf(w4b.z); p[3]=f2tf(w4b.w);
            p = &Xs[xk0 * 136 + xn0];
            p[0]=f2tf(x4a.x); p[1]=f2tf(x4a.y); p[2]=f2tf(x4a.z); p[3]=f2tf(x4a.w);
            p = &Xs[xk1 * 136 + xn1];
            p[0]=f2tf(x4b.x); p[1]=f2tf(x4b.y); p[2]=f2tf(x4b.z); p[3]=f2tf(x4b.w);
        }
        __syncthreads();
        if (k0 + 16 < C_) {   // prefetch next chunk (latency overlapped w/ mma)
            int kn = k0 + 16;
            w4a = *(const float4*)(Wt + (size_t)(m0 + wm0) * C_ + kn + wk0);
            w4b = *(const float4*)(Wt + (size_t)(m0 + wm1) * C_ + kn + wk1);
            x4a = *(const float4*)(Xb + (size_t)(kn + xk0) * N_ + n0 + xn0);
            x4b = *(const float4*)(Xb + (size_t)(kn + xk1) * N_ + n0 + xn1);
        }
        #pragma unroll
        for (int ks = 0; ks < 2; ks++) {
            const int c = ks * 8 + t;
            unsigned a[2][4];
            #pragma unroll
            for (int mt = 0; mt < 2; mt++) {
                int r = wm * 32 + mt * 16 + g;
                a[mt][0] = Ws[r * 20 + c];       a[mt][1] = Ws[(r + 8) * 20 + c];
                a[mt][2] = Ws[r * 20 + c + 4];   a[mt][3] = Ws[(r + 8) * 20 + c + 4];
            }
            #pragma unroll
            for (int nt = 0; nt < 8; nt++) {
                int n = wn * 64 + nt * 8 + g;
                unsigned bf[2] = { Xs[c * 136 + n], Xs[(c + 4) * 136 + n] };
                mma8(acc[0][nt], a[0], bf);
                mma8(acc[1][nt], a[1], bf);
            }
        }
        __syncthreads();
    }

    #pragma unroll
    for (int mt = 0; mt < 2; mt++) {
        int m  = m0 + wm * 32 + mt * 16 + g;
        int m1 = m + 8;
        float sc0 = gg[m]  * rsqrtf(rv[m]  + EPS_), sh0 = bb[m]  - rm[m]  * sc0;
        float sc1 = gg[m1] * rsqrtf(rv[m1] + EPS_), sh1 = bb[m1] - rm[m1] * sc1;
        #pragma unroll
        for (int nt = 0; nt < 8; nt++) {
            int n = n0 + wn * 64 + nt * 8 + 2 * t;
            float* c = acc[mt][nt];
            *(float2*)&Y[((size_t)b * M + m)  * N_ + n] =
                make_float2(silu_f(c[0] * sc0 + sh0), silu_f(c[1] * sc0 + sh0));
            *(float2*)&Y[((size_t)b * M + m1) * N_ + n] =
                make_float2(silu_f(c[2] * sc1 + sh1), silu_f(c[3] * sc1 + sh1));
        }
    }
}

// ============================================================================
// 3x3 SAME conv (tf32 mma) + BN + SiLU.  (unchanged)
// ============================================================================
__global__ void conv3_bn_silu_tc(const float* __restrict__ Wt,  // [O][I][3][3]
                                 const float* __restrict__ Xin, // g_v
                                 const float* __restrict__ gg,
                                 const float* __restrict__ bb,
                                 const float* __restrict__ rm,
                                 const float* __restrict__ rv,
                                 float* __restrict__ Yout)      // g_pp
{
    extern __shared__ unsigned cs[];
    unsigned* Ws = cs;               // [9][64 o][20 pad]
    unsigned* Xs = cs + 9 * 1280;    // [6 rows][16 c][72 pad]

    const int y0 = blockIdx.x * 4;
    const int m0 = blockIdx.y * 64;
    const int b  = blockIdx.z;
    const float* Xb = Xin + (size_t)b * C_ * N_;

    const int tid = threadIdx.x, lane = tid & 31, warp = tid >> 5;
    const int g = lane >> 2, t = lane & 3;
    const int wm = warp >> 2, wn = warp & 3;   // 2m x 4n

    float acc[2][8][4] = {};

    for (int c0 = 0; c0 < C_; c0 += 16) {
        __syncthreads();
        for (int e = tid; e < 6 * 16 * 66; e += 256) {
            int r = e / 1056; int rem = e - r * 1056;
            int c = rem / 66; int xx = rem - c * 66;
            int gy = y0 - 1 + r, gx = xx - 1;
            float v = 0.0f;
            if (gy >= 0 && gy < H_ && gx >= 0 && gx < W_)
                v = Xb[(size_t)(c0 + c) * N_ + gy * W_ + gx];
            Xs[(r * 16 + c) * 72 + xx] = f2tf(v);
        }
        #pragma unroll
        for (int i = 0; i < 4; i++) {
            int p = i * 256 + tid;
            int o = p >> 4, c = p & 15;
            const float* src = Wt + ((size_t)(m0 + o) * C_ + (c0 + c)) * 9;
            #pragma unroll
            for (int tp = 0; tp < 9; tp++)
                Ws[tp * 1280 + o * 20 + c] = f2tf(src[tp]);
        }
        __syncthreads();

        for (int tap = 0; tap < 9; tap++) {
            const int dy = tap / 3, dx = tap - dy * 3;
            const unsigned* Wt_s = Ws + tap * 1280;
            #pragma unroll
            for (int ks = 0; ks < 2; ks++) {
                const int c = ks * 8 + t;
                unsigned a[2][4];
                #pragma unroll
                for (int mt = 0; mt < 2; mt++) {
                    int r = wm * 32 + mt * 16 + g;
                    a[mt][0] = Wt_s[r * 20 + c];     a[mt][1] = Wt_s[(r + 8) * 20 + c];
                    a[mt][2] = Wt_s[r * 20 + c + 4]; a[mt][3] = Wt_s[(r + 8) * 20 + c + 4];
                }
                const int row0 = (wn + dy) * 16 + c;
                #pragma unroll
                for (int nt = 0; nt < 8; nt++) {
                    int xb = nt * 8 + g;
                    unsigned bf[2];
                    bf[0] = Xs[row0 * 72 + xb + dx];
                    bf[1] = Xs[(row0 + 4) * 72 + xb + dx];
                    mma8(acc[0][nt], a[0], bf);
                    mma8(acc[1][nt], a[1], bf);
                }
            }
        }
    }

    #pragma unroll
    for (int mt = 0; mt < 2; mt++) {
        int m  = m0 + wm * 32 + mt * 16 + g;
        int m1 = m + 8;
        float sc0 = gg[m]  * rsqrtf(rv[m]  + EPS_), sh0 = bb[m]  - rm[m]  * sc0;
        float sc1 = gg[m1] * rsqrtf(rv[m1] + EPS_), sh1 = bb[m1] - rm[m1] * sc1;
        #pragma unroll
        for (int nt = 0; nt < 8; nt++) {
            int n = wn * 64 + nt * 8 + 2 * t;
            float* c = acc[mt][nt];
            *(float2*)&Yout[((size_t)b * C_ + m)  * N_ + y0 * W_ + n] =
                make_float2(silu_f(c[0] * sc0 + sh0), silu_f(c[1] * sc0 + sh0));
            *(float2*)&Yout[((size_t)b * C_ + m1) * N_ + y0 * W_ + n] =
                make_float2(silu_f(c[2] * sc1 + sh1), silu_f(c[3] * sc1 + sh1));
        }
    }
}

// ============================================================================
// Area attention, FA2 style, occupancy-tuned.
// Block = 128 q rows; 8 warps x 16 q each. Q persistent in smem (frags
// reloaded per tile); S/P share registers; O + softmax state in registers.
// grid: (NA/128=8, NHEAD, 32), 2 CTAs/SM.
// ============================================================================
__global__ __launch_bounds__(256, 2)
void attn_tc3(const float* __restrict__ qk,
              const float* __restrict__ vv_g,
              float* __restrict__ att)
{
    extern __shared__ unsigned as_[];
    unsigned* Qst = as_;                       // [128][68]  (8704 w) persistent
    unsigned* Ks  = as_ + 128 * 68;            // [64][72]   (4608 w)
    unsigned* Vs  = as_ + 128 * 68 + 64 * 72;  // [64][68]   (4352 w)
    float*    Os  = (float*)as_;               // [64][132] epilogue alias

    const int q0   = blockIdx.x * 128;
    const int head = blockIdx.y;
    const int ba   = blockIdx.z;
    const int b    = ba >> 2;
    const int area = ba & 3;

    const float* Qb = qk   + ((size_t)b * 2 * C_ +      head * HD_) * N_ + area * NA_;
    const float* Kb = qk   + ((size_t)b * 2 * C_ + C_ + head * HD_) * N_ + area * NA_;
    const float* Vb = vv_g + ((size_t)b * C_     +      head * HD_) * N_ + area * NA_;
    float*       Ob = att  + ((size_t)b * C_     +      head * HD_) * N_ + area * NA_;

    const int tid = threadIdx.x, lane = tid & 31, warp = tid >> 5;
    const int g = lane >> 2, t = lane & 3;
    const int wq = warp * 16;

    // ---- stage Q [q][d] (transpose), once, persistent ----
    #pragma unroll
    for (int i = 0; i < 8; i++) {
        int e4 = i * 256 + tid;
        int d = e4 >> 5, qq = (e4 & 31) << 2;
        float4 q4 = *(const float4*)(Qb + (size_t)d * N_ + q0 + qq);
        Qst[(qq + 0) * 68 + d] = f2tf(q4.x);
        Qst[(qq + 1) * 68 + d] = f2tf(q4.y);
        Qst[(qq + 2) * 68 + d] = f2tf(q4.z);
        Qst[(qq + 3) * 68 + d] = f2tf(q4.w);
    }

    float mr0 = -1e30f, mr1 = -1e30f, lr0 = 0.0f, lr1 = 0.0f;
    float Oa[8][4] = {};
    const int sb = lane & ~3;
    const int s1l = sb + (t >> 1), s2l = s1l + 2;

    for (int j0 = 0; j0 < NA_; j0 += 64) {
        __syncthreads();   // Q staged (iter 0) / prior consumers of Ks,Vs done
        #pragma unroll
        for (int i = 0; i < 4; i++) {
            int e4 = i * 256 + tid;
            int d = e4 >> 4, kq = (e4 & 15) << 2;
            float4 k4 = *(const float4*)(Kb + (size_t)d * N_ + j0 + kq);
            *(uint4*)&Ks[d * 72 + kq] =
                make_uint4(f2tf(k4.x), f2tf(k4.y), f2tf(k4.z), f2tf(k4.w));
            float4 v4 = *(const float4*)(Vb + (size_t)d * N_ + j0 + kq);
            *(uint4*)&Vs[d * 68 + kq] =
                make_uint4(f2tf(v4.x), f2tf(v4.y), f2tf(v4.z), f2tf(v4.w));
        }
        __syncthreads();

        // ---- S = Q K^T (16 x 64 per warp); Q frags reloaded from smem ----
        float S[8][4] = {};
        #pragma unroll
        for (int kc = 0; kc < 8; kc++) {
            const int c = kc * 8 + t;
            unsigned a[4];
            a[0] = Qst[(wq + g)     * 68 + c];
            a[1] = Qst[(wq + 8 + g) * 68 + c];
            a[2] = Qst[(wq + g)     * 68 + c + 4];
            a[3] = Qst[(wq + 8 + g) * 68 + c + 4];
            #pragma unroll
            for (int nt = 0; nt < 8; nt++) {
                unsigned bf[2] = { Ks[c * 72 + nt * 8 + g], Ks[(c + 4) * 72 + nt * 8 + g] };
                mma8(S[nt], a, bf);
            }
        }

        // ---- online softmax in registers; P overwrites S in place ----
        float mx0 = -1e30f, mx1 = -1e30f;
        #pragma unroll
        for (int nt = 0; nt < 8; nt++) {
            S[nt][0] *= 0.125f; S[nt][1] *= 0.125f;
            S[nt][2] *= 0.125f; S[nt][3] *= 0.125f;
            mx0 = fmaxf(mx0, fmaxf(S[nt][0], S[nt][1]));
            mx1 = fmaxf(mx1, fmaxf(S[nt][2], S[nt][3]));
        }
        mx0 = fmaxf(mx0, __shfl_xor_sync(0xffffffffu, mx0, 1));
        mx0 = fmaxf(mx0, __shfl_xor_sync(0xffffffffu, mx0, 2));
        mx1 = fmaxf(mx1, __shfl_xor_sync(0xffffffffu, mx1, 1));
        mx1 = fmaxf(mx1, __shfl_xor_sync(0xffffffffu, mx1, 2));
        float mn0 = fmaxf(mr0, mx0), mn1 = fmaxf(mr1, mx1);
        float al0 = __expf(mr0 - mn0), al1 = __expf(mr1 - mn1);
        mr0 = mn0; mr1 = mn1;
        float s0 = 0.0f, s1 = 0.0f;
        #pragma unroll
        for (int nt = 0; nt < 8; nt++) {
            float p0 = __expf(S[nt][0] - mn0), p1 = __expf(S[nt][1] - mn0);
            float p2 = __expf(S[nt][2] - mn1), p3 = __expf(S[nt][3] - mn1);
            s0 += p0 + p1; s1 += p2 + p3;
            S[nt][0] = __uint_as_float(f2tf(p0));
            S[nt][1] = __uint_as_float(f2tf(p1));
            S[nt][2] = __uint_as_float(f2tf(p2));
            S[nt][3] = __uint_as_float(f2tf(p3));
        }
        s0 += __shfl_xor_sync(0xffffffffu, s0, 1);
        s0 += __shfl_xor_sync(0xffffffffu, s0, 2);
        s1 += __shfl_xor_sync(0xffffffffu, s1, 1);
        s1 += __shfl_xor_sync(0xffffffffu, s1, 2);
        lr0 = lr0 * al0 + s0; lr1 = lr1 * al1 + s1;

        #pragma unroll
        for (int dt = 0; dt < 8; dt++) {
            Oa[dt][0] *= al0; Oa[dt][1] *= al0;
            Oa[dt][2] *= al1; Oa[dt][3] *= al1;
        }

        // ---- O += P V ; P C-frag -> A-frag via lane shuffles ----
        #pragma unroll
        for (int kc = 0; kc < 8; kc++) {
            unsigned p0 = __float_as_uint(S[kc][0]);
            unsigned p1 = __float_as_uint(S[kc][1]);
            unsigned p2 = __float_as_uint(S[kc][2]);
            unsigned p3 = __float_as_uint(S[kc][3]);
            unsigned x0 = __shfl_sync(0xffffffffu, p0, s1l);
            unsigned x1 = __shfl_sync(0xffffffffu, p1, s1l);
            unsigned x2 = __shfl_sync(0xffffffffu, p2, s1l);
            unsigned x3 = __shfl_sync(0xffffffffu, p3, s1l);
            unsigned y0 = __shfl_sync(0xffffffffu, p0, s2l);
            unsigned y1 = __shfl_sync(0xffffffffu, p1, s2l);
            unsigned y2 = __shfl_sync(0xffffffffu, p2, s2l);
            unsigned y3 = __shfl_sync(0xffffffffu, p3, s2l);
            unsigned av[4];
            if (t & 1) { av[0] = x1; av[1] = x3; av[2] = y1; av[3] = y3; }
            else       { av[0] = x0; av[1] = x2; av[2] = y0; av[3] = y2; }
            #pragma unroll
            for (int dt = 0; dt < 8; dt++) {
                unsigned bf[2] = { Vs[(dt * 8 + g) * 68 + kc * 8 + t],
                                   Vs[(dt * 8 + g) * 68 + kc * 8 + t + 4] };
                mma8(Oa[dt], av, bf);
            }
        }
    }

    // ---- epilogue: normalize, stage [d][q] in smem, float4 stores ----
    __syncthreads();
    float li0 = 1.0f / lr0, li1 = 1.0f / lr1;
    #pragma unroll
    for (int dt = 0; dt < 8; dt++) {
        int d = dt * 8 + 2 * t;
        Os[d * 132 + wq + g]           = Oa[dt][0] * li0;
        Os[(d + 1) * 132 + wq + g]     = Oa[dt][1] * li0;
        Os[d * 132 + wq + 8 + g]       = Oa[dt][2] * li1;
        Os[(d + 1) * 132 + wq + 8 + g] = Oa[dt][3] * li1;
    }
    __syncthreads();
    #pragma unroll
    for (int i = 0; i < 8; i++) {
        int e4 = i * 256 + tid;
        int d = e4 >> 5, qq = (e4 & 31) << 2;
        float4 o4 = *(const float4*)&Os[d * 132 + qq];
        *(float4*)(Ob + (size_t)d * N_ + q0 + qq) = o4;
    }
}

// ============================================================================
// Final 1x1 conv over (att + pp), BN+SiLU -> d_out.  Double-buffered regs.
// ============================================================================
__global__ __launch_bounds__(256, 2)
void gemm_add_bn_silu_tc(const float* __restrict__ Wt,   // [512][512]
                         const float* __restrict__ Xa,
                         const float* __restrict__ Xp,
                         const float* __restrict__ gg,
                         const float* __restrict__ bb,
                         const float* __restrict__ rm,
                         const float* __restrict__ rv,
                         float* __restrict__ Y)
{
    __shared__ unsigned Ws[128 * 20];
    __shared__ unsigned Xs[16 * 136];

    const int n0 = blockIdx.x * 128;
    const int m0 = blockIdx.y * 128;
    const int b  = blockIdx.z;
    const float* X1 = Xa + (size_t)b * C_ * N_;
    const float* X2 = Xp + (size_t)b * C_ * N_;

    const int tid = threadIdx.x, lane = tid & 31, warp = tid >> 5;
    const int g = lane >> 2, t = lane & 3;
    const int wm = warp >> 1, wn = warp & 1;

    const int wm0 = tid >> 2,            wk0 = (tid & 3) << 2;
    const int wm1 = (256 + tid) >> 2,    wk1 = ((256 + tid) & 3) << 2;
    const int xk0 = tid >> 5,            xn0 = (tid & 31) << 2;
    const int xk1 = (256 + tid) >> 5,    xn1 = ((256 + tid) & 31) << 2;

    float acc[2][8][4] = {};
    float4 w4a, w4b, xa0, xa1, xp0, xp1;

    w4a = *(const float4*)(Wt + (size_t)(m0 + wm0) * C_ + wk0);
    w4b = *(const float4*)(Wt + (size_t)(m0 + wm1) * C_ + wk1);
    xa0 = *(const float4*)(X1 + (size_t)xk0 * N_ + n0 + xn0);
    xa1 = *(const float4*)(X1 + (size_t)xk1 * N_ + n0 + xn1);
    xp0 = *(const float4*)(X2 + (size_t)xk0 * N_ + n0 + xn0);
    xp1 = *(const float4*)(X2 + (size_t)xk1 * N_ + n0 + xn1);

    for (int k0 = 0; k0 < C_; k0 += 16) {
        {
            unsigned* p;
            p = &Ws[wm0 * 20 + wk0];
            p[0]=f2tf(w4a.x); p[1]=f2tf(w4a.y); p[2]=f2tf(w4a.z); p[3]=f2tf(w4a.w);
            p = &Ws[wm1 * 20 + wk1];
            p[0]=f2tf(w4b.x); p[1]=f2tf(w4b.y); p[2]=f2tf(w4b.z); p[3]=f2tf(w4b.w);
            p = &Xs[xk0 * 136 + xn0];
            p[0]=f2tf(xa0.x+xp0.x); p[1]=f2tf(xa0.y+xp0.y);
            p[2]=f2tf(xa0.z+xp0.z); p[3]=f2tf(xa0.w+xp0.w);
            p = &Xs[xk1 * 136 + xn1];
            p[0]=f2tf(xa1.x+xp1.x); p[1]=f2tf(xa1.y+xp1.y);
            p[2]=f2tf(xa1.z+xp1.z); p[3]=f2tf(xa1.w+xp1.w);
        }
        __syncthreads();
        if (k0 + 16 < C_) {
            int kn = k0 + 16;
            w4a = *(const float4*)(Wt + (size_t)(m0 + wm0) * C_ + kn + wk0);
            w4b = *(const float4*)(Wt + (size_t)(m0 + wm1) * C_ + kn + wk1);
            xa0 = *(const float4*)(X1 + (size_t)(kn + xk0) * N_ + n0 + xn0);
            xa1 = *(const float4*)(X1 + (size_t)(kn + xk1) * N_ + n0 + xn1);
            xp0 = *(const float4*)(X2 + (size_t)(kn + xk0) * N_ + n0 + xn0);
            xp1 = *(const float4*)(X2 + (size_t)(kn + xk1) * N_ + n0 + xn1);
        }
        #pragma unroll
        for (int ks = 0; ks < 2; ks++) {
            const int c = ks * 8 + t;
            unsigned a[2][4];
            #pragma unroll
            for (int mt = 0; mt < 2; mt++) {
                int r = wm * 32 + mt * 16 + g;
                a[mt][0] = Ws[r * 20 + c];       a[mt][1] = Ws[(r + 8) * 20 + c];
                a[mt][2] = Ws[r * 20 + c + 4];   a[mt][3] = Ws[(r + 8) * 20 + c + 4];
            }
            #pragma unroll
            for (int nt = 0; nt < 8; nt++) {
                int n = wn * 64 + nt * 8 + g;
                unsigned bf[2] = { Xs[c * 136 + n], Xs[(c + 4) * 136 + n] };
                mma8(acc[0][nt], a[0], bf);
                mma8(acc[1][nt], a[1], bf);
            }
        }
        __syncthreads();
    }

    #pragma unroll
    for (int mt = 0; mt < 2; mt++) {
        int m  = m0 + wm * 32 + mt * 16 + g;
        int m1 = m + 8;
        float sc0 = gg[m]  * rsqrtf(rv[m]  + EPS_), sh0 = bb[m]  - rm[m]  * sc0;
        float sc1 = gg[m1] * rsqrtf(rv[m1] + EPS_), sh1 = bb[m1] - rm[m1] * sc1;
        #pragma unroll
        for (int nt = 0; nt < 8; nt++) {
            int n = n0 + wn * 64 + nt * 8 + 2 * t;
            float* c = acc[mt][nt];
            *(float2*)&Y[((size_t)b * C_ + m)  * N_ + n] =
                make_float2(silu_f(c[0] * sc0 + sh0), silu_f(c[1] * sc0 + sh0));
            *(float2*)&Y[((size_t)b * C_ + m1) * N_ + n] =
                make_float2(silu_f(c[2] * sc1 + sh1), silu_f(c[3] * sc1 + sh1));
        }
    }
}

// ============================================================================
extern "C" void kernel_launch(void* const* d_in, const int* in_sizes, int n_in,
                              void* d_out, int out_size)
{
    const float* x     = (const float*)d_in[0];
    const float* qk_w  = (const float*)d_in[1];
    const float* qk_g  = (const float*)d_in[2];
    const float* qk_b  = (const float*)d_in[3];
    const float* qk_rm = (const float*)d_in[4];
    const float* qk_rv = (const float*)d_in[5];
    const float* v_w   = (const float*)d_in[6];
    const float* v_g   = (const float*)d_in[7];
    const float* v_b   = (const float*)d_in[8];
    const float* v_rm  = (const float*)d_in[9];
    const float* v_rv  = (const float*)d_in[10];
    const float* pe_w  = (const float*)d_in[11];
    const float* pe_g  = (const float*)d_in[12];
    const float* pe_b  = (const float*)d_in[13];
    const float* pe_rm = (const float*)d_in[14];
    const float* pe_rv = (const float*)d_in[15];
    const float* pr_w  = (const float*)d_in[16];
    const float* pr_g  = (const float*)d_in[17];
    const float* pr_b  = (const float*)d_in[18];
    const float* pr_rm = (const float*)d_in[19];
    const float* pr_rv = (const float*)d_in[20];
    float* out = (float*)d_out;

    float *p_qk, *p_v, *p_pp, *p_att;
    cudaGetSymbolAddress((void**)&p_qk,  g_qk);
    cudaGetSymbolAddress((void**)&p_v,   g_v);
    cudaGetSymbolAddress((void**)&p_pp,  g_pp);
    cudaGetSymbolAddress((void**)&p_att, g_att);

    const int conv_smem = (9 * 1280 + 6 * 16 * 72) * 4;                 // 73728
    const int attn_smem = (128 * 68 + 64 * 72 + 64 * 68) * 4;           // 70656
    cudaFuncSetAttribute(conv3_bn_silu_tc,
                         cudaFuncAttributeMaxDynamicSharedMemorySize, conv_smem);
    cudaFuncSetAttribute(attn_tc3,
                         cudaFuncAttributeMaxDynamicSharedMemorySize, attn_smem);

    dim3 thr(256);

    // 1) qk = bn_silu(conv1x1(x, qk_w))   M=1024
    gemm_bn_silu_tc<<<dim3(N_ / 128, 1024 / 128, B_), thr>>>(
        qk_w, x, qk_g, qk_b, qk_rm, qk_rv, p_qk, 1024);

    // 2) vmap = bn_silu(conv1x1(x, v_w))  M=512
    gemm_bn_silu_tc<<<dim3(N_ / 128, C_ / 128, B_), thr>>>(
        v_w, x, v_g, v_b, v_rm, v_rv, p_v, C_);

    // 3) pp = bn_silu(conv3x3(vmap, pe_w))
    conv3_bn_silu_tc<<<dim3(H_ / 4, C_ / 64, B_), thr, conv_smem>>>(
        pe_w, p_v, pe_g, pe_b, pe_rm, pe_rv, p_pp);

    // 4) area attention
    attn_tc3<<<dim3(NA_ / 128, NHEAD, B_ * AREA_), thr, attn_smem>>>(
        p_qk, p_v, p_att);

    // 5) y = bn_silu(conv1x1(att + pp, pr_w))
    gemm_add_bn_silu_tc<<<dim3(N_ / 128, C_ / 128, B_), thr>>>(
        pr_w, p_att, p_pp, pr_g, pr_b, pr_rm, pr_rv, out);
}

// round 6
// speedup vs baseline: 5.3853x; 1.0291x over previous
#include <cuda_runtime.h>
#include <math.h>

#define B_    8
#define C_    512
#define H_    64
#define W_    64
#define N_    4096          // H*W
#define AREA_ 4
#define NHEAD 8
#define HD_   64
#define NA_   1024          // N/AREA
#define EPS_  1e-5f

// ---------------- scratch (device globals; no allocation allowed) ----------
__device__ unsigned g_qk [B_ * 2 * C_ * N_];   // qk act, tf32 bits
__device__ unsigned g_v  [B_ * C_ * N_];       // v act, tf32 bits
__device__ float    g_pp [B_ * C_ * N_];       // position branch (fp32)
__device__ float    g_att[B_ * C_ * N_];       // attention out (fp32)
__device__ unsigned g_x  [B_ * C_ * N_];       // pre-rounded input
__device__ unsigned g_wqk[2 * C_ * C_];        // pre-rounded weights
__device__ unsigned g_wv [C_ * C_];
__device__ unsigned g_wpr[C_ * C_];
__device__ uint2    g_wpe[9 * 32 * 8 * 512];   // conv weights, pair layout

__device__ __forceinline__ float silu_f(float y) {
    return y / (1.0f + __expf(-y));
}
__device__ __forceinline__ unsigned f2tf(float x) {
    unsigned u; asm("cvt.rna.tf32.f32 %0, %1;" : "=r"(u) : "f"(x)); return u;
}
__device__ __forceinline__ void mma8(float* c, const unsigned* a, const unsigned* b) {
    asm volatile(
      "mma.sync.aligned.m16n8k8.row.col.f32.tf32.tf32.f32 "
      "{%0,%1,%2,%3},{%4,%5,%6,%7},{%8,%9},{%0,%1,%2,%3};"
      : "+f"(c[0]), "+f"(c[1]), "+f"(c[2]), "+f"(c[3])
      : "r"(a[0]), "r"(a[1]), "r"(a[2]), "r"(a[3]), "r"(b[0]), "r"(b[1]));
}

// ============================================================================
// Pre-round fp32 -> tf32 bits (vectorized)
// ============================================================================
__global__ void preround(const float4* __restrict__ in, uint4* __restrict__ out, int n4)
{
    int i = blockIdx.x * blockDim.x + threadIdx.x;
    if (i < n4) {
        float4 v = in[i];
        out[i] = make_uint4(f2tf(v.x), f2tf(v.y), f2tf(v.z), f2tf(v.w));
    }
}

// ============================================================================
// Transform conv weights [O][I][3][3] -> pair layout [tap][chunk][pair][o]
// pair p holds {W[o][c], W[o][c+4]} with c = chunk*16 + (p>>2)*8 + (p&3)
// ============================================================================
__global__ void conv_w_xform(const float* __restrict__ pe_w, uint2* __restrict__ Wp)
{
    int idx = blockIdx.x * 256 + threadIdx.x;
    if (idx >= 9 * 32 * 8 * 512) return;
    int o     = idx & 511;
    int p     = (idx >> 9) & 7;
    int chunk = (idx >> 12) & 31;
    int tap   = idx >> 17;
    int c = chunk * 16 + ((p >> 2) << 3) + (p & 3);
    float a  = pe_w[((size_t)o * C_ + c) * 9 + tap];
    float bq = pe_w[((size_t)o * C_ + c + 4) * 9 + tap];
    Wp[idx] = make_uint2(f2tf(a), f2tf(bq));
}

// ============================================================================
// 1x1 conv GEMM + BN + SiLU, pre-rounded tf32 in/out.  128m x 128n tiles.
// ============================================================================
__global__ __launch_bounds__(256, 2)
void gemm_bn_silu_tc(const unsigned* __restrict__ Wt,   // [M][512] tf32 bits
                     const unsigned* __restrict__ X,    // [B][512][N] tf32 bits
                     const float* __restrict__ gg,
                     const float* __restrict__ bb,
                     const float* __restrict__ rm,
                     const float* __restrict__ rv,
                     unsigned* __restrict__ Y, int M)   // tf32 bits out
{
    __shared__ unsigned Ws[128 * 20];   // [m][k]
    __shared__ unsigned Xs[16 * 136];   // [k][n]

    const int n0 = blockIdx.x * 128;
    const int m0 = blockIdx.y * 128;
    const int b  = blockIdx.z;
    const unsigned* Xb = X + (size_t)b * C_ * N_;

    const int tid = threadIdx.x, lane = tid & 31, warp = tid >> 5;
    const int g = lane >> 2, t = lane & 3;
    const int wm = warp >> 1, wn = warp & 1;

    const int wm0 = tid >> 2,            wk0 = (tid & 3) << 2;
    const int wm1 = (256 + tid) >> 2,    wk1 = ((256 + tid) & 3) << 2;
    const int xk0 = tid >> 5,            xn0 = (tid & 31) << 2;
    const int xk1 = (256 + tid) >> 5,    xn1 = ((256 + tid) & 31) << 2;

    float acc[2][8][4] = {};
    uint4 w4a, w4b, x4a, x4b;

    w4a = *(const uint4*)(Wt + (size_t)(m0 + wm0) * C_ + wk0);
    w4b = *(const uint4*)(Wt + (size_t)(m0 + wm1) * C_ + wk1);
    x4a = *(const uint4*)(Xb + (size_t)xk0 * N_ + n0 + xn0);
    x4b = *(const uint4*)(Xb + (size_t)xk1 * N_ + n0 + xn1);

    for (int k0 = 0; k0 < C_; k0 += 16) {
        *(uint4*)&Ws[wm0 * 20 + wk0] = w4a;
        *(uint4*)&Ws[wm1 * 20 + wk1] = w4b;
        *(uint4*)&Xs[xk0 * 136 + xn0] = x4a;
        *(uint4*)&Xs[xk1 * 136 + xn1] = x4b;
        __syncthreads();
        if (k0 + 16 < C_) {
            int kn = k0 + 16;
            w4a = *(const uint4*)(Wt + (size_t)(m0 + wm0) * C_ + kn + wk0);
            w4b = *(const uint4*)(Wt + (size_t)(m0 + wm1) * C_ + kn + wk1);
            x4a = *(const uint4*)(Xb + (size_t)(kn + xk0) * N_ + n0 + xn0);
            x4b = *(const uint4*)(Xb + (size_t)(kn + xk1) * N_ + n0 + xn1);
        }
        #pragma unroll
        for (int ks = 0; ks < 2; ks++) {
            const int c = ks * 8 + t;
            unsigned a[2][4];
            #pragma unroll
            for (int mt = 0; mt < 2; mt++) {
                int r = wm * 32 + mt * 16 + g;
                a[mt][0] = Ws[r * 20 + c];       a[mt][1] = Ws[(r + 8) * 20 + c];
                a[mt][2] = Ws[r * 20 + c + 4];   a[mt][3] = Ws[(r + 8) * 20 + c + 4];
            }
            #pragma unroll
            for (int nt = 0; nt < 8; nt++) {
                int n = wn * 64 + nt * 8 + g;
                unsigned bf[2] = { Xs[c * 136 + n], Xs[(c + 4) * 136 + n] };
                mma8(acc[0][nt], a[0], bf);
                mma8(acc[1][nt], a[1], bf);
            }
        }
        __syncthreads();
    }

    #pragma unroll
    for (int mt = 0; mt < 2; mt++) {
        int m  = m0 + wm * 32 + mt * 16 + g;
        int m1 = m + 8;
        float sc0 = gg[m]  * rsqrtf(rv[m]  + EPS_), sh0 = bb[m]  - rm[m]  * sc0;
        float sc1 = gg[m1] * rsqrtf(rv[m1] + EPS_), sh1 = bb[m1] - rm[m1] * sc1;
        #pragma unroll
        for (int nt = 0; nt < 8; nt++) {
            int n = n0 + wn * 64 + nt * 8 + 2 * t;
            float* c = acc[mt][nt];
            *(uint2*)&Y[((size_t)b * M + m)  * N_ + n] =
                make_uint2(f2tf(silu_f(c[0] * sc0 + sh0)), f2tf(silu_f(c[1] * sc0 + sh0)));
            *(uint2*)&Y[((size_t)b * M + m1) * N_ + n] =
                make_uint2(f2tf(silu_f(c[2] * sc1 + sh1)), f2tf(silu_f(c[3] * sc1 + sh1)));
        }
    }
}

// ============================================================================
// 3x3 SAME conv + BN + SiLU, pair layouts, pre-rounded operands.
// block: 64 o x 256 px (4 rows), 8 warps (2m x 4n).  grid (16, 8, B)
// smem: Ws2 [9 taps][8 pairs][68] uint2 + Xp [6 rows][8 pairs][68] uint2
// ============================================================================
__global__ __launch_bounds__(256, 2)
void conv3_bn_silu_tc(const uint2* __restrict__ Wp,      // transformed weights
                      const unsigned* __restrict__ Xin,  // g_v (tf32 bits)
                      const float* __restrict__ gg,
                      const float* __restrict__ bb,
                      const float* __restrict__ rm,
                      const float* __restrict__ rv,
                      float* __restrict__ Yout)          // g_pp (fp32)
{
    extern __shared__ unsigned cs[];
    uint2* Ws2 = (uint2*)cs;                 // 9*8*68 = 4896 uint2
    uint2* Xp  = (uint2*)cs + 9 * 8 * 68;    // 6*8*68 = 3264 uint2

    const int y0 = blockIdx.x * 4;
    const int m0 = blockIdx.y * 64;
    const int b  = blockIdx.z;
    const unsigned* Xb = Xin + (size_t)b * C_ * N_;

    const int tid = threadIdx.x, lane = tid & 31, warp = tid >> 5;
    const int g = lane >> 2, t = lane & 3;
    const int wm = warp >> 2, wn = warp & 3;   // 2m x 4n

    const int wsp = tid >> 5, wso = (tid & 31) * 2;   // weight staging coords

    float acc[2][8][4] = {};

    for (int ci = 0; ci < 32; ci++) {
        __syncthreads();
        // X: 6 rows x 8 channel-pairs x 66 (x = -1..64), zero pad
        for (int e = tid; e < 6 * 8 * 66; e += 256) {
            int r = e / 528; int rem = e - r * 528;
            int p = rem / 66; int xx = rem - p * 66;
            int c = ci * 16 + ((p >> 2) << 3) + (p & 3);
            int gy = y0 - 1 + r, gx = xx - 1;
            uint2 v = make_uint2(0u, 0u);
            if (gy >= 0 && gy < H_ && gx >= 0 && gx < W_) {
                const unsigned* s = Xb + (size_t)c * N_ + gy * W_ + gx;
                v.x = s[0]; v.y = s[4 * N_];
            }
            Xp[(r * 8 + p) * 68 + xx] = v;
        }
        // W: 9 taps x 8 pairs x 64 o, coalesced uint4 copies
        #pragma unroll
        for (int tap = 0; tap < 9; tap++) {
            uint4 w = *(const uint4*)&Wp[(((size_t)tap * 32 + ci) * 8 + wsp) * 512 + m0 + wso];
            *(uint4*)&Ws2[(tap * 8 + wsp) * 68 + wso] = w;
        }
        __syncthreads();

        for (int tap = 0; tap < 9; tap++) {
            const int dy = tap / 3, dx = tap - dy * 3;
            #pragma unroll
            for (int ks = 0; ks < 2; ks++) {
                const int p = ks * 4 + t;
                const uint2* wr = &Ws2[(tap * 8 + p) * 68];
                uint2 wa0 = wr[wm * 32 + g],      wa1 = wr[wm * 32 + 8 + g];
                uint2 wb0 = wr[wm * 32 + 16 + g], wb1 = wr[wm * 32 + 24 + g];
                unsigned a0[4] = { wa0.x, wa1.x, wa0.y, wa1.y };
                unsigned a1[4] = { wb0.x, wb1.x, wb0.y, wb1.y };
                const uint2* xr = &Xp[((wn + dy) * 8 + p) * 68 + dx];
                #pragma unroll
                for (int nt = 0; nt < 8; nt++) {
                    uint2 xb = xr[nt * 8 + g];
                    unsigned bf[2] = { xb.x, xb.y };
                    mma8(acc[0][nt], a0, bf);
                    mma8(acc[1][nt], a1, bf);
                }
            }
        }
    }

    #pragma unroll
    for (int mt = 0; mt < 2; mt++) {
        int m  = m0 + wm * 32 + mt * 16 + g;
        int m1 = m + 8;
        float sc0 = gg[m]  * rsqrtf(rv[m]  + EPS_), sh0 = bb[m]  - rm[m]  * sc0;
        float sc1 = gg[m1] * rsqrtf(rv[m1] + EPS_), sh1 = bb[m1] - rm[m1] * sc1;
        #pragma unroll
        for (int nt = 0; nt < 8; nt++) {
            int n = wn * 64 + nt * 8 + 2 * t;
            float* c = acc[mt][nt];
            *(float2*)&Yout[((size_t)b * C_ + m)  * N_ + y0 * W_ + n] =
                make_float2(silu_f(c[0] * sc0 + sh0), silu_f(c[1] * sc0 + sh0));
            *(float2*)&Yout[((size_t)b * C_ + m1) * N_ + y0 * W_ + n] =
                make_float2(silu_f(c[2] * sc1 + sh1), silu_f(c[3] * sc1 + sh1));
        }
    }
}

// ============================================================================
// Area attention, FA2 style with uint2 pair layouts (LDS.64 fragments).
// Block = 128 q rows; 8 warps x 16 q.  grid (8, NHEAD, 32), 2 CTAs/SM.
// ============================================================================
__global__ __launch_bounds__(256, 2)
void attn_tc4(const unsigned* __restrict__ qk,
              const unsigned* __restrict__ vv,
              float* __restrict__ att)
{
    extern __shared__ unsigned as_[];
    uint2* Qp = (uint2*)as_;                          // [q][36]  (9216 u)
    uint2* Kp = (uint2*)(as_ + 128 * 72);             // [32][68] (4352 u)
    uint2* Vp = (uint2*)(as_ + 128 * 72 + 32 * 136);  // [64][36] (4608 u)
    float* Os = (float*)as_;                          // [64][132] epilogue alias

    const int q0   = blockIdx.x * 128;
    const int head = blockIdx.y;
    const int ba   = blockIdx.z;
    const int b    = ba >> 2;
    const int area = ba & 3;

    const unsigned* Qb = qk + ((size_t)b * 2 * C_ +      head * HD_) * N_ + area * NA_;
    const unsigned* Kb = qk + ((size_t)b * 2 * C_ + C_ + head * HD_) * N_ + area * NA_;
    const unsigned* Vb = vv + ((size_t)b * C_     +      head * HD_) * N_ + area * NA_;
    float*          Ob = att + ((size_t)b * C_    +      head * HD_) * N_ + area * NA_;

    const int tid = threadIdx.x, lane = tid & 31, warp = tid >> 5;
    const int g = lane >> 2, t = lane & 3;
    const int wq = warp * 16;

    // ---- stage Q as (c, c+4) pairs, once ----
    #pragma unroll
    for (int i = 0; i < 4; i++) {
        int G = tid + i * 256;
        int dp = G >> 5, ql = (G & 31) << 2;
        int kc = dp >> 2, tt = dp & 3;
        int dlo = kc * 8 + tt;
        uint4 A  = *(const uint4*)(Qb + (size_t)dlo * N_ + q0 + ql);
        uint4 Bq = *(const uint4*)(Qb + (size_t)(dlo + 4) * N_ + q0 + ql);
        Qp[(ql + 0) * 36 + kc * 4 + tt] = make_uint2(A.x, Bq.x);
        Qp[(ql + 1) * 36 + kc * 4 + tt] = make_uint2(A.y, Bq.y);
        Qp[(ql + 2) * 36 + kc * 4 + tt] = make_uint2(A.z, Bq.z);
        Qp[(ql + 3) * 36 + kc * 4 + tt] = make_uint2(A.w, Bq.w);
    }

    float mr0 = -1e30f, mr1 = -1e30f, lr0 = 0.0f, lr1 = 0.0f;
    float Oa[8][4] = {};
    const int sb = lane & ~3;
    const int s1l = sb + (t >> 1), s2l = s1l + 2;

    for (int j0 = 0; j0 < NA_; j0 += 64) {
        __syncthreads();
        // K: pairs over (d, d+4); rows (kc,t), cols key
        #pragma unroll
        for (int i = 0; i < 2; i++) {
            int G = tid + i * 256;
            int r = G >> 4, ng = (G & 15) << 2;
            int kc = r >> 2, tt = r & 3;
            int dlo = kc * 8 + tt;
            uint4 A  = *(const uint4*)(Kb + (size_t)dlo * N_ + j0 + ng);
            uint4 Bk = *(const uint4*)(Kb + (size_t)(dlo + 4) * N_ + j0 + ng);
            uint2* dst = &Kp[r * 68 + ng];
            *(uint4*)&dst[0] = make_uint4(A.x, Bk.x, A.y, Bk.y);
            *(uint4*)&dst[2] = make_uint4(A.z, Bk.z, A.w, Bk.w);
        }
        // V: pairs over (j, j+4) within row d
        #pragma unroll
        for (int i = 0; i < 2; i++) {
            int G = tid + i * 256;
            int d = G >> 3, kcg = G & 7;
            const unsigned* src = Vb + (size_t)d * N_ + j0 + kcg * 8;
            uint4 A  = *(const uint4*)(src);
            uint4 Bv = *(const uint4*)(src + 4);
            uint2* dst = &Vp[d * 36 + kcg * 4];
            *(uint4*)&dst[0] = make_uint4(A.x, Bv.x, A.y, Bv.y);
            *(uint4*)&dst[2] = make_uint4(A.z, Bv.z, A.w, Bv.w);
        }
        __syncthreads();

        // ---- S = Q K^T ----
        float S[8][4] = {};
        #pragma unroll
        for (int kc = 0; kc < 8; kc++) {
            uint2 qa = Qp[(wq + g) * 36 + kc * 4 + t];
            uint2 qb = Qp[(wq + 8 + g) * 36 + kc * 4 + t];
            unsigned a[4] = { qa.x, qb.x, qa.y, qb.y };
            const uint2* kr = &Kp[(kc * 4 + t) * 68 + g];
            #pragma unroll
            for (int nt = 0; nt < 8; nt++) {
                uint2 kb = kr[nt * 8];
                unsigned bf[2] = { kb.x, kb.y };
                mma8(S[nt], a, bf);
            }
        }

        // ---- online softmax in registers; P overwrites S ----
        float mx0 = -1e30f, mx1 = -1e30f;
        #pragma unroll
        for (int nt = 0; nt < 8; nt++) {
            S[nt][0] *= 0.125f; S[nt][1] *= 0.125f;
            S[nt][2] *= 0.125f; S[nt][3] *= 0.125f;
            mx0 = fmaxf(mx0, fmaxf(S[nt][0], S[nt][1]));
            mx1 = fmaxf(mx1, fmaxf(S[nt][2], S[nt][3]));
        }
        mx0 = fmaxf(mx0, __shfl_xor_sync(0xffffffffu, mx0, 1));
        mx0 = fmaxf(mx0, __shfl_xor_sync(0xffffffffu, mx0, 2));
        mx1 = fmaxf(mx1, __shfl_xor_sync(0xffffffffu, mx1, 1));
        mx1 = fmaxf(mx1, __shfl_xor_sync(0xffffffffu, mx1, 2));
        float mn0 = fmaxf(mr0, mx0), mn1 = fmaxf(mr1, mx1);
        float al0 = __expf(mr0 - mn0), al1 = __expf(mr1 - mn1);
        mr0 = mn0; mr1 = mn1;
        float s0 = 0.0f, s1 = 0.0f;
        #pragma unroll
        for (int nt = 0; nt < 8; nt++) {
            float p0 = __expf(S[nt][0] - mn0), p1 = __expf(S[nt][1] - mn0);
            float p2 = __expf(S[nt][2] - mn1), p3 = __expf(S[nt][3] - mn1);
            s0 += p0 + p1; s1 += p2 + p3;
            S[nt][0] = __uint_as_float(f2tf(p0));
            S[nt][1] = __uint_as_float(f2tf(p1));
            S[nt][2] = __uint_as_float(f2tf(p2));
            S[nt][3] = __uint_as_float(f2tf(p3));
        }
        s0 += __shfl_xor_sync(0xffffffffu, s0, 1);
        s0 += __shfl_xor_sync(0xffffffffu, s0, 2);
        s1 += __shfl_xor_sync(0xffffffffu, s1, 1);
        s1 += __shfl_xor_sync(0xffffffffu, s1, 2);
        lr0 = lr0 * al0 + s0; lr1 = lr1 * al1 + s1;

        #pragma unroll
        for (int dt = 0; dt < 8; dt++) {
            Oa[dt][0] *= al0; Oa[dt][1] *= al0;
            Oa[dt][2] *= al1; Oa[dt][3] *= al1;
        }

        // ---- O += P V ----
        #pragma unroll
        for (int kc = 0; kc < 8; kc++) {
            unsigned p0 = __float_as_uint(S[kc][0]);
            unsigned p1 = __float_as_uint(S[kc][1]);
            unsigned p2 = __float_as_uint(S[kc][2]);
            unsigned p3 = __float_as_uint(S[kc][3]);
            unsigned x0 = __shfl_sync(0xffffffffu, p0, s1l);
            unsigned x1 = __shfl_sync(0xffffffffu, p1, s1l);
            unsigned x2 = __shfl_sync(0xffffffffu, p2, s1l);
            unsigned x3 = __shfl_sync(0xffffffffu, p3, s1l);
            unsigned y0 = __shfl_sync(0xffffffffu, p0, s2l);
            unsigned y1 = __shfl_sync(0xffffffffu, p1, s2l);
            unsigned y2 = __shfl_sync(0xffffffffu, p2, s2l);
            unsigned y3 = __shfl_sync(0xffffffffu, p3, s2l);
            unsigned av[4];
            if (t & 1) { av[0] = x1; av[1] = x3; av[2] = y1; av[3] = y3; }
            else       { av[0] = x0; av[1] = x2; av[2] = y0; av[3] = y2; }
            const uint2* vr = &Vp[g * 36 + kc * 4 + t];
            #pragma unroll
            for (int dt = 0; dt < 8; dt++) {
                uint2 vb = vr[dt * 288];
                unsigned bf[2] = { vb.x, vb.y };
                mma8(Oa[dt], av, bf);
            }
        }
    }

    // ---- epilogue ----
    __syncthreads();
    float li0 = 1.0f / lr0, li1 = 1.0f / lr1;
    #pragma unroll
    for (int dt = 0; dt < 8; dt++) {
        int d = dt * 8 + 2 * t;
        Os[d * 132 + wq + g]           = Oa[dt][0] * li0;
        Os[(d + 1) * 132 + wq + g]     = Oa[dt][1] * li0;
        Os[d * 132 + wq + 8 + g]       = Oa[dt][2] * li1;
        Os[(d + 1) * 132 + wq + 8 + g] = Oa[dt][3] * li1;
    }
    __syncthreads();
    #pragma unroll
    for (int i = 0; i < 8; i++) {
        int e4 = i * 256 + tid;
        int d = e4 >> 5, qq = (e4 & 31) << 2;
        float4 o4 = *(const float4*)&Os[d * 132 + qq];
        *(float4*)(Ob + (size_t)d * N_ + q0 + qq) = o4;
    }
}

// ============================================================================
// Final 1x1 conv over (att + pp), BN+SiLU -> d_out (fp32 out, W pre-rounded)
// ============================================================================
__global__ __launch_bounds__(256, 2)
void gemm_add_bn_silu_tc(const unsigned* __restrict__ Wt,
                         const float* __restrict__ Xa,
                         const float* __restrict__ Xp,
                         const float* __restrict__ gg,
                         const float* __restrict__ bb,
                         const float* __restrict__ rm,
                         const float* __restrict__ rv,
                         float* __restrict__ Y)
{
    __shared__ unsigned Ws[128 * 20];
    __shared__ unsigned Xs[16 * 136];

    const int n0 = blockIdx.x * 128;
    const int m0 = blockIdx.y * 128;
    const int b  = blockIdx.z;
    const float* X1 = Xa + (size_t)b * C_ * N_;
    const float* X2 = Xp + (size_t)b * C_ * N_;

    const int tid = threadIdx.x, lane = tid & 31, warp = tid >> 5;
    const int g = lane >> 2, t = lane & 3;
    const int wm = warp >> 1, wn = warp & 1;

    const int wm0 = tid >> 2,            wk0 = (tid & 3) << 2;
    const int wm1 = (256 + tid) >> 2,    wk1 = ((256 + tid) & 3) << 2;
    const int xk0 = tid >> 5,            xn0 = (tid & 31) << 2;
    const int xk1 = (256 + tid) >> 5,    xn1 = ((256 + tid) & 31) << 2;

    float acc[2][8][4] = {};
    uint4 w4a, w4b;
    float4 xa0, xa1, xp0, xp1;

    w4a = *(const uint4*)(Wt + (size_t)(m0 + wm0) * C_ + wk0);
    w4b = *(const uint4*)(Wt + (size_t)(m0 + wm1) * C_ + wk1);
    xa0 = *(const float4*)(X1 + (size_t)xk0 * N_ + n0 + xn0);
    xa1 = *(const float4*)(X1 + (size_t)xk1 * N_ + n0 + xn1);
    xp0 = *(const float4*)(X2 + (size_t)xk0 * N_ + n0 + xn0);
    xp1 = *(const float4*)(X2 + (size_t)xk1 * N_ + n0 + xn1);

    for (int k0 = 0; k0 < C_; k0 += 16) {
        *(uint4*)&Ws[wm0 * 20 + wk0] = w4a;
        *(uint4*)&Ws[wm1 * 20 + wk1] = w4b;
        {
            unsigned* p;
            p = &Xs[xk0 * 136 + xn0];
            p[0]=f2tf(xa0.x+xp0.x); p[1]=f2tf(xa0.y+xp0.y);
            p[2]=f2tf(xa0.z+xp0.z); p[3]=f2tf(xa0.w+xp0.w);
            p = &Xs[xk1 * 136 + xn1];
            p[0]=f2tf(xa1.x+xp1.x); p[1]=f2tf(xa1.y+xp1.y);
            p[2]=f2tf(xa1.z+xp1.z); p[3]=f2tf(xa1.w+xp1.w);
        }
        __syncthreads();
        if (k0 + 16 < C_) {
            int kn = k0 + 16;
            w4a = *(const uint4*)(Wt + (size_t)(m0 + wm0) * C_ + kn + wk0);
            w4b = *(const uint4*)(Wt + (size_t)(m0 + wm1) * C_ + kn + wk1);
            xa0 = *(const float4*)(X1 + (size_t)(kn + xk0) * N_ + n0 + xn0);
            xa1 = *(const float4*)(X1 + (size_t)(kn + xk1) * N_ + n0 + xn1);
            xp0 = *(const float4*)(X2 + (size_t)(kn + xk0) * N_ + n0 + xn0);
            xp1 = *(const float4*)(X2 + (size_t)(kn + xk1) * N_ + n0 + xn1);
        }
        #pragma unroll
        for (int ks = 0; ks < 2; ks++) {
            const int c = ks * 8 + t;
            unsigned a[2][4];
            #pragma unroll
            for (int mt = 0; mt < 2; mt++) {
                int r = wm * 32 + mt * 16 + g;
                a[mt][0] = Ws[r * 20 + c];       a[mt][1] = Ws[(r + 8) * 20 + c];
                a[mt][2] = Ws[r * 20 + c + 4];   a[mt][3] = Ws[(r + 8) * 20 + c + 4];
            }
            #pragma unroll
            for (int nt = 0; nt < 8; nt++) {
                int n = wn * 64 + nt * 8 + g;
                unsigned bf[2] = { Xs[c * 136 + n], Xs[(c + 4) * 136 + n] };
                mma8(acc[0][nt], a[0], bf);
                mma8(acc[1][nt], a[1], bf);
            }
        }
        __syncthreads();
    }

    #pragma unroll
    for (int mt = 0; mt < 2; mt++) {
        int m  = m0 + wm * 32 + mt * 16 + g;
        int m1 = m + 8;
        float sc0 = gg[m]  * rsqrtf(rv[m]  + EPS_), sh0 = bb[m]  - rm[m]  * sc0;
        float sc1 = gg[m1] * rsqrtf(rv[m1] + EPS_), sh1 = bb[m1] - rm[m1] * sc1;
        #pragma unroll
        for (int nt = 0; nt < 8; nt++) {
            int n = n0 + wn * 64 + nt * 8 + 2 * t;
            float* c = acc[mt][nt];
            *(float2*)&Y[((size_t)b * C_ + m)  * N_ + n] =
                make_float2(silu_f(c[0] * sc0 + sh0), silu_f(c[1] * sc0 + sh0));
            *(float2*)&Y[((size_t)b * C_ + m1) * N_ + n] =
                make_float2(silu_f(c[2] * sc1 + sh1), silu_f(c[3] * sc1 + sh1));
        }
    }
}

// ============================================================================
extern "C" void kernel_launch(void* const* d_in, const int* in_sizes, int n_in,
                              void* d_out, int out_size)
{
    const float* x     = (const float*)d_in[0];
    const float* qk_w  = (const float*)d_in[1];
    const float* qk_g  = (const float*)d_in[2];
    const float* qk_b  = (const float*)d_in[3];
    const float* qk_rm = (const float*)d_in[4];
    const float* qk_rv = (const float*)d_in[5];
    const float* v_w   = (const float*)d_in[6];
    const float* v_g   = (const float*)d_in[7];
    const float* v_b   = (const float*)d_in[8];
    const float* v_rm  = (const float*)d_in[9];
    const float* v_rv  = (const float*)d_in[10];
    const float* pe_w  = (const float*)d_in[11];
    const float* pe_g  = (const float*)d_in[12];
    const float* pe_b  = (const float*)d_in[13];
    const float* pe_rm = (const float*)d_in[14];
    const float* pe_rv = (const float*)d_in[15];
    const float* pr_w  = (const float*)d_in[16];
    const float* pr_g  = (const float*)d_in[17];
    const float* pr_b  = (const float*)d_in[18];
    const float* pr_rm = (const float*)d_in[19];
    const float* pr_rv = (const float*)d_in[20];
    float* out = (float*)d_out;

    unsigned *p_qk, *p_v, *p_x, *p_wqk, *p_wv, *p_wpr;
    float *p_pp, *p_att;
    uint2 *p_wpe;
    cudaGetSymbolAddress((void**)&p_qk,  g_qk);
    cudaGetSymbolAddress((void**)&p_v,   g_v);
    cudaGetSymbolAddress((void**)&p_pp,  g_pp);
    cudaGetSymbolAddress((void**)&p_att, g_att);
    cudaGetSymbolAddress((void**)&p_x,   g_x);
    cudaGetSymbolAddress((void**)&p_wqk, g_wqk);
    cudaGetSymbolAddress((void**)&p_wv,  g_wv);
    cudaGetSymbolAddress((void**)&p_wpr, g_wpr);
    cudaGetSymbolAddress((void**)&p_wpe, g_wpe);

    const int conv_smem = (9 * 8 * 68 + 6 * 8 * 68) * 8;               // 65280
    const int attn_smem = (128 * 72 + 32 * 136 + 64 * 72) * 4;         // 72704
    cudaFuncSetAttribute(conv3_bn_silu_tc,
                         cudaFuncAttributeMaxDynamicSharedMemorySize, conv_smem);
    cudaFuncSetAttribute(attn_tc4,
                         cudaFuncAttributeMaxDynamicSharedMemorySize, attn_smem);

    dim3 thr(256);

    // 0) pre-round inputs/weights to tf32 bit patterns
    preround<<<(B_ * C_ * N_ / 4 + 255) / 256, thr>>>(
        (const float4*)x, (uint4*)p_x, B_ * C_ * N_ / 4);
    preround<<<(2 * C_ * C_ / 4 + 255) / 256, thr>>>(
        (const float4*)qk_w, (uint4*)p_wqk, 2 * C_ * C_ / 4);
    preround<<<(C_ * C_ / 4 + 255) / 256, thr>>>(
        (const float4*)v_w, (uint4*)p_wv, C_ * C_ / 4);
    preround<<<(C_ * C_ / 4 + 255) / 256, thr>>>(
        (const float4*)pr_w, (uint4*)p_wpr, C_ * C_ / 4);
    conv_w_xform<<<(9 * 32 * 8 * 512 + 255) / 256, thr>>>(pe_w, p_wpe);

    // 1) qk = bn_silu(conv1x1(x, qk_w))   M=1024
    gemm_bn_silu_tc<<<dim3(N_ / 128, 1024 / 128, B_), thr>>>(
        p_wqk, p_x, qk_g, qk_b, qk_rm, qk_rv, p_qk, 1024);

    // 2) vmap = bn_silu(conv1x1(x, v_w))  M=512
    gemm_bn_silu_tc<<<dim3(N_ / 128, C_ / 128, B_), thr>>>(
        p_wv, p_x, v_g, v_b, v_rm, v_rv, p_v, C_);

    // 3) pp = bn_silu(conv3x3(vmap, pe_w))
    conv3_bn_silu_tc<<<dim3(H_ / 4, C_ / 64, B_), thr, conv_smem>>>(
        p_wpe, p_v, pe_g, pe_b, pe_rm, pe_rv, p_pp);

    // 4) area attention
    attn_tc4<<<dim3(NA_ / 128, NHEAD, B_ * AREA_), thr, attn_smem>>>(
        p_qk, p_v, p_att);

    // 5) y = bn_silu(conv1x1(att + pp, pr_w))
    gemm_add_bn_silu_tc<<<dim3(N_ / 128, C_ / 128, B_), thr>>>(
        p_wpr, p_att, p_pp, pr_g, pr_b, pr_rm, pr_rv, out);
}

// round 7
// speedup vs baseline: 5.4614x; 1.0141x over previous
#include <cuda_runtime.h>
#include <math.h>

#define B_    8
#define C_    512
#define H_    64
#define W_    64
#define N_    4096          // H*W
#define AREA_ 4
#define NHEAD 8
#define HD_   64
#define NA_   1024          // N/AREA
#define EPS_  1e-5f

// ---------------- scratch (device globals; no allocation allowed) ----------
__device__ unsigned g_qk [B_ * 2 * C_ * N_];   // qk act, tf32 bits
__device__ unsigned g_v  [B_ * C_ * N_];       // v act, tf32 bits
__device__ float    g_pp [B_ * C_ * N_];       // position branch (fp32)
__device__ float    g_att[B_ * C_ * N_];       // attention out (fp32)
__device__ unsigned g_x  [B_ * C_ * N_];       // pre-rounded input
__device__ unsigned g_wqk[2 * C_ * C_];        // pre-rounded weights
__device__ unsigned g_wv [C_ * C_];
__device__ unsigned g_wpr[C_ * C_];
__device__ uint2    g_wpe[9 * 32 * 8 * 512];   // conv weights, pair layout

__device__ __forceinline__ float silu_f(float y) {
    return y / (1.0f + __expf(-y));
}
__device__ __forceinline__ unsigned f2tf(float x) {
    unsigned u; asm("cvt.rna.tf32.f32 %0, %1;" : "=r"(u) : "f"(x)); return u;
}
__device__ __forceinline__ void mma8(float* c, const unsigned* a, const unsigned* b) {
    asm volatile(
      "mma.sync.aligned.m16n8k8.row.col.f32.tf32.tf32.f32 "
      "{%0,%1,%2,%3},{%4,%5,%6,%7},{%8,%9},{%0,%1,%2,%3};"
      : "+f"(c[0]), "+f"(c[1]), "+f"(c[2]), "+f"(c[3])
      : "r"(a[0]), "r"(a[1]), "r"(a[2]), "r"(a[3]), "r"(b[0]), "r"(b[1]));
}
__device__ __forceinline__ void cpa16(void* dst, const void* src) {
    unsigned d = (unsigned)__cvta_generic_to_shared(dst);
    asm volatile("cp.async.cg.shared.global [%0], [%1], 16;" :: "r"(d), "l"(src));
}
__device__ __forceinline__ void cpa_commit() { asm volatile("cp.async.commit_group;"); }
__device__ __forceinline__ void cpa_wait1()  { asm volatile("cp.async.wait_group 1;"); }
__device__ __forceinline__ void cpa_wait0()  { asm volatile("cp.async.wait_group 0;"); }

// ============================================================================
// Pre-round fp32 -> tf32 bits (vectorized)
// ============================================================================
__global__ void preround(const float4* __restrict__ in, uint4* __restrict__ out, int n4)
{
    int i = blockIdx.x * blockDim.x + threadIdx.x;
    if (i < n4) {
        float4 v = in[i];
        out[i] = make_uint4(f2tf(v.x), f2tf(v.y), f2tf(v.z), f2tf(v.w));
    }
}

// ============================================================================
// Transform conv weights [O][I][3][3] -> pair layout [tap][chunk][pair][o]
// ============================================================================
__global__ void conv_w_xform(const float* __restrict__ pe_w, uint2* __restrict__ Wp)
{
    int idx = blockIdx.x * 256 + threadIdx.x;
    if (idx >= 9 * 32 * 8 * 512) return;
    int o     = idx & 511;
    int p     = (idx >> 9) & 7;
    int chunk = (idx >> 12) & 31;
    int tap   = idx >> 17;
    int c = chunk * 16 + ((p >> 2) << 3) + (p & 3);
    float a  = pe_w[((size_t)o * C_ + c) * 9 + tap];
    float bq = pe_w[((size_t)o * C_ + c + 4) * 9 + tap];
    Wp[idx] = make_uint2(f2tf(a), f2tf(bq));
}

// ============================================================================
// 1x1 conv GEMM + BN + SiLU; 3-stage cp.async ring.
// Block 128m x 128n, 8 warps (4m x 2n).  Stage = Ws[128*20] + Xs[16*136].
// ============================================================================
#define GSTG 4736   // words per stage (2560 + 2176)

__global__ __launch_bounds__(256, 2)
void gemm_bn_silu_tc(const unsigned* __restrict__ Wt,   // [M][512] tf32 bits
                     const unsigned* __restrict__ X,    // [B][512][N] tf32 bits
                     const float* __restrict__ gg,
                     const float* __restrict__ bb,
                     const float* __restrict__ rm,
                     const float* __restrict__ rv,
                     unsigned* __restrict__ Y, int M)   // tf32 bits out
{
    extern __shared__ unsigned sm[];   // 3 * GSTG words

    const int n0 = blockIdx.x * 128;
    const int m0 = blockIdx.y * 128;
    const int b  = blockIdx.z;
    const unsigned* Xb = X + (size_t)b * C_ * N_;

    const int tid = threadIdx.x, lane = tid & 31, warp = tid >> 5;
    const int g = lane >> 2, t = lane & 3;
    const int wm = warp >> 1, wn = warp & 1;

    const int wm0 = tid >> 2,            wk0 = (tid & 3) << 2;
    const int wm1 = (256 + tid) >> 2,    wk1 = ((256 + tid) & 3) << 2;
    const int xk0 = tid >> 5,            xn0 = (tid & 31) << 2;
    const int xk1 = (256 + tid) >> 5,    xn1 = ((256 + tid) & 31) << 2;

    // issue one k-chunk's copies into stage s
    #define GISSUE(K0, S) do {                                                  \
        unsigned* bs = sm + (S) * GSTG;                                         \
        cpa16(&bs[wm0 * 20 + wk0], Wt + (size_t)(m0 + wm0) * C_ + (K0) + wk0);  \
        cpa16(&bs[wm1 * 20 + wk1], Wt + (size_t)(m0 + wm1) * C_ + (K0) + wk1);  \
        cpa16(&bs[2560 + xk0 * 136 + xn0], Xb + (size_t)((K0) + xk0) * N_ + n0 + xn0); \
        cpa16(&bs[2560 + xk1 * 136 + xn1], Xb + (size_t)((K0) + xk1) * N_ + n0 + xn1); \
        cpa_commit();                                                           \
    } while (0)

    float acc[2][8][4] = {};

    GISSUE(0, 0);
    GISSUE(16, 1);

    for (int i = 0; i < 32; i++) {
        cpa_wait1();          // chunk i complete (1 group may stay in flight)
        __syncthreads();      // all threads' copies visible; stage (i+2)%3 free
        if (i + 2 < 32) GISSUE((i + 2) * 16, (i + 2) % 3);
        else            cpa_commit();   // keep group accounting uniform

        const unsigned* Ws = sm + (i % 3) * GSTG;
        const unsigned* Xs = Ws + 2560;
        #pragma unroll
        for (int ks = 0; ks < 2; ks++) {
            const int c = ks * 8 + t;
            unsigned a[2][4];
            #pragma unroll
            for (int mt = 0; mt < 2; mt++) {
                int r = wm * 32 + mt * 16 + g;
                a[mt][0] = Ws[r * 20 + c];       a[mt][1] = Ws[(r + 8) * 20 + c];
                a[mt][2] = Ws[r * 20 + c + 4];   a[mt][3] = Ws[(r + 8) * 20 + c + 4];
            }
            #pragma unroll
            for (int nt = 0; nt < 8; nt++) {
                int n = wn * 64 + nt * 8 + g;
                unsigned bf[2] = { Xs[c * 136 + n], Xs[(c + 4) * 136 + n] };
                mma8(acc[0][nt], a[0], bf);
                mma8(acc[1][nt], a[1], bf);
            }
        }
    }

    #pragma unroll
    for (int mt = 0; mt < 2; mt++) {
        int m  = m0 + wm * 32 + mt * 16 + g;
        int m1 = m + 8;
        float sc0 = gg[m]  * rsqrtf(rv[m]  + EPS_), sh0 = bb[m]  - rm[m]  * sc0;
        float sc1 = gg[m1] * rsqrtf(rv[m1] + EPS_), sh1 = bb[m1] - rm[m1] * sc1;
        #pragma unroll
        for (int nt = 0; nt < 8; nt++) {
            int n = n0 + wn * 64 + nt * 8 + 2 * t;
            float* c = acc[mt][nt];
            *(uint2*)&Y[((size_t)b * M + m)  * N_ + n] =
                make_uint2(f2tf(silu_f(c[0] * sc0 + sh0)), f2tf(silu_f(c[1] * sc0 + sh0)));
            *(uint2*)&Y[((size_t)b * M + m1) * N_ + n] =
                make_uint2(f2tf(silu_f(c[2] * sc1 + sh1)), f2tf(silu_f(c[3] * sc1 + sh1)));
        }
    }
}

// ============================================================================
// 3x3 SAME conv + BN + SiLU, pair layouts; W staged via cp.async.
// ============================================================================
__global__ __launch_bounds__(256, 2)
void conv3_bn_silu_tc(const uint2* __restrict__ Wp,
                      const unsigned* __restrict__ Xin,  // g_v (tf32 bits)
                      const float* __restrict__ gg,
                      const float* __restrict__ bb,
                      const float* __restrict__ rm,
                      const float* __restrict__ rv,
                      float* __restrict__ Yout)          // g_pp (fp32)
{
    extern __shared__ unsigned cs[];
    uint2* Ws2 = (uint2*)cs;                 // 9*8*68 uint2
    uint2* Xp  = (uint2*)cs + 9 * 8 * 68;    // 6*8*68 uint2

    const int y0 = blockIdx.x * 4;
    const int m0 = blockIdx.y * 64;
    const int b  = blockIdx.z;
    const unsigned* Xb = Xin + (size_t)b * C_ * N_;

    const int tid = threadIdx.x, lane = tid & 31, warp = tid >> 5;
    const int g = lane >> 2, t = lane & 3;
    const int wm = warp >> 2, wn = warp & 3;   // 2m x 4n

    const int wsp = tid >> 5, wso = (tid & 31) * 2;

    float acc[2][8][4] = {};

    for (int ci = 0; ci < 32; ci++) {
        __syncthreads();
        // W: 9 taps x 16B per thread via cp.async (overlaps with X staging below)
        #pragma unroll
        for (int tap = 0; tap < 9; tap++) {
            cpa16(&Ws2[(tap * 8 + wsp) * 68 + wso],
                  &Wp[(((size_t)tap * 32 + ci) * 8 + wsp) * 512 + m0 + wso]);
        }
        cpa_commit();
        // X: 6 rows x 8 channel-pairs x 66 (x = -1..64), zero pad
        for (int e = tid; e < 6 * 8 * 66; e += 256) {
            int r = e / 528; int rem = e - r * 528;
            int p = rem / 66; int xx = rem - p * 66;
            int c = ci * 16 + ((p >> 2) << 3) + (p & 3);
            int gy = y0 - 1 + r, gx = xx - 1;
            uint2 v = make_uint2(0u, 0u);
            if (gy >= 0 && gy < H_ && gx >= 0 && gx < W_) {
                const unsigned* s = Xb + (size_t)c * N_ + gy * W_ + gx;
                v.x = s[0]; v.y = s[4 * N_];
            }
            Xp[(r * 8 + p) * 68 + xx] = v;
        }
        cpa_wait0();
        __syncthreads();

        for (int tap = 0; tap < 9; tap++) {
            const int dy = tap / 3, dx = tap - dy * 3;
            #pragma unroll
            for (int ks = 0; ks < 2; ks++) {
                const int p = ks * 4 + t;
                const uint2* wr = &Ws2[(tap * 8 + p) * 68];
                uint2 wa0 = wr[wm * 32 + g],      wa1 = wr[wm * 32 + 8 + g];
                uint2 wb0 = wr[wm * 32 + 16 + g], wb1 = wr[wm * 32 + 24 + g];
                unsigned a0[4] = { wa0.x, wa1.x, wa0.y, wa1.y };
                unsigned a1[4] = { wb0.x, wb1.x, wb0.y, wb1.y };
                const uint2* xr = &Xp[((wn + dy) * 8 + p) * 68 + dx];
                #pragma unroll
                for (int nt = 0; nt < 8; nt++) {
                    uint2 xb = xr[nt * 8 + g];
                    unsigned bf[2] = { xb.x, xb.y };
                    mma8(acc[0][nt], a0, bf);
                    mma8(acc[1][nt], a1, bf);
                }
            }
        }
    }

    #pragma unroll
    for (int mt = 0; mt < 2; mt++) {
        int m  = m0 + wm * 32 + mt * 16 + g;
        int m1 = m + 8;
        float sc0 = gg[m]  * rsqrtf(rv[m]  + EPS_), sh0 = bb[m]  - rm[m]  * sc0;
        float sc1 = gg[m1] * rsqrtf(rv[m1] + EPS_), sh1 = bb[m1] - rm[m1] * sc1;
        #pragma unroll
        for (int nt = 0; nt < 8; nt++) {
            int n = wn * 64 + nt * 8 + 2 * t;
            float* c = acc[mt][nt];
            *(float2*)&Yout[((size_t)b * C_ + m)  * N_ + y0 * W_ + n] =
                make_float2(silu_f(c[0] * sc0 + sh0), silu_f(c[1] * sc0 + sh0));
            *(float2*)&Yout[((size_t)b * C_ + m1) * N_ + y0 * W_ + n] =
                make_float2(silu_f(c[2] * sc1 + sh1), silu_f(c[3] * sc1 + sh1));
        }
    }
}

// ============================================================================
// Area attention, FA2 style with uint2 pair layouts (unchanged from round 6)
// ============================================================================
__global__ __launch_bounds__(256, 2)
void attn_tc4(const unsigned* __restrict__ qk,
              const unsigned* __restrict__ vv,
              float* __restrict__ att)
{
    extern __shared__ unsigned as_[];
    uint2* Qp = (uint2*)as_;                          // [q][36]
    uint2* Kp = (uint2*)(as_ + 128 * 72);             // [32][68]
    uint2* Vp = (uint2*)(as_ + 128 * 72 + 32 * 136);  // [64][36]
    float* Os = (float*)as_;                          // [64][132] alias

    const int q0   = blockIdx.x * 128;
    const int head = blockIdx.y;
    const int ba   = blockIdx.z;
    const int b    = ba >> 2;
    const int area = ba & 3;

    const unsigned* Qb = qk + ((size_t)b * 2 * C_ +      head * HD_) * N_ + area * NA_;
    const unsigned* Kb = qk + ((size_t)b * 2 * C_ + C_ + head * HD_) * N_ + area * NA_;
    const unsigned* Vb = vv + ((size_t)b * C_     +      head * HD_) * N_ + area * NA_;
    float*          Ob = att + ((size_t)b * C_    +      head * HD_) * N_ + area * NA_;

    const int tid = threadIdx.x, lane = tid & 31, warp = tid >> 5;
    const int g = lane >> 2, t = lane & 3;
    const int wq = warp * 16;

    #pragma unroll
    for (int i = 0; i < 4; i++) {
        int G = tid + i * 256;
        int dp = G >> 5, ql = (G & 31) << 2;
        int kc = dp >> 2, tt = dp & 3;
        int dlo = kc * 8 + tt;
        uint4 A  = *(const uint4*)(Qb + (size_t)dlo * N_ + q0 + ql);
        uint4 Bq = *(const uint4*)(Qb + (size_t)(dlo + 4) * N_ + q0 + ql);
        Qp[(ql + 0) * 36 + kc * 4 + tt] = make_uint2(A.x, Bq.x);
        Qp[(ql + 1) * 36 + kc * 4 + tt] = make_uint2(A.y, Bq.y);
        Qp[(ql + 2) * 36 + kc * 4 + tt] = make_uint2(A.z, Bq.z);
        Qp[(ql + 3) * 36 + kc * 4 + tt] = make_uint2(A.w, Bq.w);
    }

    float mr0 = -1e30f, mr1 = -1e30f, lr0 = 0.0f, lr1 = 0.0f;
    float Oa[8][4] = {};
    const int sb = lane & ~3;
    const int s1l = sb + (t >> 1), s2l = s1l + 2;

    for (int j0 = 0; j0 < NA_; j0 += 64) {
        __syncthreads();
        #pragma unroll
        for (int i = 0; i < 2; i++) {
            int G = tid + i * 256;
            int r = G >> 4, ng = (G & 15) << 2;
            int kc = r >> 2, tt = r & 3;
            int dlo = kc * 8 + tt;
            uint4 A  = *(const uint4*)(Kb + (size_t)dlo * N_ + j0 + ng);
            uint4 Bk = *(const uint4*)(Kb + (size_t)(dlo + 4) * N_ + j0 + ng);
            uint2* dst = &Kp[r * 68 + ng];
            *(uint4*)&dst[0] = make_uint4(A.x, Bk.x, A.y, Bk.y);
            *(uint4*)&dst[2] = make_uint4(A.z, Bk.z, A.w, Bk.w);
        }
        #pragma unroll
        for (int i = 0; i < 2; i++) {
            int G = tid + i * 256;
            int d = G >> 3, kcg = G & 7;
            const unsigned* src = Vb + (size_t)d * N_ + j0 + kcg * 8;
            uint4 A  = *(const uint4*)(src);
            uint4 Bv = *(const uint4*)(src + 4);
            uint2* dst = &Vp[d * 36 + kcg * 4];
            *(uint4*)&dst[0] = make_uint4(A.x, Bv.x, A.y, Bv.y);
            *(uint4*)&dst[2] = make_uint4(A.z, Bv.z, A.w, Bv.w);
        }
        __syncthreads();

        float S[8][4] = {};
        #pragma unroll
        for (int kc = 0; kc < 8; kc++) {
            uint2 qa = Qp[(wq + g) * 36 + kc * 4 + t];
            uint2 qb = Qp[(wq + 8 + g) * 36 + kc * 4 + t];
            unsigned a[4] = { qa.x, qb.x, qa.y, qb.y };
            const uint2* kr = &Kp[(kc * 4 + t) * 68 + g];
            #pragma unroll
            for (int nt = 0; nt < 8; nt++) {
                uint2 kb = kr[nt * 8];
                unsigned bf[2] = { kb.x, kb.y };
                mma8(S[nt], a, bf);
            }
        }

        float mx0 = -1e30f, mx1 = -1e30f;
        #pragma unroll
        for (int nt = 0; nt < 8; nt++) {
            S[nt][0] *= 0.125f; S[nt][1] *= 0.125f;
            S[nt][2] *= 0.125f; S[nt][3] *= 0.125f;
            mx0 = fmaxf(mx0, fmaxf(S[nt][0], S[nt][1]));
            mx1 = fmaxf(mx1, fmaxf(S[nt][2], S[nt][3]));
        }
        mx0 = fmaxf(mx0, __shfl_xor_sync(0xffffffffu, mx0, 1));
        mx0 = fmaxf(mx0, __shfl_xor_sync(0xffffffffu, mx0, 2));
        mx1 = fmaxf(mx1, __shfl_xor_sync(0xffffffffu, mx1, 1));
        mx1 = fmaxf(mx1, __shfl_xor_sync(0xffffffffu, mx1, 2));
        float mn0 = fmaxf(mr0, mx0), mn1 = fmaxf(mr1, mx1);
        float al0 = __expf(mr0 - mn0), al1 = __expf(mr1 - mn1);
        mr0 = mn0; mr1 = mn1;
        float s0 = 0.0f, s1 = 0.0f;
        #pragma unroll
        for (int nt = 0; nt < 8; nt++) {
            float p0 = __expf(S[nt][0] - mn0), p1 = __expf(S[nt][1] - mn0);
            float p2 = __expf(S[nt][2] - mn1), p3 = __expf(S[nt][3] - mn1);
            s0 += p0 + p1; s1 += p2 + p3;
            S[nt][0] = __uint_as_float(f2tf(p0));
            S[nt][1] = __uint_as_float(f2tf(p1));
            S[nt][2] = __uint_as_float(f2tf(p2));
            S[nt][3] = __uint_as_float(f2tf(p3));
        }
        s0 += __shfl_xor_sync(0xffffffffu, s0, 1);
        s0 += __shfl_xor_sync(0xffffffffu, s0, 2);
        s1 += __shfl_xor_sync(0xffffffffu, s1, 1);
        s1 += __shfl_xor_sync(0xffffffffu, s1, 2);
        lr0 = lr0 * al0 + s0; lr1 = lr1 * al1 + s1;

        #pragma unroll
        for (int dt = 0; dt < 8; dt++) {
            Oa[dt][0] *= al0; Oa[dt][1] *= al0;
            Oa[dt][2] *= al1; Oa[dt][3] *= al1;
        }

        #pragma unroll
        for (int kc = 0; kc < 8; kc++) {
            unsigned p0 = __float_as_uint(S[kc][0]);
            unsigned p1 = __float_as_uint(S[kc][1]);
            unsigned p2 = __float_as_uint(S[kc][2]);
            unsigned p3 = __float_as_uint(S[kc][3]);
            unsigned x0 = __shfl_sync(0xffffffffu, p0, s1l);
            unsigned x1 = __shfl_sync(0xffffffffu, p1, s1l);
            unsigned x2 = __shfl_sync(0xffffffffu, p2, s1l);
            unsigned x3 = __shfl_sync(0xffffffffu, p3, s1l);
            unsigned y0 = __shfl_sync(0xffffffffu, p0, s2l);
            unsigned y1 = __shfl_sync(0xffffffffu, p1, s2l);
            unsigned y2 = __shfl_sync(0xffffffffu, p2, s2l);
            unsigned y3 = __shfl_sync(0xffffffffu, p3, s2l);
            unsigned av[4];
            if (t & 1) { av[0] = x1; av[1] = x3; av[2] = y1; av[3] = y3; }
            else       { av[0] = x0; av[1] = x2; av[2] = y0; av[3] = y2; }
            const uint2* vr = &Vp[g * 36 + kc * 4 + t];
            #pragma unroll
            for (int dt = 0; dt < 8; dt++) {
                uint2 vb = vr[dt * 288];
                unsigned bf[2] = { vb.x, vb.y };
                mma8(Oa[dt], av, bf);
            }
        }
    }

    __syncthreads();
    float li0 = 1.0f / lr0, li1 = 1.0f / lr1;
    #pragma unroll
    for (int dt = 0; dt < 8; dt++) {
        int d = dt * 8 + 2 * t;
        Os[d * 132 + wq + g]           = Oa[dt][0] * li0;
        Os[(d + 1) * 132 + wq + g]     = Oa[dt][1] * li0;
        Os[d * 132 + wq + 8 + g]       = Oa[dt][2] * li1;
        Os[(d + 1) * 132 + wq + 8 + g] = Oa[dt][3] * li1;
    }
    __syncthreads();
    #pragma unroll
    for (int i = 0; i < 8; i++) {
        int e4 = i * 256 + tid;
        int d = e4 >> 5, qq = (e4 & 31) << 2;
        float4 o4 = *(const float4*)&Os[d * 132 + qq];
        *(float4*)(Ob + (size_t)d * N_ + q0 + qq) = o4;
    }
}

// ============================================================================
// Final 1x1 conv over (att + pp), BN+SiLU -> d_out (unchanged from round 6)
// ============================================================================
__global__ __launch_bounds__(256, 2)
void gemm_add_bn_silu_tc(const unsigned* __restrict__ Wt,
                         const float* __restrict__ Xa,
                         const float* __restrict__ Xp,
                         const float* __restrict__ gg,
                         const float* __restrict__ bb,
                         const float* __restrict__ rm,
                         const float* __restrict__ rv,
                         float* __restrict__ Y)
{
    __shared__ unsigned Ws[128 * 20];
    __shared__ unsigned Xs[16 * 136];

    const int n0 = blockIdx.x * 128;
    const int m0 = blockIdx.y * 128;
    const int b  = blockIdx.z;
    const float* X1 = Xa + (size_t)b * C_ * N_;
    const float* X2 = Xp + (size_t)b * C_ * N_;

    const int tid = threadIdx.x, lane = tid & 31, warp = tid >> 5;
    const int g = lane >> 2, t = lane & 3;
    const int wm = warp >> 1, wn = warp & 1;

    const int wm0 = tid >> 2,            wk0 = (tid & 3) << 2;
    const int wm1 = (256 + tid) >> 2,    wk1 = ((256 + tid) & 3) << 2;
    const int xk0 = tid >> 5,            xn0 = (tid & 31) << 2;
    const int xk1 = (256 + tid) >> 5,    xn1 = ((256 + tid) & 31) << 2;

    float acc[2][8][4] = {};
    float4 xa0, xa1, xp0, xp1;

    xa0 = *(const float4*)(X1 + (size_t)xk0 * N_ + n0 + xn0);
    xa1 = *(const float4*)(X1 + (size_t)xk1 * N_ + n0 + xn1);
    xp0 = *(const float4*)(X2 + (size_t)xk0 * N_ + n0 + xn0);
    xp1 = *(const float4*)(X2 + (size_t)xk1 * N_ + n0 + xn1);

    for (int k0 = 0; k0 < C_; k0 += 16) {
        // W via cp.async, X via registers (must compute att+pp then round)
        cpa16(&Ws[wm0 * 20 + wk0], Wt + (size_t)(m0 + wm0) * C_ + k0 + wk0);
        cpa16(&Ws[wm1 * 20 + wk1], Wt + (size_t)(m0 + wm1) * C_ + k0 + wk1);
        cpa_commit();
        {
            unsigned* p;
            p = &Xs[xk0 * 136 + xn0];
            p[0]=f2tf(xa0.x+xp0.x); p[1]=f2tf(xa0.y+xp0.y);
            p[2]=f2tf(xa0.z+xp0.z); p[3]=f2tf(xa0.w+xp0.w);
            p = &Xs[xk1 * 136 + xn1];
            p[0]=f2tf(xa1.x+xp1.x); p[1]=f2tf(xa1.y+xp1.y);
            p[2]=f2tf(xa1.z+xp1.z); p[3]=f2tf(xa1.w+xp1.w);
        }
        cpa_wait0();
        __syncthreads();
        if (k0 + 16 < C_) {
            int kn = k0 + 16;
            xa0 = *(const float4*)(X1 + (size_t)(kn + xk0) * N_ + n0 + xn0);
            xa1 = *(const float4*)(X1 + (size_t)(kn + xk1) * N_ + n0 + xn1);
            xp0 = *(const float4*)(X2 + (size_t)(kn + xk0) * N_ + n0 + xn0);
            xp1 = *(const float4*)(X2 + (size_t)(kn + xk1) * N_ + n0 + xn1);
        }
        #pragma unroll
        for (int ks = 0; ks < 2; ks++) {
            const int c = ks * 8 + t;
            unsigned a[2][4];
            #pragma unroll
            for (int mt = 0; mt < 2; mt++) {
                int r = wm * 32 + mt * 16 + g;
                a[mt][0] = Ws[r * 20 + c];       a[mt][1] = Ws[(r + 8) * 20 + c];
                a[mt][2] = Ws[r * 20 + c + 4];   a[mt][3] = Ws[(r + 8) * 20 + c + 4];
            }
            #pragma unroll
            for (int nt = 0; nt < 8; nt++) {
                int n = wn * 64 + nt * 8 + g;
                unsigned bf[2] = { Xs[c * 136 + n], Xs[(c + 4) * 136 + n] };
                mma8(acc[0][nt], a[0], bf);
                mma8(acc[1][nt], a[1], bf);
            }
        }
        __syncthreads();
    }

    #pragma unroll
    for (int mt = 0; mt < 2; mt++) {
        int m  = m0 + wm * 32 + mt * 16 + g;
        int m1 = m + 8;
        float sc0 = gg[m]  * rsqrtf(rv[m]  + EPS_), sh0 = bb[m]  - rm[m]  * sc0;
        float sc1 = gg[m1] * rsqrtf(rv[m1] + EPS_), sh1 = bb[m1] - rm[m1] * sc1;
        #pragma unroll
        for (int nt = 0; nt < 8; nt++) {
            int n = n0 + wn * 64 + nt * 8 + 2 * t;
            float* c = acc[mt][nt];
            *(float2*)&Y[((size_t)b * C_ + m)  * N_ + n] =
                make_float2(silu_f(c[0] * sc0 + sh0), silu_f(c[1] * sc0 + sh0));
            *(float2*)&Y[((size_t)b * C_ + m1) * N_ + n] =
                make_float2(silu_f(c[2] * sc1 + sh1), silu_f(c[3] * sc1 + sh1));
        }
    }
}

// ============================================================================
extern "C" void kernel_launch(void* const* d_in, const int* in_sizes, int n_in,
                              void* d_out, int out_size)
{
    const float* x     = (const float*)d_in[0];
    const float* qk_w  = (const float*)d_in[1];
    const float* qk_g  = (const float*)d_in[2];
    const float* qk_b  = (const float*)d_in[3];
    const float* qk_rm = (const float*)d_in[4];
    const float* qk_rv = (const float*)d_in[5];
    const float* v_w   = (const float*)d_in[6];
    const float* v_g   = (const float*)d_in[7];
    const float* v_b   = (const float*)d_in[8];
    const float* v_rm  = (const float*)d_in[9];
    const float* v_rv  = (const float*)d_in[10];
    const float* pe_w  = (const float*)d_in[11];
    const float* pe_g  = (const float*)d_in[12];
    const float* pe_b  = (const float*)d_in[13];
    const float* pe_rm = (const float*)d_in[14];
    const float* pe_rv = (const float*)d_in[15];
    const float* pr_w  = (const float*)d_in[16];
    const float* pr_g  = (const float*)d_in[17];
    const float* pr_b  = (const float*)d_in[18];
    const float* pr_rm = (const float*)d_in[19];
    const float* pr_rv = (const float*)d_in[20];
    float* out = (float*)d_out;

    unsigned *p_qk, *p_v, *p_x, *p_wqk, *p_wv, *p_wpr;
    float *p_pp, *p_att;
    uint2 *p_wpe;
    cudaGetSymbolAddress((void**)&p_qk,  g_qk);
    cudaGetSymbolAddress((void**)&p_v,   g_v);
    cudaGetSymbolAddress((void**)&p_pp,  g_pp);
    cudaGetSymbolAddress((void**)&p_att, g_att);
    cudaGetSymbolAddress((void**)&p_x,   g_x);
    cudaGetSymbolAddress((void**)&p_wqk, g_wqk);
    cudaGetSymbolAddress((void**)&p_wv,  g_wv);
    cudaGetSymbolAddress((void**)&p_wpr, g_wpr);
    cudaGetSymbolAddress((void**)&p_wpe, g_wpe);

    const int gemm_smem = 3 * GSTG * 4;                                // 56832
    const int conv_smem = (9 * 8 * 68 + 6 * 8 * 68) * 8;               // 65280
    const int attn_smem = (128 * 72 + 32 * 136 + 64 * 72) * 4;         // 72704
    cudaFuncSetAttribute(gemm_bn_silu_tc,
                         cudaFuncAttributeMaxDynamicSharedMemorySize, gemm_smem);
    cudaFuncSetAttribute(conv3_bn_silu_tc,
                         cudaFuncAttributeMaxDynamicSharedMemorySize, conv_smem);
    cudaFuncSetAttribute(attn_tc4,
                         cudaFuncAttributeMaxDynamicSharedMemorySize, attn_smem);

    dim3 thr(256);

    // 0) pre-round inputs/weights to tf32 bit patterns
    preround<<<(B_ * C_ * N_ / 4 + 255) / 256, thr>>>(
        (const float4*)x, (uint4*)p_x, B_ * C_ * N_ / 4);
    preround<<<(2 * C_ * C_ / 4 + 255) / 256, thr>>>(
        (const float4*)qk_w, (uint4*)p_wqk, 2 * C_ * C_ / 4);
    preround<<<(C_ * C_ / 4 + 255) / 256, thr>>>(
        (const float4*)v_w, (uint4*)p_wv, C_ * C_ / 4);
    preround<<<(C_ * C_ / 4 + 255) / 256, thr>>>(
        (const float4*)pr_w, (uint4*)p_wpr, C_ * C_ / 4);
    conv_w_xform<<<(9 * 32 * 8 * 512 + 255) / 256, thr>>>(pe_w, p_wpe);

    // 1) qk = bn_silu(conv1x1(x, qk_w))   M=1024
    gemm_bn_silu_tc<<<dim3(N_ / 128, 1024 / 128, B_), thr, gemm_smem>>>(
        p_wqk, p_x, qk_g, qk_b, qk_rm, qk_rv, p_qk, 1024);

    // 2) vmap = bn_silu(conv1x1(x, v_w))  M=512
    gemm_bn_silu_tc<<<dim3(N_ / 128, C_ / 128, B_), thr, gemm_smem>>>(
        p_wv, p_x, v_g, v_b, v_rm, v_rv, p_v, C_);

    // 3) pp = bn_silu(conv3x3(vmap, pe_w))
    conv3_bn_silu_tc<<<dim3(H_ / 4, C_ / 64, B_), thr, conv_smem>>>(
        p_wpe, p_v, pe_g, pe_b, pe_rm, pe_rv, p_pp);

    // 4) area attention
    attn_tc4<<<dim3(NA_ / 128, NHEAD, B_ * AREA_), thr, attn_smem>>>(
        p_qk, p_v, p_att);

    // 5) y = bn_silu(conv1x1(att + pp, pr_w))
    gemm_add_bn_silu_tc<<<dim3(N_ / 128, C_ / 128, B_), thr>>>(
        p_wpr, p_att, p_pp, pr_g, pr_b, pr_rm, pr_rv, out);
}

// round 10
// speedup vs baseline: 7.0972x; 1.2995x over previous
#include <cuda_runtime.h>
#include <cuda_fp16.h>
#include <math.h>
#include <stdint.h>

#define B_    8
#define C_    512
#define H_    64
#define W_    64
#define N_    4096          // H*W
#define AREA_ 4
#define NHEAD 8
#define HD_   64
#define NA_   1024          // N/AREA
#define EPS_  1e-5f

// ---------------- scratch (device globals; no allocation allowed) ----------
__device__ __half g_xt  [B_ * N_ * C_];        // x^T  [b][n][c]
__device__ __half g_wqkh[2 * C_ * C_];         // weights, half row-major
__device__ __half g_wvh [C_ * C_];
__device__ __half g_wprh[C_ * C_];
__device__ __half g_wpeh[9 * 32 * 512 * 16];   // conv w [tap][ci][o][16]
__device__ __half g_qkT [B_ * N_ * 2 * C_];    // qk act, token-major [b][n][2C]
__device__ __half g_vh  [B_ * C_ * N_];        // v act [b][c][n]
__device__ __half g_vT  [B_ * N_ * C_];        // v act transposed [b][n][c]
__device__ __half g_ppT [B_ * N_ * C_];        // conv3 out, token-major
__device__ __half g_attT[B_ * N_ * C_];        // attention out, token-major

__device__ __forceinline__ float silu_f(float y) {
    return y / (1.0f + __expf(-y));
}
__device__ __forceinline__ unsigned h2f(float a, float b) {
    __half2 h = __floats2half2_rn(a, b);
    return *reinterpret_cast<unsigned*>(&h);
}
// D += A*B, m16n8k16 f16 in / f32 accum, row.col
__device__ __forceinline__ void mma16(float* c, const unsigned* a, const unsigned* b) {
    asm volatile(
      "mma.sync.aligned.m16n8k16.row.col.f32.f16.f16.f32 "
      "{%0,%1,%2,%3},{%4,%5,%6,%7},{%8,%9},{%0,%1,%2,%3};"
      : "+f"(c[0]), "+f"(c[1]), "+f"(c[2]), "+f"(c[3])
      : "r"(a[0]), "r"(a[1]), "r"(a[2]), "r"(a[3]), "r"(b[0]), "r"(b[1]));
}
__device__ __forceinline__ void cpa16(void* dst, const void* src) {
    unsigned d = (unsigned)__cvta_generic_to_shared(dst);
    asm volatile("cp.async.cg.shared.global [%0], [%1], 16;" :: "r"(d), "l"(src));
}
__device__ __forceinline__ void cpa16z(void* dst, const void* src, unsigned sz) {
    unsigned d = (unsigned)__cvta_generic_to_shared(dst);
    asm volatile("cp.async.cg.shared.global [%0], [%1], 16, %2;" :: "r"(d), "l"(src), "r"(sz));
}
__device__ __forceinline__ void cpa_commit() { asm volatile("cp.async.commit_group;"); }
__device__ __forceinline__ void cpa_wait1()  { asm volatile("cp.async.wait_group 1;"); }
__device__ __forceinline__ void cpa_wait0()  { asm volatile("cp.async.wait_group 0;"); }

// ============================================================================
// Prep kernels
// ============================================================================
__global__ void f2h_k(const float4* __restrict__ in, uint4* __restrict__ out, int n8)
{
    int i = blockIdx.x * blockDim.x + threadIdx.x;
    if (i < n8) {
        float4 a = in[2 * i], b = in[2 * i + 1];
        out[i] = make_uint4(h2f(a.x, a.y), h2f(a.z, a.w), h2f(b.x, b.y), h2f(b.z, b.w));
    }
}

// x [b][c][n] fp32 -> g_xt [b][n][c] half
__global__ void xpose_h(const float* __restrict__ x, __half* __restrict__ xt)
{
    __shared__ float ts[32][33];
    const int b  = blockIdx.z;
    const int c0 = blockIdx.y * 32;
    const int nb = blockIdx.x * 32;
    const int tx = threadIdx.x, ty = threadIdx.y;   // 32 x 8
    const float* xb = x + ((size_t)b * C_ + c0) * N_ + nb;
    #pragma unroll
    for (int i = 0; i < 4; i++) {
        int c = ty + i * 8;
        ts[c][tx] = xb[(size_t)c * N_ + tx];
    }
    __syncthreads();
    const int e0 = ty * 32 + tx;
    #pragma unroll
    for (int i = 0; i < 2; i++) {
        int idx = i * 256 + e0;
        int n = idx >> 4, w = idx & 15;
        unsigned word = h2f(ts[2 * w][n], ts[2 * w + 1][n]);
        ((unsigned*)(xt + ((size_t)b * N_ + nb + n) * C_ + c0))[w] = word;
    }
}

// pe_w [O][I][3][3] fp32 -> g_wpeh [tap][ci][o][16] half
__global__ void conv_w_xform_h(const float* __restrict__ pe_w, __half* __restrict__ wp)
{
    int idx = blockIdx.x * 256 + threadIdx.x;
    if (idx >= 9 * 32 * 512 * 16) return;
    int cl  = idx & 15;
    int o   = (idx >> 4) & 511;
    int ci  = (idx >> 13) & 31;
    int tap = idx >> 18;
    wp[idx] = __float2half_rn(pe_w[((size_t)o * C_ + ci * 16 + cl) * 9 + tap]);
}

// ============================================================================
// fp16 GEMM + BN + SiLU.  Writes Y^T [n][m] half (always) and Y [m][n] (opt).
// Tile 128x128, 8 warps (4m x 2n), K-chunk 32, 2-stage cp.async.
// ============================================================================
#define GH_STG 5120   // words/stage: A 128*20 + B 128*20

__global__ __launch_bounds__(256, 2)
void gemm_h(const __half* __restrict__ Wt,
            const __half* __restrict__ Xt,
            const float* __restrict__ gg, const float* __restrict__ bb,
            const float* __restrict__ rm, const float* __restrict__ rv,
            __half* __restrict__ Yt,      // [b][n][M]
            __half* __restrict__ Yc,      // [b][m][N] or null
            int M)
{
    extern __shared__ unsigned sm[];     // 2 * GH_STG words

    const int n0 = blockIdx.x * 128;
    const int m0 = blockIdx.y * 128;
    const int b  = blockIdx.z;
    const __half* Wb = Wt + (size_t)m0 * C_;
    const __half* Xb = Xt + ((size_t)b * N_ + n0) * C_;

    const int tid = threadIdx.x, lane = tid & 31, warp = tid >> 5;
    const int g = lane >> 2, t = lane & 3;
    const int wm = warp >> 1, wn = warp & 1;

    float acc[2][8][4] = {};

    #define GH_ISSUE(CH, S) do {                                            \
        unsigned* bs = sm + (S) * GH_STG;                                   \
        _Pragma("unroll")                                                   \
        for (int i_ = 0; i_ < 4; i_++) {                                    \
            int e = tid + 256 * i_;                                         \
            int op = e >> 9, r = (e >> 2) & 127, q = e & 3;                 \
            const __half* src = (op ? Xb : Wb) + (size_t)r * C_ + (CH) * 32 + q * 8; \
            cpa16(bs + (op ? 2560 : 0) + r * 20 + q * 4, src);              \
        }                                                                   \
        cpa_commit();                                                       \
    } while (0)

    GH_ISSUE(0, 0);
    GH_ISSUE(1, 1);

    for (int ch = 0; ch < 16; ch++) {
        cpa_wait1();
        __syncthreads();
        const unsigned* Ws = sm + (ch & 1) * GH_STG;
        const unsigned* Xs = Ws + 2560;
        #pragma unroll
        for (int ks = 0; ks < 2; ks++) {
            const int base = 8 * ks + t;
            unsigned a[2][4];
            #pragma unroll
            for (int mt = 0; mt < 2; mt++) {
                int R0 = wm * 32 + mt * 16 + g;
                a[mt][0] = Ws[R0 * 20 + base];
                a[mt][1] = Ws[(R0 + 8) * 20 + base];
                a[mt][2] = Ws[R0 * 20 + base + 4];
                a[mt][3] = Ws[(R0 + 8) * 20 + base + 4];
            }
            #pragma unroll
            for (int nt = 0; nt < 8; nt++) {
                int n = wn * 64 + nt * 8 + g;
                unsigned bf[2] = { Xs[n * 20 + base], Xs[n * 20 + base + 4] };
                mma16(acc[0][nt], a[0], bf);
                mma16(acc[1][nt], a[1], bf);
            }
        }
        __syncthreads();
        if (ch + 2 < 16) GH_ISSUE(ch + 2, ch & 1);
        else             cpa_commit();
    }

    __half* hs = (__half*)sm;            // [128 n][136 m]
    #pragma unroll
    for (int mt = 0; mt < 2; mt++) {
        int R0 = wm * 32 + mt * 16 + g;
        int m  = m0 + R0, m1 = m + 8;
        float sc0 = gg[m]  * rsqrtf(rv[m]  + EPS_), sh0 = bb[m]  - rm[m]  * sc0;
        float sc1 = gg[m1] * rsqrtf(rv[m1] + EPS_), sh1 = bb[m1] - rm[m1] * sc1;
        #pragma unroll
        for (int nt = 0; nt < 8; nt++) {
            float* c = acc[mt][nt];
            float v0 = silu_f(c[0] * sc0 + sh0), v1 = silu_f(c[1] * sc0 + sh0);
            float v2 = silu_f(c[2] * sc1 + sh1), v3 = silu_f(c[3] * sc1 + sh1);
            int px0 = wn * 64 + nt * 8 + 2 * t;
            if (Yc) {
                *(unsigned*)(Yc + ((size_t)b * M + m)  * N_ + n0 + px0) = h2f(v0, v1);
                *(unsigned*)(Yc + ((size_t)b * M + m1) * N_ + n0 + px0) = h2f(v2, v3);
            }
            hs[px0 * 136 + R0]           = __float2half_rn(v0);
            hs[(px0 + 1) * 136 + R0]     = __float2half_rn(v1);
            hs[px0 * 136 + R0 + 8]       = __float2half_rn(v2);
            hs[(px0 + 1) * 136 + R0 + 8] = __float2half_rn(v3);
        }
    }
    __syncthreads();
    const unsigned* hw = (const unsigned*)hs;
    #pragma unroll
    for (int i = 0; i < 32; i++) {
        int e = tid + 256 * i;
        int n = e >> 6, w = e & 63;
        ((unsigned*)(Yt + ((size_t)b * N_ + n0 + n) * M + m0))[w] = hw[n * 68 + w];
    }
    #undef GH_ISSUE
}

// ============================================================================
// fp16 3x3 SAME conv + BN + SiLU.  A = g_wpeh, B = vT; output ppT [n][c].
// ============================================================================
#define CV_AW  (9 * 64 * 12)
#define CV_BX  (6 * 66 * 12)
#define CV_SMEM ((CV_AW + CV_BX) * 4)

__global__ __launch_bounds__(256, 2)
void conv3_h(const __half* __restrict__ Wp,
             const __half* __restrict__ vT,
             const float* __restrict__ gg, const float* __restrict__ bb,
             const float* __restrict__ rm, const float* __restrict__ rv,
             __half* __restrict__ ppT)
{
    extern __shared__ unsigned cs[];
    unsigned* Aw = cs;               // [tap*64 + o][12]
    unsigned* Bx = cs + CV_AW;       // [r*66 + p][12]

    const int y0 = blockIdx.x * 4;
    const int m0 = blockIdx.y * 64;
    const int b  = blockIdx.z;
    const __half* vTb = vT + (size_t)b * N_ * C_;

    const int tid = threadIdx.x, lane = tid & 31, warp = tid >> 5;
    const int g = lane >> 2, t = lane & 3;
    const int wm = warp >> 2, wn = warp & 3;   // 2m x 4n

    float acc[2][8][4] = {};

    for (int ci = 0; ci < 32; ci++) {
        __syncthreads();
        for (int e = tid; e < 1152; e += 256) {
            int tap = e >> 7, r = (e >> 1) & 63, q = e & 1;
            cpa16(Aw + (tap * 64 + r) * 12 + q * 4,
                  Wp + (((size_t)tap * 32 + ci) * 512 + m0 + r) * 16 + q * 8);
        }
        for (int e = tid; e < 792; e += 256) {
            int r = e / 132, rem = e - r * 132;
            int p = rem >> 1, q = rem & 1;
            int gy = y0 - 1 + r, gx = p - 1;
            bool ok = (gy >= 0 && gy < H_ && gx >= 0 && gx < W_);
            const __half* src = vTb + (ok ? ((size_t)(gy * W_ + gx) * C_ + ci * 16 + q * 8) : 0);
            cpa16z(Bx + (r * 66 + p) * 12 + q * 4, src, ok ? 16u : 0u);
        }
        cpa_commit();
        cpa_wait0();
        __syncthreads();

        for (int tap = 0; tap < 9; tap++) {
            const int dy = tap / 3, dx = tap - dy * 3;
            unsigned a[2][4];
            #pragma unroll
            for (int mt = 0; mt < 2; mt++) {
                int R0 = wm * 32 + mt * 16 + g;
                const unsigned* ar = Aw + (tap * 64 + R0) * 12;
                a[mt][0] = ar[t];          a[mt][1] = ar[8 * 12 + t];
                a[mt][2] = ar[t + 4];      a[mt][3] = ar[8 * 12 + t + 4];
            }
            const int r = wn + dy;
            #pragma unroll
            for (int nt = 0; nt < 8; nt++) {
                int p = nt * 8 + g + dx;
                const unsigned* br = Bx + (r * 66 + p) * 12;
                unsigned bf[2] = { br[t], br[t + 4] };
                mma16(acc[0][nt], a[0], bf);
                mma16(acc[1][nt], a[1], bf);
            }
        }
    }

    __syncthreads();
    __half* hs = (__half*)cs;        // [256 px][72 o]
    #pragma unroll
    for (int mt = 0; mt < 2; mt++) {
        int R0 = wm * 32 + mt * 16 + g;
        int m  = m0 + R0, m1 = m + 8;
        float sc0 = gg[m]  * rsqrtf(rv[m]  + EPS_), sh0 = bb[m]  - rm[m]  * sc0;
        float sc1 = gg[m1] * rsqrtf(rv[m1] + EPS_), sh1 = bb[m1] - rm[m1] * sc1;
        #pragma unroll
        for (int nt = 0; nt < 8; nt++) {
            float* c = acc[mt][nt];
            int P0 = wn * 64 + nt * 8 + 2 * t;
            hs[P0 * 72 + R0]           = __float2half_rn(silu_f(c[0] * sc0 + sh0));
            hs[(P0 + 1) * 72 + R0]     = __float2half_rn(silu_f(c[1] * sc0 + sh0));
            hs[P0 * 72 + R0 + 8]       = __float2half_rn(silu_f(c[2] * sc1 + sh1));
            hs[(P0 + 1) * 72 + R0 + 8] = __float2half_rn(silu_f(c[3] * sc1 + sh1));
        }
    }
    __syncthreads();
    const unsigned* hw = (const unsigned*)hs;
    #pragma unroll
    for (int i = 0; i < 32; i++) {
        int e = tid + 256 * i;
        int P = e >> 5, w = e & 31;
        ((unsigned*)(ppT + ((size_t)b * N_ + y0 * W_ + P) * C_ + m0))[w] = hw[P * 36 + w];
    }
}

// ============================================================================
// fp16 area attention (FA2), zero shuffles.  Output attT [b][tok][512].
// FIXED: stage full 64-half rows (q = e & 7 -> 32 words per row).
// ============================================================================
#define AT_QS (128 * 36)
#define AT_KS (64 * 36)
#define AT_VS (64 * 36)
#define AT_SMEM ((AT_QS + AT_KS + AT_VS) * 4)

__global__ __launch_bounds__(256, 2)
void attn_h(const __half* __restrict__ qkT,
            const __half* __restrict__ vh,
            __half* __restrict__ attT)
{
    extern __shared__ unsigned as_[];
    unsigned* Qs = as_;                   // [q][36]
    unsigned* Ks = as_ + AT_QS;           // [j][36]
    unsigned* Vs = as_ + AT_QS + AT_KS;   // [d][36]

    const int q0   = blockIdx.x * 128;
    const int head = blockIdx.y;
    const int ba   = blockIdx.z;
    const int b    = ba >> 2;
    const int area = ba & 3;
    const int atok = area * NA_;

    const __half* Qb = qkT + ((size_t)b * N_ + atok + q0) * (2 * C_) + head * HD_;
    const __half* Kb = qkT + ((size_t)b * N_ + atok) * (2 * C_) + C_ + head * HD_;
    const __half* Vb = vh  + ((size_t)b * C_ + head * HD_) * N_ + atok;
    __half*       Ob = attT + ((size_t)b * N_ + atok + q0) * C_ + head * HD_;

    const int tid = threadIdx.x, lane = tid & 31, warp = tid >> 5;
    const int g = lane >> 2, t = lane & 3;
    const int wq = warp * 16;

    // stage Q once: 128 rows x 32 words (FULL rows)
    #pragma unroll
    for (int i = 0; i < 4; i++) {
        int e = tid + 256 * i;
        int r = e >> 3, q = e & 7;
        cpa16(Qs + r * 36 + q * 4, Qb + (size_t)r * (2 * C_) + q * 8);
    }
    cpa_commit();

    float mr0 = -1e30f, mr1 = -1e30f, lr0 = 0.0f, lr1 = 0.0f;
    float Oa[8][4] = {};
    unsigned qf[4][4];
    bool qf_done = false;

    for (int j0 = 0; j0 < NA_; j0 += 64) {
        __syncthreads();
        // K: 64 rows x 32 words
        #pragma unroll
        for (int i = 0; i < 2; i++) {
            int e = tid + 256 * i;
            int r = e >> 3, q = e & 7;
            cpa16(Ks + r * 36 + q * 4, Kb + (size_t)(j0 + r) * (2 * C_) + q * 8);
        }
        // V: 64 rows x 32 words
        #pragma unroll
        for (int i = 0; i < 2; i++) {
            int e = tid + 256 * i;
            int r = e >> 3, q = e & 7;
            cpa16(Vs + r * 36 + q * 4, Vb + (size_t)r * N_ + j0 + q * 8);
        }
        cpa_commit();
        cpa_wait0();
        __syncthreads();

        if (!qf_done) {
            qf_done = true;
            #pragma unroll
            for (int s = 0; s < 4; s++) {
                qf[s][0] = Qs[(wq + g) * 36 + 8 * s + t];
                qf[s][1] = Qs[(wq + 8 + g) * 36 + 8 * s + t];
                qf[s][2] = Qs[(wq + g) * 36 + 8 * s + t + 4];
                qf[s][3] = Qs[(wq + 8 + g) * 36 + 8 * s + t + 4];
            }
        }

        float S[8][4] = {};
        #pragma unroll
        for (int s = 0; s < 4; s++) {
            #pragma unroll
            for (int nt = 0; nt < 8; nt++) {
                int j = nt * 8 + g;
                unsigned bf[2] = { Ks[j * 36 + 8 * s + t], Ks[j * 36 + 8 * s + t + 4] };
                mma16(S[nt], qf[s], bf);
            }
        }

        float mx0 = -1e30f, mx1 = -1e30f;
        #pragma unroll
        for (int nt = 0; nt < 8; nt++) {
            S[nt][0] *= 0.125f; S[nt][1] *= 0.125f;
            S[nt][2] *= 0.125f; S[nt][3] *= 0.125f;
            mx0 = fmaxf(mx0, fmaxf(S[nt][0], S[nt][1]));
            mx1 = fmaxf(mx1, fmaxf(S[nt][2], S[nt][3]));
        }
        mx0 = fmaxf(mx0, __shfl_xor_sync(0xffffffffu, mx0, 1));
        mx0 = fmaxf(mx0, __shfl_xor_sync(0xffffffffu, mx0, 2));
        mx1 = fmaxf(mx1, __shfl_xor_sync(0xffffffffu, mx1, 1));
        mx1 = fmaxf(mx1, __shfl_xor_sync(0xffffffffu, mx1, 2));
        float mn0 = fmaxf(mr0, mx0), mn1 = fmaxf(mr1, mx1);
        float al0 = __expf(mr0 - mn0), al1 = __expf(mr1 - mn1);
        mr0 = mn0; mr1 = mn1;
        float s0 = 0.0f, s1 = 0.0f;
        #pragma unroll
        for (int nt = 0; nt < 8; nt++) {
            S[nt][0] = __expf(S[nt][0] - mn0);
            S[nt][1] = __expf(S[nt][1] - mn0);
            S[nt][2] = __expf(S[nt][2] - mn1);
            S[nt][3] = __expf(S[nt][3] - mn1);
            s0 += S[nt][0] + S[nt][1];
            s1 += S[nt][2] + S[nt][3];
        }
        s0 += __shfl_xor_sync(0xffffffffu, s0, 1);
        s0 += __shfl_xor_sync(0xffffffffu, s0, 2);
        s1 += __shfl_xor_sync(0xffffffffu, s1, 1);
        s1 += __shfl_xor_sync(0xffffffffu, s1, 2);
        lr0 = lr0 * al0 + s0; lr1 = lr1 * al1 + s1;

        #pragma unroll
        for (int dt = 0; dt < 8; dt++) {
            Oa[dt][0] *= al0; Oa[dt][1] *= al0;
            Oa[dt][2] *= al1; Oa[dt][3] *= al1;
        }

        #pragma unroll
        for (int s = 0; s < 4; s++) {
            unsigned pa[4] = {
                h2f(S[2 * s][0],     S[2 * s][1]),
                h2f(S[2 * s][2],     S[2 * s][3]),
                h2f(S[2 * s + 1][0], S[2 * s + 1][1]),
                h2f(S[2 * s + 1][2], S[2 * s + 1][3])
            };
            #pragma unroll
            for (int dt = 0; dt < 8; dt++) {
                int d = dt * 8 + g;
                unsigned bf[2] = { Vs[d * 36 + 8 * s + t], Vs[d * 36 + 8 * s + t + 4] };
                mma16(Oa[dt], pa, bf);
            }
        }
    }

    float li0 = 1.0f / lr0, li1 = 1.0f / lr1;
    __half* r0p = Ob + (size_t)(wq + g) * C_;
    __half* r1p = Ob + (size_t)(wq + 8 + g) * C_;
    #pragma unroll
    for (int dt = 0; dt < 8; dt++) {
        int dcol = dt * 8 + 2 * t;
        *(unsigned*)(r0p + dcol) = h2f(Oa[dt][0] * li0, Oa[dt][1] * li0);
        *(unsigned*)(r1p + dcol) = h2f(Oa[dt][2] * li1, Oa[dt][3] * li1);
    }
}

// ============================================================================
// fp16 final GEMM: y = silu(BN(W_pr @ (att+pp))), f32 out [b][c][n]
// ============================================================================
__global__ __launch_bounds__(256, 2)
void gemm_add_h(const __half* __restrict__ Wt,
                const __half* __restrict__ attT,
                const __half* __restrict__ ppT,
                const float* __restrict__ gg, const float* __restrict__ bb,
                const float* __restrict__ rm, const float* __restrict__ rv,
                float* __restrict__ Y)
{
    __shared__ unsigned Ws[128 * 20];
    __shared__ unsigned Xs[128 * 20];

    const int n0 = blockIdx.x * 128;
    const int m0 = blockIdx.y * 128;
    const int b  = blockIdx.z;
    const __half* Wb = Wt + (size_t)m0 * C_;
    const __half* Ab = attT + ((size_t)b * N_ + n0) * C_;
    const __half* Pb = ppT  + ((size_t)b * N_ + n0) * C_;

    const int tid = threadIdx.x, lane = tid & 31, warp = tid >> 5;
    const int g = lane >> 2, t = lane & 3;
    const int wm = warp >> 1, wn = warp & 1;

    float acc[2][8][4] = {};

    for (int ch = 0; ch < 16; ch++) {
        __syncthreads();
        #pragma unroll
        for (int i = 0; i < 2; i++) {
            int e = tid + 256 * i;
            int r = e >> 2, q = e & 3;
            cpa16(Ws + r * 20 + q * 4, Wb + (size_t)r * C_ + ch * 32 + q * 8);
        }
        cpa_commit();
        #pragma unroll
        for (int i = 0; i < 2; i++) {
            int e = tid + 256 * i;
            int r = e >> 2, q = e & 3;
            size_t off = (size_t)r * C_ + ch * 32 + q * 8;
            uint4 a4 = *(const uint4*)(Ab + off);
            uint4 p4 = *(const uint4*)(Pb + off);
            __half2* ah = (__half2*)&a4;
            __half2* ph = (__half2*)&p4;
            uint4 o;
            __half2 s0h = __hadd2(ah[0], ph[0]); o.x = *(unsigned*)&s0h;
            __half2 s1h = __hadd2(ah[1], ph[1]); o.y = *(unsigned*)&s1h;
            __half2 s2h = __hadd2(ah[2], ph[2]); o.z = *(unsigned*)&s2h;
            __half2 s3h = __hadd2(ah[3], ph[3]); o.w = *(unsigned*)&s3h;
            *(uint4*)&Xs[r * 20 + q * 4] = o;
        }
        cpa_wait0();
        __syncthreads();
        #pragma unroll
        for (int ks = 0; ks < 2; ks++) {
            const int base = 8 * ks + t;
            unsigned a[2][4];
            #pragma unroll
            for (int mt = 0; mt < 2; mt++) {
                int R0 = wm * 32 + mt * 16 + g;
                a[mt][0] = Ws[R0 * 20 + base];
                a[mt][1] = Ws[(R0 + 8) * 20 + base];
                a[mt][2] = Ws[R0 * 20 + base + 4];
                a[mt][3] = Ws[(R0 + 8) * 20 + base + 4];
            }
            #pragma unroll
            for (int nt = 0; nt < 8; nt++) {
                int n = wn * 64 + nt * 8 + g;
                unsigned bf[2] = { Xs[n * 20 + base], Xs[n * 20 + base + 4] };
                mma16(acc[0][nt], a[0], bf);
                mma16(acc[1][nt], a[1], bf);
            }
        }
    }

    #pragma unroll
    for (int mt = 0; mt < 2; mt++) {
        int m  = m0 + wm * 32 + mt * 16 + g;
        int m1 = m + 8;
        float sc0 = gg[m]  * rsqrtf(rv[m]  + EPS_), sh0 = bb[m]  - rm[m]  * sc0;
        float sc1 = gg[m1] * rsqrtf(rv[m1] + EPS_), sh1 = bb[m1] - rm[m1] * sc1;
        #pragma unroll
        for (int nt = 0; nt < 8; nt++) {
            int n = n0 + wn * 64 + nt * 8 + 2 * t;
            float* c = acc[mt][nt];
            *(float2*)&Y[((size_t)b * C_ + m)  * N_ + n] =
                make_float2(silu_f(c[0] * sc0 + sh0), silu_f(c[1] * sc0 + sh0));
            *(float2*)&Y[((size_t)b * C_ + m1) * N_ + n] =
                make_float2(silu_f(c[2] * sc1 + sh1), silu_f(c[3] * sc1 + sh1));
        }
    }
}

// ============================================================================
extern "C" void kernel_launch(void* const* d_in, const int* in_sizes, int n_in,
                              void* d_out, int out_size)
{
    const float* x     = (const float*)d_in[0];
    const float* qk_w  = (const float*)d_in[1];
    const float* qk_g  = (const float*)d_in[2];
    const float* qk_b  = (const float*)d_in[3];
    const float* qk_rm = (const float*)d_in[4];
    const float* qk_rv = (const float*)d_in[5];
    const float* v_w   = (const float*)d_in[6];
    const float* v_g   = (const float*)d_in[7];
    const float* v_b   = (const float*)d_in[8];
    const float* v_rm  = (const float*)d_in[9];
    const float* v_rv  = (const float*)d_in[10];
    const float* pe_w  = (const float*)d_in[11];
    const float* pe_g  = (const float*)d_in[12];
    const float* pe_b  = (const float*)d_in[13];
    const float* pe_rm = (const float*)d_in[14];
    const float* pe_rv = (const float*)d_in[15];
    const float* pr_w  = (const float*)d_in[16];
    const float* pr_g  = (const float*)d_in[17];
    const float* pr_b  = (const float*)d_in[18];
    const float* pr_rm = (const float*)d_in[19];
    const float* pr_rv = (const float*)d_in[20];
    float* out = (float*)d_out;

    __half *p_xt, *p_wqk, *p_wv, *p_wpr, *p_wpe, *p_qkT, *p_vh, *p_vT, *p_ppT, *p_attT;
    cudaGetSymbolAddress((void**)&p_xt,   g_xt);
    cudaGetSymbolAddress((void**)&p_wqk,  g_wqkh);
    cudaGetSymbolAddress((void**)&p_wv,   g_wvh);
    cudaGetSymbolAddress((void**)&p_wpr,  g_wprh);
    cudaGetSymbolAddress((void**)&p_wpe,  g_wpeh);
    cudaGetSymbolAddress((void**)&p_qkT,  g_qkT);
    cudaGetSymbolAddress((void**)&p_vh,   g_vh);
    cudaGetSymbolAddress((void**)&p_vT,   g_vT);
    cudaGetSymbolAddress((void**)&p_ppT,  g_ppT);
    cudaGetSymbolAddress((void**)&p_attT, g_attT);

    cudaFuncSetAttribute(gemm_h,
                         cudaFuncAttributeMaxDynamicSharedMemorySize, 2 * GH_STG * 4);
    cudaFuncSetAttribute(conv3_h,
                         cudaFuncAttributeMaxDynamicSharedMemorySize, CV_SMEM);
    cudaFuncSetAttribute(attn_h,
                         cudaFuncAttributeMaxDynamicSharedMemorySize, AT_SMEM);

    dim3 thr(256);

    // 0) prep
    f2h_k<<<(2 * C_ * C_ / 8 + 255) / 256, thr>>>((const float4*)qk_w, (uint4*)p_wqk, 2 * C_ * C_ / 8);
    f2h_k<<<(C_ * C_ / 8 + 255) / 256, thr>>>((const float4*)v_w,  (uint4*)p_wv,  C_ * C_ / 8);
    f2h_k<<<(C_ * C_ / 8 + 255) / 256, thr>>>((const float4*)pr_w, (uint4*)p_wpr, C_ * C_ / 8);
    conv_w_xform_h<<<(9 * 32 * 512 * 16 + 255) / 256, thr>>>(pe_w, p_wpe);
    xpose_h<<<dim3(N_ / 32, C_ / 32, B_), dim3(32, 8)>>>(x, p_xt);

    // 1) qk -> qkT
    gemm_h<<<dim3(N_ / 128, 1024 / 128, B_), thr, 2 * GH_STG * 4>>>(
        p_wqk, p_xt, qk_g, qk_b, qk_rm, qk_rv, p_qkT, (__half*)nullptr, 1024);

    // 2) v -> vT + vh
    gemm_h<<<dim3(N_ / 128, C_ / 128, B_), thr, 2 * GH_STG * 4>>>(
        p_wv, p_xt, v_g, v_b, v_rm, v_rv, p_vT, p_vh, C_);

    // 3) conv3: vT -> ppT
    conv3_h<<<dim3(H_ / 4, C_ / 64, B_), thr, CV_SMEM>>>(
        p_wpe, p_vT, pe_g, pe_b, pe_rm, pe_rv, p_ppT);

    // 4) attention: qkT + vh -> attT
    attn_h<<<dim3(NA_ / 128, NHEAD, B_ * AREA_), thr, AT_SMEM>>>(
        p_qkT, p_vh, p_attT);

    // 5) final: W_pr @ (attT + ppT) -> out (fp32)
    gemm_add_h<<<dim3(N_ / 128, C_ / 128, B_), thr>>>(
        p_wpr, p_attT, p_ppT, pr_g, pr_b, pr_rm, pr_rv, out);
}

// round 11
// speedup vs baseline: 11.4140x; 1.6082x over previous
#include <cuda_runtime.h>
#include <cuda_fp16.h>
#include <math.h>
#include <stdint.h>

#define B_    8
#define C_    512
#define H_    64
#define W_    64
#define N_    4096          // H*W
#define AREA_ 4
#define NHEAD 8
#define HD_   64
#define NA_   1024          // N/AREA
#define EPS_  1e-5f

// ---------------- scratch (device globals; no allocation allowed) ----------
__device__ __half g_xt  [B_ * N_ * C_];        // x^T  [b][n][c]
__device__ __half g_wqkh[2 * C_ * C_];         // weights, half row-major
__device__ __half g_wvh [C_ * C_];
__device__ __half g_wprh[C_ * C_];
__device__ __half g_wpeh[9 * 32 * 512 * 16];   // conv w [tap][ci][o][16]
__device__ __half g_qkT [B_ * N_ * 2 * C_];    // qk act, token-major [b][n][2C]
__device__ __half g_vh  [B_ * C_ * N_];        // v act [b][c][n]
__device__ __half g_vT  [B_ * N_ * C_];        // v act transposed [b][n][c]
__device__ __half g_ppT [B_ * N_ * C_];        // conv3 out, token-major
__device__ __half g_attT[B_ * N_ * C_];        // attention out, token-major

__device__ __forceinline__ float silu_f(float y) {
    return y / (1.0f + __expf(-y));
}
__device__ __forceinline__ unsigned h2f(float a, float b) {
    __half2 h = __floats2half2_rn(a, b);
    return *reinterpret_cast<unsigned*>(&h);
}
// D += A*B, m16n8k16 f16 in / f32 accum, row.col
__device__ __forceinline__ void mma16(float* c, const unsigned* a, const unsigned* b) {
    asm volatile(
      "mma.sync.aligned.m16n8k16.row.col.f32.f16.f16.f32 "
      "{%0,%1,%2,%3},{%4,%5,%6,%7},{%8,%9},{%0,%1,%2,%3};"
      : "+f"(c[0]), "+f"(c[1]), "+f"(c[2]), "+f"(c[3])
      : "r"(a[0]), "r"(a[1]), "r"(a[2]), "r"(a[3]), "r"(b[0]), "r"(b[1]));
}
// 4x 8x8 b16 matrices in one instruction
__device__ __forceinline__ void ldsm4(unsigned* r, uint32_t addr) {
    asm volatile("ldmatrix.sync.aligned.m8n8.x4.shared.b16 {%0,%1,%2,%3}, [%4];"
        : "=r"(r[0]), "=r"(r[1]), "=r"(r[2]), "=r"(r[3]) : "r"(addr));
}
__device__ __forceinline__ void cpa16(void* dst, const void* src) {
    unsigned d = (unsigned)__cvta_generic_to_shared(dst);
    asm volatile("cp.async.cg.shared.global [%0], [%1], 16;" :: "r"(d), "l"(src));
}
__device__ __forceinline__ void cpa16z(void* dst, const void* src, unsigned sz) {
    unsigned d = (unsigned)__cvta_generic_to_shared(dst);
    asm volatile("cp.async.cg.shared.global [%0], [%1], 16, %2;" :: "r"(d), "l"(src), "r"(sz));
}
__device__ __forceinline__ void cpa_commit() { asm volatile("cp.async.commit_group;"); }
__device__ __forceinline__ void cpa_wait1()  { asm volatile("cp.async.wait_group 1;"); }
__device__ __forceinline__ void cpa_wait0()  { asm volatile("cp.async.wait_group 0;"); }

// ============================================================================
// Prep kernels
// ============================================================================
__global__ void f2h_k(const float4* __restrict__ in, uint4* __restrict__ out, int n8)
{
    int i = blockIdx.x * blockDim.x + threadIdx.x;
    if (i < n8) {
        float4 a = in[2 * i], b = in[2 * i + 1];
        out[i] = make_uint4(h2f(a.x, a.y), h2f(a.z, a.w), h2f(b.x, b.y), h2f(b.z, b.w));
    }
}

// x [b][c][n] fp32 -> g_xt [b][n][c] half
__global__ void xpose_h(const float* __restrict__ x, __half* __restrict__ xt)
{
    __shared__ float ts[32][33];
    const int b  = blockIdx.z;
    const int c0 = blockIdx.y * 32;
    const int nb = blockIdx.x * 32;
    const int tx = threadIdx.x, ty = threadIdx.y;   // 32 x 8
    const float* xb = x + ((size_t)b * C_ + c0) * N_ + nb;
    #pragma unroll
    for (int i = 0; i < 4; i++) {
        int c = ty + i * 8;
        ts[c][tx] = xb[(size_t)c * N_ + tx];
    }
    __syncthreads();
    const int e0 = ty * 32 + tx;
    #pragma unroll
    for (int i = 0; i < 2; i++) {
        int idx = i * 256 + e0;
        int n = idx >> 4, w = idx & 15;
        unsigned word = h2f(ts[2 * w][n], ts[2 * w + 1][n]);
        ((unsigned*)(xt + ((size_t)b * N_ + nb + n) * C_ + c0))[w] = word;
    }
}

// pe_w [O][I][3][3] fp32 -> g_wpeh [tap][ci][o][16] half
__global__ void conv_w_xform_h(const float* __restrict__ pe_w, __half* __restrict__ wp)
{
    int idx = blockIdx.x * 256 + threadIdx.x;
    if (idx >= 9 * 32 * 512 * 16) return;
    int cl  = idx & 15;
    int o   = (idx >> 4) & 511;
    int ci  = (idx >> 13) & 31;
    int tap = idx >> 18;
    wp[idx] = __float2half_rn(pe_w[((size_t)o * C_ + ci * 16 + cl) * 9 + tap]);
}

// ============================================================================
// fp16 GEMM + BN + SiLU, ldmatrix fragments.
// Tile 128x128, 8 warps (4m x 2n), K-chunk 32, 2-stage cp.async.
// ============================================================================
#define GH_STG 5120   // words/stage: A 128*20 + B 128*20

__global__ __launch_bounds__(256, 2)
void gemm_h(const __half* __restrict__ Wt,
            const __half* __restrict__ Xt,
            const float* __restrict__ gg, const float* __restrict__ bb,
            const float* __restrict__ rm, const float* __restrict__ rv,
            __half* __restrict__ Yt,      // [b][n][M]
            __half* __restrict__ Yc,      // [b][m][N] or null
            int M)
{
    extern __shared__ unsigned sm[];     // 2 * GH_STG words

    const int n0 = blockIdx.x * 128;
    const int m0 = blockIdx.y * 128;
    const int b  = blockIdx.z;
    const __half* Wb = Wt + (size_t)m0 * C_;
    const __half* Xb = Xt + ((size_t)b * N_ + n0) * C_;

    const int tid = threadIdx.x, lane = tid & 31, warp = tid >> 5;
    const int g = lane >> 2, t = lane & 3;
    const int wm = warp >> 1, wn = warp & 1;
    const int mrow = lane & 7, msel = lane >> 3;
    const int mlo = msel & 1, mhi = msel >> 1;
    const uint32_t smb = (unsigned)__cvta_generic_to_shared(sm);

    float acc[2][8][4] = {};

    #define GH_ISSUE(CH, S) do {                                            \
        unsigned* bs = sm + (S) * GH_STG;                                   \
        _Pragma("unroll")                                                   \
        for (int i_ = 0; i_ < 4; i_++) {                                    \
            int e = tid + 256 * i_;                                         \
            int op = e >> 9, r = (e >> 2) & 127, q = e & 3;                 \
            const __half* src = (op ? Xb : Wb) + (size_t)r * C_ + (CH) * 32 + q * 8; \
            cpa16(bs + (op ? 2560 : 0) + r * 20 + q * 4, src);              \
        }                                                                   \
        cpa_commit();                                                       \
    } while (0)

    GH_ISSUE(0, 0);
    GH_ISSUE(1, 1);

    for (int ch = 0; ch < 16; ch++) {
        cpa_wait1();
        __syncthreads();
        const uint32_t sb = smb + (unsigned)((ch & 1) * (GH_STG * 4));
        const uint32_t xbse = sb + 2560 * 4;
        #pragma unroll
        for (int ks = 0; ks < 2; ks++) {
            unsigned a[2][4];
            #pragma unroll
            for (int mt = 0; mt < 2; mt++) {
                int row = wm * 32 + mt * 16 + mlo * 8 + mrow;
                ldsm4(a[mt], sb + (unsigned)((row * 20 + ks * 8 + mhi * 4) * 4));
            }
            #pragma unroll
            for (int ntp = 0; ntp < 4; ntp++) {
                unsigned bv[4];
                int row = wn * 64 + ntp * 16 + mhi * 8 + mrow;
                ldsm4(bv, xbse + (unsigned)((row * 20 + ks * 8 + mlo * 4) * 4));
                mma16(acc[0][2 * ntp],     a[0], bv);
                mma16(acc[0][2 * ntp + 1], a[0], bv + 2);
                mma16(acc[1][2 * ntp],     a[1], bv);
                mma16(acc[1][2 * ntp + 1], a[1], bv + 2);
            }
        }
        __syncthreads();
        if (ch + 2 < 16) GH_ISSUE(ch + 2, ch & 1);
        else             cpa_commit();
    }

    __half* hs = (__half*)sm;            // [128 n][136 m]
    #pragma unroll
    for (int mt = 0; mt < 2; mt++) {
        int R0 = wm * 32 + mt * 16 + g;
        int m  = m0 + R0, m1 = m + 8;
        float sc0 = gg[m]  * rsqrtf(rv[m]  + EPS_), sh0 = bb[m]  - rm[m]  * sc0;
        float sc1 = gg[m1] * rsqrtf(rv[m1] + EPS_), sh1 = bb[m1] - rm[m1] * sc1;
        #pragma unroll
        for (int nt = 0; nt < 8; nt++) {
            float* c = acc[mt][nt];
            float v0 = silu_f(c[0] * sc0 + sh0), v1 = silu_f(c[1] * sc0 + sh0);
            float v2 = silu_f(c[2] * sc1 + sh1), v3 = silu_f(c[3] * sc1 + sh1);
            int px0 = wn * 64 + nt * 8 + 2 * t;
            if (Yc) {
                *(unsigned*)(Yc + ((size_t)b * M + m)  * N_ + n0 + px0) = h2f(v0, v1);
                *(unsigned*)(Yc + ((size_t)b * M + m1) * N_ + n0 + px0) = h2f(v2, v3);
            }
            hs[px0 * 136 + R0]           = __float2half_rn(v0);
            hs[(px0 + 1) * 136 + R0]     = __float2half_rn(v1);
            hs[px0 * 136 + R0 + 8]       = __float2half_rn(v2);
            hs[(px0 + 1) * 136 + R0 + 8] = __float2half_rn(v3);
        }
    }
    __syncthreads();
    const unsigned* hw = (const unsigned*)hs;
    #pragma unroll
    for (int i = 0; i < 32; i++) {
        int e = tid + 256 * i;
        int n = e >> 6, w = e & 63;
        ((unsigned*)(Yt + ((size_t)b * N_ + n0 + n) * M + m0))[w] = hw[n * 68 + w];
    }
    #undef GH_ISSUE
}

// ============================================================================
// fp16 3x3 SAME conv + BN + SiLU, ldmatrix fragments.  Output ppT [n][c].
// ============================================================================
#define CV_AW  (9 * 64 * 12)
#define CV_BX  (6 * 66 * 12)
#define CV_SMEM ((CV_AW + CV_BX) * 4)

__global__ __launch_bounds__(256, 2)
void conv3_h(const __half* __restrict__ Wp,
             const __half* __restrict__ vT,
             const float* __restrict__ gg, const float* __restrict__ bb,
             const float* __restrict__ rm, const float* __restrict__ rv,
             __half* __restrict__ ppT)
{
    extern __shared__ unsigned cs[];
    unsigned* Aw = cs;               // [tap*64 + o][12]
    unsigned* Bx = cs + CV_AW;       // [r*66 + p][12]

    const int y0 = blockIdx.x * 4;
    const int m0 = blockIdx.y * 64;
    const int b  = blockIdx.z;
    const __half* vTb = vT + (size_t)b * N_ * C_;

    const int tid = threadIdx.x, lane = tid & 31, warp = tid >> 5;
    const int g = lane >> 2, t = lane & 3;
    const int wm = warp >> 2, wn = warp & 3;   // 2m x 4n
    const int mrow = lane & 7, msel = lane >> 3;
    const int mlo = msel & 1, mhi = msel >> 1;
    const uint32_t awb = (unsigned)__cvta_generic_to_shared(Aw);
    const uint32_t bxb = (unsigned)__cvta_generic_to_shared(Bx);

    float acc[2][8][4] = {};

    for (int ci = 0; ci < 32; ci++) {
        __syncthreads();
        for (int e = tid; e < 1152; e += 256) {
            int tap = e >> 7, r = (e >> 1) & 63, q = e & 1;
            cpa16(Aw + (tap * 64 + r) * 12 + q * 4,
                  Wp + (((size_t)tap * 32 + ci) * 512 + m0 + r) * 16 + q * 8);
        }
        for (int e = tid; e < 792; e += 256) {
            int r = e / 132, rem = e - r * 132;
            int p = rem >> 1, q = rem & 1;
            int gy = y0 - 1 + r, gx = p - 1;
            bool ok = (gy >= 0 && gy < H_ && gx >= 0 && gx < W_);
            const __half* src = vTb + (ok ? ((size_t)(gy * W_ + gx) * C_ + ci * 16 + q * 8) : 0);
            cpa16z(Bx + (r * 66 + p) * 12 + q * 4, src, ok ? 16u : 0u);
        }
        cpa_commit();
        cpa_wait0();
        __syncthreads();

        for (int tap = 0; tap < 9; tap++) {
            const int dy = tap / 3, dx = tap - dy * 3;
            unsigned a[2][4];
            #pragma unroll
            for (int mt = 0; mt < 2; mt++) {
                int row = tap * 64 + wm * 32 + mt * 16 + mlo * 8 + mrow;
                ldsm4(a[mt], awb + (unsigned)((row * 12 + mhi * 4) * 4));
            }
            const int rr = wn + dy;
            #pragma unroll
            for (int ntp = 0; ntp < 4; ntp++) {
                unsigned bv[4];
                int row = rr * 66 + ntp * 16 + mhi * 8 + mrow + dx;
                ldsm4(bv, bxb + (unsigned)((row * 12 + mlo * 4) * 4));
                mma16(acc[0][2 * ntp],     a[0], bv);
                mma16(acc[0][2 * ntp + 1], a[0], bv + 2);
                mma16(acc[1][2 * ntp],     a[1], bv);
                mma16(acc[1][2 * ntp + 1], a[1], bv + 2);
            }
        }
    }

    __syncthreads();
    __half* hs = (__half*)cs;        // [256 px][72 o]
    #pragma unroll
    for (int mt = 0; mt < 2; mt++) {
        int R0 = wm * 32 + mt * 16 + g;
        int m  = m0 + R0, m1 = m + 8;
        float sc0 = gg[m]  * rsqrtf(rv[m]  + EPS_), sh0 = bb[m]  - rm[m]  * sc0;
        float sc1 = gg[m1] * rsqrtf(rv[m1] + EPS_), sh1 = bb[m1] - rm[m1] * sc1;
        #pragma unroll
        for (int nt = 0; nt < 8; nt++) {
            float* c = acc[mt][nt];
            int P0 = wn * 64 + nt * 8 + 2 * t;
            hs[P0 * 72 + R0]           = __float2half_rn(silu_f(c[0] * sc0 + sh0));
            hs[(P0 + 1) * 72 + R0]     = __float2half_rn(silu_f(c[1] * sc0 + sh0));
            hs[P0 * 72 + R0 + 8]       = __float2half_rn(silu_f(c[2] * sc1 + sh1));
            hs[(P0 + 1) * 72 + R0 + 8] = __float2half_rn(silu_f(c[3] * sc1 + sh1));
        }
    }
    __syncthreads();
    const unsigned* hw = (const unsigned*)hs;
    #pragma unroll
    for (int i = 0; i < 32; i++) {
        int e = tid + 256 * i;
        int P = e >> 5, w = e & 31;
        ((unsigned*)(ppT + ((size_t)b * N_ + y0 * W_ + P) * C_ + m0))[w] = hw[P * 36 + w];
    }
}

// ============================================================================
// fp16 area attention (FA2), ldmatrix fragments, zero shuffles.
// ============================================================================
#define AT_QS (128 * 36)
#define AT_KS (64 * 36)
#define AT_VS (64 * 36)
#define AT_SMEM ((AT_QS + AT_KS + AT_VS) * 4)

__global__ __launch_bounds__(256, 2)
void attn_h(const __half* __restrict__ qkT,
            const __half* __restrict__ vh,
            __half* __restrict__ attT)
{
    extern __shared__ unsigned as_[];
    unsigned* Qs = as_;                   // [q][36]
    unsigned* Ks = as_ + AT_QS;           // [j][36]
    unsigned* Vs = as_ + AT_QS + AT_KS;   // [d][36]

    const int q0   = blockIdx.x * 128;
    const int head = blockIdx.y;
    const int ba   = blockIdx.z;
    const int b    = ba >> 2;
    const int area = ba & 3;
    const int atok = area * NA_;

    const __half* Qb = qkT + ((size_t)b * N_ + atok + q0) * (2 * C_) + head * HD_;
    const __half* Kb = qkT + ((size_t)b * N_ + atok) * (2 * C_) + C_ + head * HD_;
    const __half* Vb = vh  + ((size_t)b * C_ + head * HD_) * N_ + atok;
    __half*       Ob = attT + ((size_t)b * N_ + atok + q0) * C_ + head * HD_;

    const int tid = threadIdx.x, lane = tid & 31, warp = tid >> 5;
    const int g = lane >> 2, t = lane & 3;
    const int wq = warp * 16;
    const int mrow = lane & 7, msel = lane >> 3;
    const int mlo = msel & 1, mhi = msel >> 1;
    const uint32_t ksb = (unsigned)__cvta_generic_to_shared(Ks);
    const uint32_t vsb = (unsigned)__cvta_generic_to_shared(Vs);

    // stage Q once: 128 rows x 32 words (full rows)
    #pragma unroll
    for (int i = 0; i < 4; i++) {
        int e = tid + 256 * i;
        int r = e >> 3, q = e & 7;
        cpa16(Qs + r * 36 + q * 4, Qb + (size_t)r * (2 * C_) + q * 8);
    }
    cpa_commit();

    float mr0 = -1e30f, mr1 = -1e30f, lr0 = 0.0f, lr1 = 0.0f;
    float Oa[8][4] = {};
    unsigned qf[4][4];
    bool qf_done = false;

    for (int j0 = 0; j0 < NA_; j0 += 64) {
        __syncthreads();
        #pragma unroll
        for (int i = 0; i < 2; i++) {
            int e = tid + 256 * i;
            int r = e >> 3, q = e & 7;
            cpa16(Ks + r * 36 + q * 4, Kb + (size_t)(j0 + r) * (2 * C_) + q * 8);
        }
        #pragma unroll
        for (int i = 0; i < 2; i++) {
            int e = tid + 256 * i;
            int r = e >> 3, q = e & 7;
            cpa16(Vs + r * 36 + q * 4, Vb + (size_t)r * N_ + j0 + q * 8);
        }
        cpa_commit();
        cpa_wait0();
        __syncthreads();

        if (!qf_done) {
            qf_done = true;
            #pragma unroll
            for (int s = 0; s < 4; s++) {
                qf[s][0] = Qs[(wq + g) * 36 + 8 * s + t];
                qf[s][1] = Qs[(wq + 8 + g) * 36 + 8 * s + t];
                qf[s][2] = Qs[(wq + g) * 36 + 8 * s + t + 4];
                qf[s][3] = Qs[(wq + 8 + g) * 36 + 8 * s + t + 4];
            }
        }

        // ---- S = Q K^T ----
        float S[8][4] = {};
        #pragma unroll
        for (int s = 0; s < 4; s++) {
            #pragma unroll
            for (int ntp = 0; ntp < 4; ntp++) {
                unsigned bv[4];
                int row = ntp * 16 + mhi * 8 + mrow;
                ldsm4(bv, ksb + (unsigned)((row * 36 + s * 8 + mlo * 4) * 4));
                mma16(S[2 * ntp],     qf[s], bv);
                mma16(S[2 * ntp + 1], qf[s], bv + 2);
            }
        }

        float mx0 = -1e30f, mx1 = -1e30f;
        #pragma unroll
        for (int nt = 0; nt < 8; nt++) {
            S[nt][0] *= 0.125f; S[nt][1] *= 0.125f;
            S[nt][2] *= 0.125f; S[nt][3] *= 0.125f;
            mx0 = fmaxf(mx0, fmaxf(S[nt][0], S[nt][1]));
            mx1 = fmaxf(mx1, fmaxf(S[nt][2], S[nt][3]));
        }
        mx0 = fmaxf(mx0, __shfl_xor_sync(0xffffffffu, mx0, 1));
        mx0 = fmaxf(mx0, __shfl_xor_sync(0xffffffffu, mx0, 2));
        mx1 = fmaxf(mx1, __shfl_xor_sync(0xffffffffu, mx1, 1));
        mx1 = fmaxf(mx1, __shfl_xor_sync(0xffffffffu, mx1, 2));
        float mn0 = fmaxf(mr0, mx0), mn1 = fmaxf(mr1, mx1);
        float al0 = __expf(mr0 - mn0), al1 = __expf(mr1 - mn1);
        mr0 = mn0; mr1 = mn1;
        float s0 = 0.0f, s1 = 0.0f;
        #pragma unroll
        for (int nt = 0; nt < 8; nt++) {
            S[nt][0] = __expf(S[nt][0] - mn0);
            S[nt][1] = __expf(S[nt][1] - mn0);
            S[nt][2] = __expf(S[nt][2] - mn1);
            S[nt][3] = __expf(S[nt][3] - mn1);
            s0 += S[nt][0] + S[nt][1];
            s1 += S[nt][2] + S[nt][3];
        }
        s0 += __shfl_xor_sync(0xffffffffu, s0, 1);
        s0 += __shfl_xor_sync(0xffffffffu, s0, 2);
        s1 += __shfl_xor_sync(0xffffffffu, s1, 1);
        s1 += __shfl_xor_sync(0xffffffffu, s1, 2);
        lr0 = lr0 * al0 + s0; lr1 = lr1 * al1 + s1;

        #pragma unroll
        for (int dt = 0; dt < 8; dt++) {
            Oa[dt][0] *= al0; Oa[dt][1] *= al0;
            Oa[dt][2] *= al1; Oa[dt][3] *= al1;
        }

        // ---- O += P V ----
        #pragma unroll
        for (int s = 0; s < 4; s++) {
            unsigned pa[4] = {
                h2f(S[2 * s][0],     S[2 * s][1]),
                h2f(S[2 * s][2],     S[2 * s][3]),
                h2f(S[2 * s + 1][0], S[2 * s + 1][1]),
                h2f(S[2 * s + 1][2], S[2 * s + 1][3])
            };
            #pragma unroll
            for (int dtp = 0; dtp < 4; dtp++) {
                unsigned bv[4];
                int row = dtp * 16 + mhi * 8 + mrow;
                ldsm4(bv, vsb + (unsigned)((row * 36 + s * 8 + mlo * 4) * 4));
                mma16(Oa[2 * dtp],     pa, bv);
                mma16(Oa[2 * dtp + 1], pa, bv + 2);
            }
        }
    }

    float li0 = 1.0f / lr0, li1 = 1.0f / lr1;
    __half* r0p = Ob + (size_t)(wq + g) * C_;
    __half* r1p = Ob + (size_t)(wq + 8 + g) * C_;
    #pragma unroll
    for (int dt = 0; dt < 8; dt++) {
        int dcol = dt * 8 + 2 * t;
        *(unsigned*)(r0p + dcol) = h2f(Oa[dt][0] * li0, Oa[dt][1] * li0);
        *(unsigned*)(r1p + dcol) = h2f(Oa[dt][2] * li1, Oa[dt][3] * li1);
    }
}

// ============================================================================
// fp16 final GEMM: y = silu(BN(W_pr @ (att+pp))), f32 out [b][c][n]
// ============================================================================
__global__ __launch_bounds__(256, 2)
void gemm_add_h(const __half* __restrict__ Wt,
                const __half* __restrict__ attT,
                const __half* __restrict__ ppT,
                const float* __restrict__ gg, const float* __restrict__ bb,
                const float* __restrict__ rm, const float* __restrict__ rv,
                float* __restrict__ Y)
{
    __shared__ unsigned Ws[128 * 20];
    __shared__ unsigned Xs[128 * 20];

    const int n0 = blockIdx.x * 128;
    const int m0 = blockIdx.y * 128;
    const int b  = blockIdx.z;
    const __half* Wb = Wt + (size_t)m0 * C_;
    const __half* Ab = attT + ((size_t)b * N_ + n0) * C_;
    const __half* Pb = ppT  + ((size_t)b * N_ + n0) * C_;

    const int tid = threadIdx.x, lane = tid & 31, warp = tid >> 5;
    const int g = lane >> 2, t = lane & 3;
    const int wm = warp >> 1, wn = warp & 1;
    const int mrow = lane & 7, msel = lane >> 3;
    const int mlo = msel & 1, mhi = msel >> 1;
    const uint32_t wsb = (unsigned)__cvta_generic_to_shared(Ws);
    const uint32_t xsb = (unsigned)__cvta_generic_to_shared(Xs);

    float acc[2][8][4] = {};

    for (int ch = 0; ch < 16; ch++) {
        __syncthreads();
        #pragma unroll
        for (int i = 0; i < 2; i++) {
            int e = tid + 256 * i;
            int r = e >> 2, q = e & 3;
            cpa16(Ws + r * 20 + q * 4, Wb + (size_t)r * C_ + ch * 32 + q * 8);
        }
        cpa_commit();
        #pragma unroll
        for (int i = 0; i < 2; i++) {
            int e = tid + 256 * i;
            int r = e >> 2, q = e & 3;
            size_t off = (size_t)r * C_ + ch * 32 + q * 8;
            uint4 a4 = *(const uint4*)(Ab + off);
            uint4 p4 = *(const uint4*)(Pb + off);
            __half2* ah = (__half2*)&a4;
            __half2* ph = (__half2*)&p4;
            uint4 o;
            __half2 s0h = __hadd2(ah[0], ph[0]); o.x = *(unsigned*)&s0h;
            __half2 s1h = __hadd2(ah[1], ph[1]); o.y = *(unsigned*)&s1h;
            __half2 s2h = __hadd2(ah[2], ph[2]); o.z = *(unsigned*)&s2h;
            __half2 s3h = __hadd2(ah[3], ph[3]); o.w = *(unsigned*)&s3h;
            *(uint4*)&Xs[r * 20 + q * 4] = o;
        }
        cpa_wait0();
        __syncthreads();
        #pragma unroll
        for (int ks = 0; ks < 2; ks++) {
            unsigned a[2][4];
            #pragma unroll
            for (int mt = 0; mt < 2; mt++) {
                int row = wm * 32 + mt * 16 + mlo * 8 + mrow;
                ldsm4(a[mt], wsb + (unsigned)((row * 20 + ks * 8 + mhi * 4) * 4));
            }
            #pragma unroll
            for (int ntp = 0; ntp < 4; ntp++) {
                unsigned bv[4];
                int row = wn * 64 + ntp * 16 + mhi * 8 + mrow;
                ldsm4(bv, xsb + (unsigned)((row * 20 + ks * 8 + mlo * 4) * 4));
                mma16(acc[0][2 * ntp],     a[0], bv);
                mma16(acc[0][2 * ntp + 1], a[0], bv + 2);
                mma16(acc[1][2 * ntp],     a[1], bv);
                mma16(acc[1][2 * ntp + 1], a[1], bv + 2);
            }
        }
    }

    #pragma unroll
    for (int mt = 0; mt < 2; mt++) {
        int m  = m0 + wm * 32 + mt * 16 + g;
        int m1 = m + 8;
        float sc0 = gg[m]  * rsqrtf(rv[m]  + EPS_), sh0 = bb[m]  - rm[m]  * sc0;
        float sc1 = gg[m1] * rsqrtf(rv[m1] + EPS_), sh1 = bb[m1] - rm[m1] * sc1;
        #pragma unroll
        for (int nt = 0; nt < 8; nt++) {
            int n = n0 + wn * 64 + nt * 8 + 2 * t;
            float* c = acc[mt][nt];
            *(float2*)&Y[((size_t)b * C_ + m)  * N_ + n] =
                make_float2(silu_f(c[0] * sc0 + sh0), silu_f(c[1] * sc0 + sh0));
            *(float2*)&Y[((size_t)b * C_ + m1) * N_ + n] =
                make_float2(silu_f(c[2] * sc1 + sh1), silu_f(c[3] * sc1 + sh1));
        }
    }
}

// ============================================================================
extern "C" void kernel_launch(void* const* d_in, const int* in_sizes, int n_in,
                              void* d_out, int out_size)
{
    const float* x     = (const float*)d_in[0];
    const float* qk_w  = (const float*)d_in[1];
    const float* qk_g  = (const float*)d_in[2];
    const float* qk_b  = (const float*)d_in[3];
    const float* qk_rm = (const float*)d_in[4];
    const float* qk_rv = (const float*)d_in[5];
    const float* v_w   = (const float*)d_in[6];
    const float* v_g   = (const float*)d_in[7];
    const float* v_b   = (const float*)d_in[8];
    const float* v_rm  = (const float*)d_in[9];
    const float* v_rv  = (const float*)d_in[10];
    const float* pe_w  = (const float*)d_in[11];
    const float* pe_g  = (const float*)d_in[12];
    const float* pe_b  = (const float*)d_in[13];
    const float* pe_rm = (const float*)d_in[14];
    const float* pe_rv = (const float*)d_in[15];
    const float* pr_w  = (const float*)d_in[16];
    const float* pr_g  = (const float*)d_in[17];
    const float* pr_b  = (const float*)d_in[18];
    const float* pr_rm = (const float*)d_in[19];
    const float* pr_rv = (const float*)d_in[20];
    float* out = (float*)d_out;

    __half *p_xt, *p_wqk, *p_wv, *p_wpr, *p_wpe, *p_qkT, *p_vh, *p_vT, *p_ppT, *p_attT;
    cudaGetSymbolAddress((void**)&p_xt,   g_xt);
    cudaGetSymbolAddress((void**)&p_wqk,  g_wqkh);
    cudaGetSymbolAddress((void**)&p_wv,   g_wvh);
    cudaGetSymbolAddress((void**)&p_wpr,  g_wprh);
    cudaGetSymbolAddress((void**)&p_wpe,  g_wpeh);
    cudaGetSymbolAddress((void**)&p_qkT,  g_qkT);
    cudaGetSymbolAddress((void**)&p_vh,   g_vh);
    cudaGetSymbolAddress((void**)&p_vT,   g_vT);
    cudaGetSymbolAddress((void**)&p_ppT,  g_ppT);
    cudaGetSymbolAddress((void**)&p_attT, g_attT);

    cudaFuncSetAttribute(gemm_h,
                         cudaFuncAttributeMaxDynamicSharedMemorySize, 2 * GH_STG * 4);
    cudaFuncSetAttribute(conv3_h,
                         cudaFuncAttributeMaxDynamicSharedMemorySize, CV_SMEM);
    cudaFuncSetAttribute(attn_h,
                         cudaFuncAttributeMaxDynamicSharedMemorySize, AT_SMEM);

    dim3 thr(256);

    // 0) prep
    f2h_k<<<(2 * C_ * C_ / 8 + 255) / 256, thr>>>((const float4*)qk_w, (uint4*)p_wqk, 2 * C_ * C_ / 8);
    f2h_k<<<(C_ * C_ / 8 + 255) / 256, thr>>>((const float4*)v_w,  (uint4*)p_wv,  C_ * C_ / 8);
    f2h_k<<<(C_ * C_ / 8 + 255) / 256, thr>>>((const float4*)pr_w, (uint4*)p_wpr, C_ * C_ / 8);
    conv_w_xform_h<<<(9 * 32 * 512 * 16 + 255) / 256, thr>>>(pe_w, p_wpe);
    xpose_h<<<dim3(N_ / 32, C_ / 32, B_), dim3(32, 8)>>>(x, p_xt);

    // 1) qk -> qkT
    gemm_h<<<dim3(N_ / 128, 1024 / 128, B_), thr, 2 * GH_STG * 4>>>(
        p_wqk, p_xt, qk_g, qk_b, qk_rm, qk_rv, p_qkT, (__half*)nullptr, 1024);

    // 2) v -> vT + vh
    gemm_h<<<dim3(N_ / 128, C_ / 128, B_), thr, 2 * GH_STG * 4>>>(
        p_wv, p_xt, v_g, v_b, v_rm, v_rv, p_vT, p_vh, C_);

    // 3) conv3: vT -> ppT
    conv3_h<<<dim3(H_ / 4, C_ / 64, B_), thr, CV_SMEM>>>(
        p_wpe, p_vT, pe_g, pe_b, pe_rm, pe_rv, p_ppT);

    // 4) attention: qkT + vh -> attT
    attn_h<<<dim3(NA_ / 128, NHEAD, B_ * AREA_), thr, AT_SMEM>>>(
        p_qkT, p_vh, p_attT);

    // 5) final: W_pr @ (attT + ppT) -> out (fp32)
    gemm_add_h<<<dim3(N_ / 128, C_ / 128, B_), thr>>>(
        p_wpr, p_attT, p_ppT, pr_g, pr_b, pr_rm, pr_rv, out);
}

// round 12
// speedup vs baseline: 11.8870x; 1.0414x over previous
#include <cuda_runtime.h>
#include <cuda_fp16.h>
#include <math.h>
#include <stdint.h>

#define B_    8
#define C_    512
#define H_    64
#define W_    64
#define N_    4096          // H*W
#define AREA_ 4
#define NHEAD 8
#define HD_   64
#define NA_   1024          // N/AREA
#define EPS_  1e-5f

// ---------------- scratch (device globals; no allocation allowed) ----------
__device__ __half g_xt  [B_ * N_ * C_];        // x^T  [b][n][c]
__device__ __half g_wqkh[2 * C_ * C_];         // weights, half row-major
__device__ __half g_wvh [C_ * C_];
__device__ __half g_wprh[C_ * C_];
__device__ __half g_wpeh[9 * 32 * 512 * 16];   // conv w [tap][ci][o][16]
__device__ __half g_qkT [B_ * N_ * 2 * C_];    // qk act, token-major [b][n][2C]
__device__ __half g_vh  [B_ * C_ * N_];        // v act [b][c][n]
__device__ __half g_vT  [B_ * N_ * C_];        // v act transposed [b][n][c]
__device__ __half g_ppT [B_ * N_ * C_];        // conv3 out, token-major
__device__ __half g_attT[B_ * N_ * C_];        // attention out, token-major

__device__ __forceinline__ float silu_f(float y) {
    return y / (1.0f + __expf(-y));
}
__device__ __forceinline__ unsigned h2f(float a, float b) {
    __half2 h = __floats2half2_rn(a, b);
    return *reinterpret_cast<unsigned*>(&h);
}
// D += A*B, m16n8k16 f16 in / f32 accum, row.col
__device__ __forceinline__ void mma16(float* c, const unsigned* a, const unsigned* b) {
    asm volatile(
      "mma.sync.aligned.m16n8k16.row.col.f32.f16.f16.f32 "
      "{%0,%1,%2,%3},{%4,%5,%6,%7},{%8,%9},{%0,%1,%2,%3};"
      : "+f"(c[0]), "+f"(c[1]), "+f"(c[2]), "+f"(c[3])
      : "r"(a[0]), "r"(a[1]), "r"(a[2]), "r"(a[3]), "r"(b[0]), "r"(b[1]));
}
// 4x 8x8 b16 matrices in one instruction
__device__ __forceinline__ void ldsm4(unsigned* r, uint32_t addr) {
    asm volatile("ldmatrix.sync.aligned.m8n8.x4.shared.b16 {%0,%1,%2,%3}, [%4];"
        : "=r"(r[0]), "=r"(r[1]), "=r"(r[2]), "=r"(r[3]) : "r"(addr));
}
__device__ __forceinline__ void cpa16(void* dst, const void* src) {
    unsigned d = (unsigned)__cvta_generic_to_shared(dst);
    asm volatile("cp.async.cg.shared.global [%0], [%1], 16;" :: "r"(d), "l"(src));
}
__device__ __forceinline__ void cpa16z(void* dst, const void* src, unsigned sz) {
    unsigned d = (unsigned)__cvta_generic_to_shared(dst);
    asm volatile("cp.async.cg.shared.global [%0], [%1], 16, %2;" :: "r"(d), "l"(src), "r"(sz));
}
__device__ __forceinline__ void cpa_commit() { asm volatile("cp.async.commit_group;"); }
__device__ __forceinline__ void cpa_wait1()  { asm volatile("cp.async.wait_group 1;"); }
__device__ __forceinline__ void cpa_wait0()  { asm volatile("cp.async.wait_group 0;"); }

// ============================================================================
// Prep kernels
// ============================================================================
__global__ void f2h_k(const float4* __restrict__ in, uint4* __restrict__ out, int n8)
{
    int i = blockIdx.x * blockDim.x + threadIdx.x;
    if (i < n8) {
        float4 a = in[2 * i], b = in[2 * i + 1];
        out[i] = make_uint4(h2f(a.x, a.y), h2f(a.z, a.w), h2f(b.x, b.y), h2f(b.z, b.w));
    }
}

// x [b][c][n] fp32 -> g_xt [b][n][c] half
__global__ void xpose_h(const float* __restrict__ x, __half* __restrict__ xt)
{
    __shared__ float ts[32][33];
    const int b  = blockIdx.z;
    const int c0 = blockIdx.y * 32;
    const int nb = blockIdx.x * 32;
    const int tx = threadIdx.x, ty = threadIdx.y;   // 32 x 8
    const float* xb = x + ((size_t)b * C_ + c0) * N_ + nb;
    #pragma unroll
    for (int i = 0; i < 4; i++) {
        int c = ty + i * 8;
        ts[c][tx] = xb[(size_t)c * N_ + tx];
    }
    __syncthreads();
    const int e0 = ty * 32 + tx;
    #pragma unroll
    for (int i = 0; i < 2; i++) {
        int idx = i * 256 + e0;
        int n = idx >> 4, w = idx & 15;
        unsigned word = h2f(ts[2 * w][n], ts[2 * w + 1][n]);
        ((unsigned*)(xt + ((size_t)b * N_ + nb + n) * C_ + c0))[w] = word;
    }
}

// pe_w [O][I][3][3] fp32 -> g_wpeh [tap][ci][o][16] half
__global__ void conv_w_xform_h(const float* __restrict__ pe_w, __half* __restrict__ wp)
{
    int idx = blockIdx.x * 256 + threadIdx.x;
    if (idx >= 9 * 32 * 512 * 16) return;
    int cl  = idx & 15;
    int o   = (idx >> 4) & 511;
    int ci  = (idx >> 13) & 31;
    int tap = idx >> 18;
    wp[idx] = __float2half_rn(pe_w[((size_t)o * C_ + ci * 16 + cl) * 9 + tap]);
}

// ============================================================================
// fp16 GEMM + BN + SiLU, ldmatrix fragments.  (unchanged from round 11)
// ============================================================================
#define GH_STG 5120   // words/stage: A 128*20 + B 128*20

__global__ __launch_bounds__(256, 2)
void gemm_h(const __half* __restrict__ Wt,
            const __half* __restrict__ Xt,
            const float* __restrict__ gg, const float* __restrict__ bb,
            const float* __restrict__ rm, const float* __restrict__ rv,
            __half* __restrict__ Yt,      // [b][n][M]
            __half* __restrict__ Yc,      // [b][m][N] or null
            int M)
{
    extern __shared__ unsigned sm[];     // 2 * GH_STG words

    const int n0 = blockIdx.x * 128;
    const int m0 = blockIdx.y * 128;
    const int b  = blockIdx.z;
    const __half* Wb = Wt + (size_t)m0 * C_;
    const __half* Xb = Xt + ((size_t)b * N_ + n0) * C_;

    const int tid = threadIdx.x, lane = tid & 31, warp = tid >> 5;
    const int g = lane >> 2, t = lane & 3;
    const int wm = warp >> 1, wn = warp & 1;
    const int mrow = lane & 7, msel = lane >> 3;
    const int mlo = msel & 1, mhi = msel >> 1;
    const uint32_t smb = (unsigned)__cvta_generic_to_shared(sm);

    float acc[2][8][4] = {};

    #define GH_ISSUE(CH, S) do {                                            \
        unsigned* bs = sm + (S) * GH_STG;                                   \
        _Pragma("unroll")                                                   \
        for (int i_ = 0; i_ < 4; i_++) {                                    \
            int e = tid + 256 * i_;                                         \
            int op = e >> 9, r = (e >> 2) & 127, q = e & 3;                 \
            const __half* src = (op ? Xb : Wb) + (size_t)r * C_ + (CH) * 32 + q * 8; \
            cpa16(bs + (op ? 2560 : 0) + r * 20 + q * 4, src);              \
        }                                                                   \
        cpa_commit();                                                       \
    } while (0)

    GH_ISSUE(0, 0);
    GH_ISSUE(1, 1);

    for (int ch = 0; ch < 16; ch++) {
        cpa_wait1();
        __syncthreads();
        const uint32_t sb = smb + (unsigned)((ch & 1) * (GH_STG * 4));
        const uint32_t xbse = sb + 2560 * 4;
        #pragma unroll
        for (int ks = 0; ks < 2; ks++) {
            unsigned a[2][4];
            #pragma unroll
            for (int mt = 0; mt < 2; mt++) {
                int row = wm * 32 + mt * 16 + mlo * 8 + mrow;
                ldsm4(a[mt], sb + (unsigned)((row * 20 + ks * 8 + mhi * 4) * 4));
            }
            #pragma unroll
            for (int ntp = 0; ntp < 4; ntp++) {
                unsigned bv[4];
                int row = wn * 64 + ntp * 16 + mhi * 8 + mrow;
                ldsm4(bv, xbse + (unsigned)((row * 20 + ks * 8 + mlo * 4) * 4));
                mma16(acc[0][2 * ntp],     a[0], bv);
                mma16(acc[0][2 * ntp + 1], a[0], bv + 2);
                mma16(acc[1][2 * ntp],     a[1], bv);
                mma16(acc[1][2 * ntp + 1], a[1], bv + 2);
            }
        }
        __syncthreads();
        if (ch + 2 < 16) GH_ISSUE(ch + 2, ch & 1);
        else             cpa_commit();
    }

    __half* hs = (__half*)sm;            // [128 n][136 m]
    #pragma unroll
    for (int mt = 0; mt < 2; mt++) {
        int R0 = wm * 32 + mt * 16 + g;
        int m  = m0 + R0, m1 = m + 8;
        float sc0 = gg[m]  * rsqrtf(rv[m]  + EPS_), sh0 = bb[m]  - rm[m]  * sc0;
        float sc1 = gg[m1] * rsqrtf(rv[m1] + EPS_), sh1 = bb[m1] - rm[m1] * sc1;
        #pragma unroll
        for (int nt = 0; nt < 8; nt++) {
            float* c = acc[mt][nt];
            float v0 = silu_f(c[0] * sc0 + sh0), v1 = silu_f(c[1] * sc0 + sh0);
            float v2 = silu_f(c[2] * sc1 + sh1), v3 = silu_f(c[3] * sc1 + sh1);
            int px0 = wn * 64 + nt * 8 + 2 * t;
            if (Yc) {
                *(unsigned*)(Yc + ((size_t)b * M + m)  * N_ + n0 + px0) = h2f(v0, v1);
                *(unsigned*)(Yc + ((size_t)b * M + m1) * N_ + n0 + px0) = h2f(v2, v3);
            }
            hs[px0 * 136 + R0]           = __float2half_rn(v0);
            hs[(px0 + 1) * 136 + R0]     = __float2half_rn(v1);
            hs[px0 * 136 + R0 + 8]       = __float2half_rn(v2);
            hs[(px0 + 1) * 136 + R0 + 8] = __float2half_rn(v3);
        }
    }
    __syncthreads();
    const unsigned* hw = (const unsigned*)hs;
    #pragma unroll
    for (int i = 0; i < 32; i++) {
        int e = tid + 256 * i;
        int n = e >> 6, w = e & 63;
        ((unsigned*)(Yt + ((size_t)b * N_ + n0 + n) * M + m0))[w] = hw[n * 68 + w];
    }
    #undef GH_ISSUE
}

// ============================================================================
// fp16 3x3 SAME conv + BN + SiLU, ldmatrix + 2-stage cp.async ring.
// ============================================================================
#define CV_AW  (9 * 64 * 12)
#define CV_BX  (6 * 66 * 12)
#define CV_STG (CV_AW + CV_BX)          // 11664 words per stage
#define CV_SMEM (2 * CV_STG * 4)        // 93312 B

__global__ __launch_bounds__(256, 2)
void conv3_h(const __half* __restrict__ Wp,
             const __half* __restrict__ vT,
             const float* __restrict__ gg, const float* __restrict__ bb,
             const float* __restrict__ rm, const float* __restrict__ rv,
             __half* __restrict__ ppT)
{
    extern __shared__ unsigned cs[];    // 2 stages: [Aw | Bx]

    const int y0 = blockIdx.x * 4;
    const int m0 = blockIdx.y * 64;
    const int b  = blockIdx.z;
    const __half* vTb = vT + (size_t)b * N_ * C_;

    const int tid = threadIdx.x, lane = tid & 31, warp = tid >> 5;
    const int g = lane >> 2, t = lane & 3;
    const int wm = warp >> 2, wn = warp & 3;   // 2m x 4n
    const int mrow = lane & 7, msel = lane >> 3;
    const int mlo = msel & 1, mhi = msel >> 1;
    const uint32_t csb = (unsigned)__cvta_generic_to_shared(cs);

    float acc[2][8][4] = {};

    #define CV_ISSUE(CI, S) do {                                               \
        unsigned* Aw_ = cs + (S) * CV_STG;                                     \
        unsigned* Bx_ = Aw_ + CV_AW;                                           \
        for (int e = tid; e < 1152; e += 256) {                                \
            int tap_ = e >> 7, r_ = (e >> 1) & 63, q_ = e & 1;                 \
            cpa16(Aw_ + (tap_ * 64 + r_) * 12 + q_ * 4,                        \
                  Wp + (((size_t)tap_ * 32 + (CI)) * 512 + m0 + r_) * 16 + q_ * 8); \
        }                                                                      \
        for (int e = tid; e < 792; e += 256) {                                 \
            int r_ = e / 132, rem_ = e - r_ * 132;                             \
            int p_ = rem_ >> 1, q_ = rem_ & 1;                                 \
            int gy_ = y0 - 1 + r_, gx_ = p_ - 1;                               \
            bool ok_ = (gy_ >= 0 && gy_ < H_ && gx_ >= 0 && gx_ < W_);         \
            const __half* src_ = vTb + (ok_ ? ((size_t)(gy_ * W_ + gx_) * C_ + (CI) * 16 + q_ * 8) : 0); \
            cpa16z(Bx_ + (r_ * 66 + p_) * 12 + q_ * 4, src_, ok_ ? 16u : 0u);  \
        }                                                                      \
        cpa_commit();                                                          \
    } while (0)

    CV_ISSUE(0, 0);
    CV_ISSUE(1, 1);

    for (int ci = 0; ci < 32; ci++) {
        cpa_wait1();
        __syncthreads();
        const uint32_t awb = csb + (unsigned)((ci & 1) * (CV_STG * 4));
        const uint32_t bxb = awb + CV_AW * 4;

        for (int tap = 0; tap < 9; tap++) {
            const int dy = tap / 3, dx = tap - dy * 3;
            unsigned a[2][4];
            #pragma unroll
            for (int mt = 0; mt < 2; mt++) {
                int row = tap * 64 + wm * 32 + mt * 16 + mlo * 8 + mrow;
                ldsm4(a[mt], awb + (unsigned)((row * 12 + mhi * 4) * 4));
            }
            const int rr = wn + dy;
            #pragma unroll
            for (int ntp = 0; ntp < 4; ntp++) {
                unsigned bv[4];
                int row = rr * 66 + ntp * 16 + mhi * 8 + mrow + dx;
                ldsm4(bv, bxb + (unsigned)((row * 12 + mlo * 4) * 4));
                mma16(acc[0][2 * ntp],     a[0], bv);
                mma16(acc[0][2 * ntp + 1], a[0], bv + 2);
                mma16(acc[1][2 * ntp],     a[1], bv);
                mma16(acc[1][2 * ntp + 1], a[1], bv + 2);
            }
        }
        __syncthreads();
        if (ci + 2 < 32) CV_ISSUE(ci + 2, ci & 1);
        else             cpa_commit();
    }
    #undef CV_ISSUE

    __syncthreads();
    __half* hs = (__half*)cs;        // [256 px][72 o]
    #pragma unroll
    for (int mt = 0; mt < 2; mt++) {
        int R0 = wm * 32 + mt * 16 + g;
        int m  = m0 + R0, m1 = m + 8;
        float sc0 = gg[m]  * rsqrtf(rv[m]  + EPS_), sh0 = bb[m]  - rm[m]  * sc0;
        float sc1 = gg[m1] * rsqrtf(rv[m1] + EPS_), sh1 = bb[m1] - rm[m1] * sc1;
        #pragma unroll
        for (int nt = 0; nt < 8; nt++) {
            float* c = acc[mt][nt];
            int P0 = wn * 64 + nt * 8 + 2 * t;
            hs[P0 * 72 + R0]           = __float2half_rn(silu_f(c[0] * sc0 + sh0));
            hs[(P0 + 1) * 72 + R0]     = __float2half_rn(silu_f(c[1] * sc0 + sh0));
            hs[P0 * 72 + R0 + 8]       = __float2half_rn(silu_f(c[2] * sc1 + sh1));
            hs[(P0 + 1) * 72 + R0 + 8] = __float2half_rn(silu_f(c[3] * sc1 + sh1));
        }
    }
    __syncthreads();
    const unsigned* hw = (const unsigned*)hs;
    #pragma unroll
    for (int i = 0; i < 32; i++) {
        int e = tid + 256 * i;
        int P = e >> 5, w = e & 31;
        ((unsigned*)(ppT + ((size_t)b * N_ + y0 * W_ + P) * C_ + m0))[w] = hw[P * 36 + w];
    }
}

// ============================================================================
// fp16 area attention (FA2), ldmatrix + 2-stage KV ring, zero shuffles.
// ============================================================================
#define AT_QS (128 * 36)
#define AT_KS (64 * 36)
#define AT_VS (64 * 36)
#define AT_KV (AT_KS + AT_VS)                 // 4608 words per stage
#define AT_SMEM ((AT_QS + 2 * AT_KV) * 4)     // 55296 B

__global__ __launch_bounds__(256, 2)
void attn_h(const __half* __restrict__ qkT,
            const __half* __restrict__ vh,
            __half* __restrict__ attT)
{
    extern __shared__ unsigned as_[];
    unsigned* Qs = as_;                   // [q][36]

    const int q0   = blockIdx.x * 128;
    const int head = blockIdx.y;
    const int ba   = blockIdx.z;
    const int b    = ba >> 2;
    const int area = ba & 3;
    const int atok = area * NA_;

    const __half* Qb = qkT + ((size_t)b * N_ + atok + q0) * (2 * C_) + head * HD_;
    const __half* Kb = qkT + ((size_t)b * N_ + atok) * (2 * C_) + C_ + head * HD_;
    const __half* Vb = vh  + ((size_t)b * C_ + head * HD_) * N_ + atok;
    __half*       Ob = attT + ((size_t)b * N_ + atok + q0) * C_ + head * HD_;

    const int tid = threadIdx.x, lane = tid & 31, warp = tid >> 5;
    const int g = lane >> 2, t = lane & 3;
    const int wq = warp * 16;
    const int mrow = lane & 7, msel = lane >> 3;
    const int mlo = msel & 1, mhi = msel >> 1;
    const uint32_t asb = (unsigned)__cvta_generic_to_shared(as_);

    // stage Q once: 128 rows x 32 words (its own commit group)
    #pragma unroll
    for (int i = 0; i < 4; i++) {
        int e = tid + 256 * i;
        int r = e >> 3, q = e & 7;
        cpa16(Qs + r * 36 + q * 4, Qb + (size_t)r * (2 * C_) + q * 8);
    }
    cpa_commit();

    #define AT_ISSUE(JT, S) do {                                              \
        unsigned* Ks_ = as_ + AT_QS + (S) * AT_KV;                            \
        unsigned* Vs_ = Ks_ + AT_KS;                                          \
        _Pragma("unroll")                                                     \
        for (int i_ = 0; i_ < 2; i_++) {                                      \
            int e = tid + 256 * i_;                                           \
            int r_ = e >> 3, q_ = e & 7;                                      \
            cpa16(Ks_ + r_ * 36 + q_ * 4,                                     \
                  Kb + (size_t)((JT) * 64 + r_) * (2 * C_) + q_ * 8);         \
        }                                                                     \
        _Pragma("unroll")                                                     \
        for (int i_ = 0; i_ < 2; i_++) {                                      \
            int e = tid + 256 * i_;                                           \
            int r_ = e >> 3, q_ = e & 7;                                      \
            cpa16(Vs_ + r_ * 36 + q_ * 4,                                     \
                  Vb + (size_t)r_ * N_ + (JT) * 64 + q_ * 8);                 \
        }                                                                     \
        cpa_commit();                                                         \
    } while (0)

    AT_ISSUE(0, 0);
    AT_ISSUE(1, 1);

    float mr0 = -1e30f, mr1 = -1e30f, lr0 = 0.0f, lr1 = 0.0f;
    float Oa[8][4] = {};
    unsigned qf[4][4];
    bool qf_done = false;

    for (int jt = 0; jt < 16; jt++) {
        cpa_wait1();              // Q (first iter) + KV tile jt complete
        __syncthreads();
        const uint32_t ksb = asb + (unsigned)((AT_QS + (jt & 1) * AT_KV) * 4);
        const uint32_t vsb = ksb + (unsigned)(AT_KS * 4);

        if (!qf_done) {
            qf_done = true;
            #pragma unroll
            for (int s = 0; s < 4; s++) {
                qf[s][0] = Qs[(wq + g) * 36 + 8 * s + t];
                qf[s][1] = Qs[(wq + 8 + g) * 36 + 8 * s + t];
                qf[s][2] = Qs[(wq + g) * 36 + 8 * s + t + 4];
                qf[s][3] = Qs[(wq + 8 + g) * 36 + 8 * s + t + 4];
            }
        }

        // ---- S = Q K^T ----
        float S[8][4] = {};
        #pragma unroll
        for (int s = 0; s < 4; s++) {
            #pragma unroll
            for (int ntp = 0; ntp < 4; ntp++) {
                unsigned bv[4];
                int row = ntp * 16 + mhi * 8 + mrow;
                ldsm4(bv, ksb + (unsigned)((row * 36 + s * 8 + mlo * 4) * 4));
                mma16(S[2 * ntp],     qf[s], bv);
                mma16(S[2 * ntp + 1], qf[s], bv + 2);
            }
        }

        float mx0 = -1e30f, mx1 = -1e30f;
        #pragma unroll
        for (int nt = 0; nt < 8; nt++) {
            S[nt][0] *= 0.125f; S[nt][1] *= 0.125f;
            S[nt][2] *= 0.125f; S[nt][3] *= 0.125f;
            mx0 = fmaxf(mx0, fmaxf(S[nt][0], S[nt][1]));
            mx1 = fmaxf(mx1, fmaxf(S[nt][2], S[nt][3]));
        }
        mx0 = fmaxf(mx0, __shfl_xor_sync(0xffffffffu, mx0, 1));
        mx0 = fmaxf(mx0, __shfl_xor_sync(0xffffffffu, mx0, 2));
        mx1 = fmaxf(mx1, __shfl_xor_sync(0xffffffffu, mx1, 1));
        mx1 = fmaxf(mx1, __shfl_xor_sync(0xffffffffu, mx1, 2));
        float mn0 = fmaxf(mr0, mx0), mn1 = fmaxf(mr1, mx1);
        float al0 = __expf(mr0 - mn0), al1 = __expf(mr1 - mn1);
        mr0 = mn0; mr1 = mn1;
        float s0 = 0.0f, s1 = 0.0f;
        #pragma unroll
        for (int nt = 0; nt < 8; nt++) {
            S[nt][0] = __expf(S[nt][0] - mn0);
            S[nt][1] = __expf(S[nt][1] - mn0);
            S[nt][2] = __expf(S[nt][2] - mn1);
            S[nt][3] = __expf(S[nt][3] - mn1);
            s0 += S[nt][0] + S[nt][1];
            s1 += S[nt][2] + S[nt][3];
        }
        s0 += __shfl_xor_sync(0xffffffffu, s0, 1);
        s0 += __shfl_xor_sync(0xffffffffu, s0, 2);
        s1 += __shfl_xor_sync(0xffffffffu, s1, 1);
        s1 += __shfl_xor_sync(0xffffffffu, s1, 2);
        lr0 = lr0 * al0 + s0; lr1 = lr1 * al1 + s1;

        #pragma unroll
        for (int dt = 0; dt < 8; dt++) {
            Oa[dt][0] *= al0; Oa[dt][1] *= al0;
            Oa[dt][2] *= al1; Oa[dt][3] *= al1;
        }

        // ---- O += P V ----
        #pragma unroll
        for (int s = 0; s < 4; s++) {
            unsigned pa[4] = {
                h2f(S[2 * s][0],     S[2 * s][1]),
                h2f(S[2 * s][2],     S[2 * s][3]),
                h2f(S[2 * s + 1][0], S[2 * s + 1][1]),
                h2f(S[2 * s + 1][2], S[2 * s + 1][3])
            };
            #pragma unroll
            for (int dtp = 0; dtp < 4; dtp++) {
                unsigned bv[4];
                int row = dtp * 16 + mhi * 8 + mrow;
                ldsm4(bv, vsb + (unsigned)((row * 36 + s * 8 + mlo * 4) * 4));
                mma16(Oa[2 * dtp],     pa, bv);
                mma16(Oa[2 * dtp + 1], pa, bv + 2);
            }
        }
        __syncthreads();
        if (jt + 2 < 16) AT_ISSUE(jt + 2, jt & 1);
        else             cpa_commit();
    }
    #undef AT_ISSUE

    float li0 = 1.0f / lr0, li1 = 1.0f / lr1;
    __half* r0p = Ob + (size_t)(wq + g) * C_;
    __half* r1p = Ob + (size_t)(wq + 8 + g) * C_;
    #pragma unroll
    for (int dt = 0; dt < 8; dt++) {
        int dcol = dt * 8 + 2 * t;
        *(unsigned*)(r0p + dcol) = h2f(Oa[dt][0] * li0, Oa[dt][1] * li0);
        *(unsigned*)(r1p + dcol) = h2f(Oa[dt][2] * li1, Oa[dt][3] * li1);
    }
}

// ============================================================================
// fp16 final GEMM: y = silu(BN(W_pr @ (att+pp))), f32 out  (unchanged)
// ============================================================================
__global__ __launch_bounds__(256, 2)
void gemm_add_h(const __half* __restrict__ Wt,
                const __half* __restrict__ attT,
                const __half* __restrict__ ppT,
                const float* __restrict__ gg, const float* __restrict__ bb,
                const float* __restrict__ rm, const float* __restrict__ rv,
                float* __restrict__ Y)
{
    __shared__ unsigned Ws[128 * 20];
    __shared__ unsigned Xs[128 * 20];

    const int n0 = blockIdx.x * 128;
    const int m0 = blockIdx.y * 128;
    const int b  = blockIdx.z;
    const __half* Wb = Wt + (size_t)m0 * C_;
    const __half* Ab = attT + ((size_t)b * N_ + n0) * C_;
    const __half* Pb = ppT  + ((size_t)b * N_ + n0) * C_;

    const int tid = threadIdx.x, lane = tid & 31, warp = tid >> 5;
    const int g = lane >> 2, t = lane & 3;
    const int wm = warp >> 1, wn = warp & 1;
    const int mrow = lane & 7, msel = lane >> 3;
    const int mlo = msel & 1, mhi = msel >> 1;
    const uint32_t wsb = (unsigned)__cvta_generic_to_shared(Ws);
    const uint32_t xsb = (unsigned)__cvta_generic_to_shared(Xs);

    float acc[2][8][4] = {};

    for (int ch = 0; ch < 16; ch++) {
        __syncthreads();
        #pragma unroll
        for (int i = 0; i < 2; i++) {
            int e = tid + 256 * i;
            int r = e >> 2, q = e & 3;
            cpa16(Ws + r * 20 + q * 4, Wb + (size_t)r * C_ + ch * 32 + q * 8);
        }
        cpa_commit();
        #pragma unroll
        for (int i = 0; i < 2; i++) {
            int e = tid + 256 * i;
            int r = e >> 2, q = e & 3;
            size_t off = (size_t)r * C_ + ch * 32 + q * 8;
            uint4 a4 = *(const uint4*)(Ab + off);
            uint4 p4 = *(const uint4*)(Pb + off);
            __half2* ah = (__half2*)&a4;
            __half2* ph = (__half2*)&p4;
            uint4 o;
            __half2 s0h = __hadd2(ah[0], ph[0]); o.x = *(unsigned*)&s0h;
            __half2 s1h = __hadd2(ah[1], ph[1]); o.y = *(unsigned*)&s1h;
            __half2 s2h = __hadd2(ah[2], ph[2]); o.z = *(unsigned*)&s2h;
            __half2 s3h = __hadd2(ah[3], ph[3]); o.w = *(unsigned*)&s3h;
            *(uint4*)&Xs[r * 20 + q * 4] = o;
        }
        cpa_wait0();
        __syncthreads();
        #pragma unroll
        for (int ks = 0; ks < 2; ks++) {
            unsigned a[2][4];
            #pragma unroll
            for (int mt = 0; mt < 2; mt++) {
                int row = wm * 32 + mt * 16 + mlo * 8 + mrow;
                ldsm4(a[mt], wsb + (unsigned)((row * 20 + ks * 8 + mhi * 4) * 4));
            }
            #pragma unroll
            for (int ntp = 0; ntp < 4; ntp++) {
                unsigned bv[4];
                int row = wn * 64 + ntp * 16 + mhi * 8 + mrow;
                ldsm4(bv, xsb + (unsigned)((row * 20 + ks * 8 + mlo * 4) * 4));
                mma16(acc[0][2 * ntp],     a[0], bv);
                mma16(acc[0][2 * ntp + 1], a[0], bv + 2);
                mma16(acc[1][2 * ntp],     a[1], bv);
                mma16(acc[1][2 * ntp + 1], a[1], bv + 2);
            }
        }
    }

    #pragma unroll
    for (int mt = 0; mt < 2; mt++) {
        int m  = m0 + wm * 32 + mt * 16 + g;
        int m1 = m + 8;
        float sc0 = gg[m]  * rsqrtf(rv[m]  + EPS_), sh0 = bb[m]  - rm[m]  * sc0;
        float sc1 = gg[m1] * rsqrtf(rv[m1] + EPS_), sh1 = bb[m1] - rm[m1] * sc1;
        #pragma unroll
        for (int nt = 0; nt < 8; nt++) {
            int n = n0 + wn * 64 + nt * 8 + 2 * t;
            float* c = acc[mt][nt];
            *(float2*)&Y[((size_t)b * C_ + m)  * N_ + n] =
                make_float2(silu_f(c[0] * sc0 + sh0), silu_f(c[1] * sc0 + sh0));
            *(float2*)&Y[((size_t)b * C_ + m1) * N_ + n] =
                make_float2(silu_f(c[2] * sc1 + sh1), silu_f(c[3] * sc1 + sh1));
        }
    }
}

// ============================================================================
extern "C" void kernel_launch(void* const* d_in, const int* in_sizes, int n_in,
                              void* d_out, int out_size)
{
    const float* x     = (const float*)d_in[0];
    const float* qk_w  = (const float*)d_in[1];
    const float* qk_g  = (const float*)d_in[2];
    const float* qk_b  = (const float*)d_in[3];
    const float* qk_rm = (const float*)d_in[4];
    const float* qk_rv = (const float*)d_in[5];
    const float* v_w   = (const float*)d_in[6];
    const float* v_g   = (const float*)d_in[7];
    const float* v_b   = (const float*)d_in[8];
    const float* v_rm  = (const float*)d_in[9];
    const float* v_rv  = (const float*)d_in[10];
    const float* pe_w  = (const float*)d_in[11];
    const float* pe_g  = (const float*)d_in[12];
    const float* pe_b  = (const float*)d_in[13];
    const float* pe_rm = (const float*)d_in[14];
    const float* pe_rv = (const float*)d_in[15];
    const float* pr_w  = (const float*)d_in[16];
    const float* pr_g  = (const float*)d_in[17];
    const float* pr_b  = (const float*)d_in[18];
    const float* pr_rm = (const float*)d_in[19];
    const float* pr_rv = (const float*)d_in[20];
    float* out = (float*)d_out;

    __half *p_xt, *p_wqk, *p_wv, *p_wpr, *p_wpe, *p_qkT, *p_vh, *p_vT, *p_ppT, *p_attT;
    cudaGetSymbolAddress((void**)&p_xt,   g_xt);
    cudaGetSymbolAddress((void**)&p_wqk,  g_wqkh);
    cudaGetSymbolAddress((void**)&p_wv,   g_wvh);
    cudaGetSymbolAddress((void**)&p_wpr,  g_wprh);
    cudaGetSymbolAddress((void**)&p_wpe,  g_wpeh);
    cudaGetSymbolAddress((void**)&p_qkT,  g_qkT);
    cudaGetSymbolAddress((void**)&p_vh,   g_vh);
    cudaGetSymbolAddress((void**)&p_vT,   g_vT);
    cudaGetSymbolAddress((void**)&p_ppT,  g_ppT);
    cudaGetSymbolAddress((void**)&p_attT, g_attT);

    cudaFuncSetAttribute(gemm_h,
                         cudaFuncAttributeMaxDynamicSharedMemorySize, 2 * GH_STG * 4);
    cudaFuncSetAttribute(conv3_h,
                         cudaFuncAttributeMaxDynamicSharedMemorySize, CV_SMEM);
    cudaFuncSetAttribute(attn_h,
                         cudaFuncAttributeMaxDynamicSharedMemorySize, AT_SMEM);

    dim3 thr(256);

    // 0) prep
    f2h_k<<<(2 * C_ * C_ / 8 + 255) / 256, thr>>>((const float4*)qk_w, (uint4*)p_wqk, 2 * C_ * C_ / 8);
    f2h_k<<<(C_ * C_ / 8 + 255) / 256, thr>>>((const float4*)v_w,  (uint4*)p_wv,  C_ * C_ / 8);
    f2h_k<<<(C_ * C_ / 8 + 255) / 256, thr>>>((const float4*)pr_w, (uint4*)p_wpr, C_ * C_ / 8);
    conv_w_xform_h<<<(9 * 32 * 512 * 16 + 255) / 256, thr>>>(pe_w, p_wpe);
    xpose_h<<<dim3(N_ / 32, C_ / 32, B_), dim3(32, 8)>>>(x, p_xt);

    // 1) qk -> qkT
    gemm_h<<<dim3(N_ / 128, 1024 / 128, B_), thr, 2 * GH_STG * 4>>>(
        p_wqk, p_xt, qk_g, qk_b, qk_rm, qk_rv, p_qkT, (__half*)nullptr, 1024);

    // 2) v -> vT + vh
    gemm_h<<<dim3(N_ / 128, C_ / 128, B_), thr, 2 * GH_STG * 4>>>(
        p_wv, p_xt, v_g, v_b, v_rm, v_rv, p_vT, p_vh, C_);

    // 3) conv3: vT -> ppT
    conv3_h<<<dim3(H_ / 4, C_ / 64, B_), thr, CV_SMEM>>>(
        p_wpe, p_vT, pe_g, pe_b, pe_rm, pe_rv, p_ppT);

    // 4) attention: qkT + vh -> attT
    attn_h<<<dim3(NA_ / 128, NHEAD, B_ * AREA_), thr, AT_SMEM>>>(
        p_qkT, p_vh, p_attT);

    // 5) final: W_pr @ (attT + ppT) -> out (fp32)
    gemm_add_h<<<dim3(N_ / 128, C_ / 128, B_), thr>>>(
        p_wpr, p_attT, p_ppT, pr_g, pr_b, pr_rm, pr_rv, out);
}